// round 3
// baseline (speedup 1.0000x reference)
#include <cuda_runtime.h>
#include <math.h>

// Problem constants
#define BB 2
#define CC 48
#define HH 64
#define WW 64
#define NN 4096
#define RPE_S 191
#define NSPLIT 2
#define KEYS_PER_SPLIT (NN / NSPLIT)

typedef unsigned long long ull;

// ---------------- scratch (device globals; no allocation allowed) -------------
__device__ float g_q  [BB*CC*NN];
__device__ float g_x2 [BB*96*NN];
__device__ float g_pos[BB*NN*2];
__device__ float g_xs [BB*CC*NN];
__device__ float g_k  [BB*CC*NN];
__device__ float g_v  [BB*CC*NN];
__device__ float g_win[BB*CC*NN];
__device__ float g_opart[NSPLIT*BB*CC*NN];
__device__ float g_mpart[NSPLIT*BB*NN];
__device__ float g_lpart[NSPLIT*BB*NN];

// ---------------- f32x2 packed math helpers ------------------------------------
__device__ __forceinline__ ull pk2(float a, float b) {
    ull r; asm("mov.b64 %0,{%1,%2};" : "=l"(r) : "f"(a), "f"(b)); return r;
}
__device__ __forceinline__ void upk2(ull v, float& a, float& b) {
    asm("mov.b64 {%0,%1},%2;" : "=f"(a), "=f"(b) : "l"(v));
}
__device__ __forceinline__ void fma2(ull& d, ull a, ull b) {
    asm("fma.rn.f32x2 %0,%1,%2,%0;" : "+l"(d) : "l"(a), "l"(b));
}
__device__ __forceinline__ ull mul2(ull a, ull b) {
    ull r; asm("mul.rn.f32x2 %0,%1,%2;" : "=l"(r) : "l"(a), "l"(b)); return r;
}

// ---------------- generic helpers ----------------------------------------------
__device__ __forceinline__ float bilin(const float* __restrict__ img, int H, int W,
                                       float gx, float gy) {
    float x0f = floorf(gx), y0f = floorf(gy);
    int   x0  = (int)x0f,   y0  = (int)y0f;
    float wx  = gx - x0f,   wy  = gy - y0f;
    float acc = 0.f;
#pragma unroll
    for (int dy = 0; dy < 2; dy++) {
        int yc = y0 + dy;
        if (yc < 0 || yc >= H) continue;
        float wyv = dy ? wy : (1.f - wy);
#pragma unroll
        for (int dx = 0; dx < 2; dx++) {
            int xc = x0 + dx;
            if (xc < 0 || xc >= W) continue;
            float wxv = dx ? wx : (1.f - wx);
            acc += img[yc * W + xc] * (wyv * wxv);
        }
    }
    return acc;
}

// ---------------- 1x1 conv: q = Wq x + bq (float4 / 4 pixels per thread) -------
__global__ void conv_q_kernel(const float* __restrict__ x, const float* __restrict__ W,
                              const float* __restrict__ bias) {
    int idx = blockIdx.x * 256 + threadIdx.x;
    if (idx >= BB * CC * (NN / 4)) return;
    int p4 = idx & (NN / 4 - 1);
    int o  = (idx >> 10) % CC;
    int b  = idx / (CC * (NN / 4));
    float bo = bias[o];
    float4 acc = make_float4(bo, bo, bo, bo);
    const float4* xb = (const float4*)(x + b * CC * NN) + p4;
    const float* wr = W + o * CC;
#pragma unroll 8
    for (int c = 0; c < CC; c++) {
        float4 xv = xb[c * (NN / 4)];
        float w = wr[c];
        acc.x += w * xv.x; acc.y += w * xv.y; acc.z += w * xv.z; acc.w += w * xv.w;
    }
    ((float4*)g_q)[idx] = acc;
}

// ---------------- 1x1 conv (96ch) + BN ------------------------------------------
__global__ void conv_x2_kernel(const float* __restrict__ x, const float* __restrict__ W,
                               const float* __restrict__ bias,
                               const float* __restrict__ bng, const float* __restrict__ bnb,
                               const float* __restrict__ bnm, const float* __restrict__ bnv) {
    int idx = blockIdx.x * 256 + threadIdx.x;
    if (idx >= BB * 96 * (NN / 4)) return;
    int p4 = idx & (NN / 4 - 1);
    int o  = (idx >> 10) % 96;
    int b  = idx / (96 * (NN / 4));
    float bo = bias[o];
    float4 acc = make_float4(bo, bo, bo, bo);
    const float4* xb = (const float4*)(x + b * CC * NN) + p4;
    const float* wr = W + o * CC;
#pragma unroll 8
    for (int c = 0; c < CC; c++) {
        float4 xv = xb[c * (NN / 4)];
        float w = wr[c];
        acc.x += w * xv.x; acc.y += w * xv.y; acc.z += w * xv.z; acc.w += w * xv.w;
    }
    float sc = rsqrtf(bnv[o] + 1e-5f) * bng[o];
    float sh = bnb[o] - bnm[o] * sc;
    acc.x = acc.x * sc + sh; acc.y = acc.y * sc + sh;
    acc.z = acc.z * sc + sh; acc.w = acc.w * sc + sh;
    ((float4*)g_x2)[idx] = acc;
}

// ---------------- offset head + position + grid-sample x ------------------------
__global__ void deform_kernel(const float* __restrict__ x,
                              const float* __restrict__ dww, const float* __restrict__ dwb,
                              const float* __restrict__ lng, const float* __restrict__ lnb,
                              const float* __restrict__ pww) {
    int b = blockIdx.y;
    int y = blockIdx.x;
    int tid = threadIdx.x;
    __shared__ float ts[CC * WW];
    __shared__ float posr[WW * 2];

    for (int i = tid; i < CC * WW; i += 256) {
        int c = i >> 6, px = i & 63;
        float acc = dwb[c];
        const float* qc = g_q + (b * CC + c) * NN;
        const float* wc = dww + c * 9;
#pragma unroll
        for (int ky = 0; ky < 3; ky++) {
            int yy = y + ky - 1;
            if (yy < 0 || yy > 63) continue;
#pragma unroll
            for (int kx = 0; kx < 3; kx++) {
                int xx = px + kx - 1;
                if (xx < 0 || xx > 63) continue;
                acc += qc[(yy << 6) + xx] * wc[ky * 3 + kx];
            }
        }
        ts[c * 64 + px] = acc;
    }
    __syncthreads();

    if (tid < WW) {
        int px = tid;
        float mu = 0.f;
        for (int c = 0; c < CC; c++) mu += ts[c * 64 + px];
        mu *= (1.f / CC);
        float var = 0.f;
        for (int c = 0; c < CC; c++) { float d = ts[c * 64 + px] - mu; var += d * d; }
        var *= (1.f / CC);
        float rs = rsqrtf(var + 1e-5f);
        float a0 = 0.f, a1 = 0.f;
        for (int c = 0; c < CC; c++) {
            float v = (ts[c * 64 + px] - mu) * rs * lng[c] + lnb[c];
            v = 0.5f * v * (1.f + erff(v * 0.7071067811865475f));
            a0 += pww[c] * v;
            a1 += pww[CC + c] * v;
        }
        float py  = tanhf(a0) * (2.f / 63.f) + ((0.5f + (float)y ) * (2.f / 63.f) - 1.f);
        float pxx = tanhf(a1) * (2.f / 63.f) + ((0.5f + (float)px) * (2.f / 63.f) - 1.f);
        posr[px * 2 + 0] = py;
        posr[px * 2 + 1] = pxx;
        int n = (y << 6) + px;
        g_pos[(b * NN + n) * 2 + 0] = py;
        g_pos[(b * NN + n) * 2 + 1] = pxx;
    }
    __syncthreads();

    for (int i = tid; i < CC * WW; i += 256) {
        int c = i >> 6, px = i & 63;
        float py  = posr[px * 2 + 0];
        float pxx = posr[px * 2 + 1];
        float gx = (pxx + 1.f) * 0.5f * 63.f;
        float gy = (py  + 1.f) * 0.5f * 63.f;
        const float* img = x + (b * CC + c) * NN;
        g_xs[(b * CC + c) * NN + (y << 6) + px] = bilin(img, HH, WW, gx, gy);
    }
}

// ---------------- k,v projections (float4) ---------------------------------------
__global__ void conv_kv_kernel(const float* __restrict__ Wk, const float* __restrict__ bk,
                               const float* __restrict__ Wv, const float* __restrict__ bv) {
    int idx = blockIdx.x * 256 + threadIdx.x;
    if (idx >= BB * CC * (NN / 4)) return;
    int p4 = idx & (NN / 4 - 1);
    int o  = (idx >> 10) % CC;
    int b  = idx / (CC * (NN / 4));
    float bko = bk[o], bvo = bv[o];
    float4 ak = make_float4(bko, bko, bko, bko);
    float4 av = make_float4(bvo, bvo, bvo, bvo);
    const float4* xb = (const float4*)(g_xs + b * CC * NN) + p4;
    const float* wkr = Wk + o * CC;
    const float* wvr = Wv + o * CC;
#pragma unroll 8
    for (int c = 0; c < CC; c++) {
        float4 xv = xb[c * (NN / 4)];
        float wk = wkr[c], wv = wvr[c];
        ak.x += wk * xv.x; ak.y += wk * xv.y; ak.z += wk * xv.z; ak.w += wk * xv.w;
        av.x += wv * xv.x; av.y += wv * xv.y; av.z += wv * xv.z; av.w += wv * xv.w;
    }
    ((float4*)g_k)[idx] = ak;
    ((float4*)g_v)[idx] = av;
}

// ---------------- fused flash attention: f32x2 FMA + smem-resident RPE ----------
// block: 512 threads, 128 queries (2 image rows), key tiles of 64, split-KV=2.
// S phase: mt=tid>>4 (32 groups x 4 queries), kt=tid&15 (16 groups x 4 keys).
// PV phase: ct=tid&15 -> 3 channels.
// smem layout (floats):
#define OFF_RPE  0
#define OFF_QSM  36484                      // 48 x 128
#define OFF_KDUP (OFF_QSM + 6144)           // K: [c][128 dup] / V: [n][96 dup]
#define OFF_PS   (OFF_KDUP + 6144)          // 64 x 132
#define OFF_KB   (OFF_PS + 8448)            // 64
#define OFF_WY0  (OFF_KB + 64)              // 2 x 64
#define OFF_WY1  (OFF_WY0 + 128)
#define OFF_RY0  (OFF_WY1 + 128)
#define OFF_RY1  (OFF_RY0 + 128)
#define SMEM_FLOATS (OFF_RY1 + 128)
#define ATTN_SMEM_BYTES (SMEM_FLOATS * 4)

__global__ void __launch_bounds__(512, 1) attn_kernel(const float* __restrict__ rpe) {
    extern __shared__ float sm[];
    float* rpe_s = sm + OFF_RPE;
    float* qsm   = sm + OFF_QSM;
    float* kvd   = sm + OFF_KDUP;
    float* Ps    = sm + OFF_PS;
    float* kb_s  = sm + OFF_KB;
    float* wy0_s = sm + OFF_WY0;
    float* wy1_s = sm + OFF_WY1;
    int*   ry0_p = (int*)(sm + OFF_RY0);
    int*   ry1_p = (int*)(sm + OFF_RY1);

    const int yb    = blockIdx.x;       // 2 query rows: 2*yb, 2*yb+1
    const int split = blockIdx.y;
    const int b     = blockIdx.z;
    const int tid   = threadIdx.x;
    const int kt    = tid & 15;
    const int mt    = tid >> 4;         // 0..31
    const int m0    = yb * 128;

    const float scale = 0.14433756729740643f;   // 1/sqrt(48)

    // load rpe table into smem (float4 bulk + tail)
    {
        const float4* r4 = (const float4*)rpe;
        float4* s4 = (float4*)rpe_s;
        for (int i = tid; i < (RPE_S * RPE_S) / 4; i += 512) s4[i] = r4[i];
        if (tid == 0) rpe_s[RPE_S * RPE_S - 1] = rpe[RPE_S * RPE_S - 1];
    }
    // load q tile [c][m], pre-scaled
    for (int i = tid; i < CC * 128; i += 512) {
        int c = i >> 7, m = i & 127;
        qsm[c * 128 + m] = g_q[(b * CC + c) * NN + m0 + m] * scale;
    }

    // per-query grid x coords (col = (mt&15)*4+mi since 4 queries never straddle rows)
    float gxq[4];
#pragma unroll
    for (int mi = 0; mi < 4; mi++)
        gxq[mi] = 47.5f + (float)((mt & 15) * 4 + mi) * (95.0f / 63.0f);
    const int myrow = mt >> 4;          // 0 or 1

    float rmax[4], rsum[4], f[4];
    ull o01[3] = {0, 0, 0}, o23[3] = {0, 0, 0};
#pragma unroll
    for (int mi = 0; mi < 4; mi++) { rmax[mi] = -1e30f; rsum[mi] = 0.f; }

    const int nbase = split * KEYS_PER_SPLIT;
    for (int t = 0; t < KEYS_PER_SPLIT / 64; t++) {
        const int n0 = nbase + t * 64;
        __syncthreads();   // prev tile's PV done with kvd/Ps; aux free

        // load K tile duplicated: kvd[c*128 + 2n{,+1}]
        for (int i = tid; i < CC * 64; i += 512) {
            int c = i >> 6, n = i & 63;
            float kv = g_k[(b * CC + c) * NN + n0 + n];
            kvd[c * 128 + 2 * n]     = kv;
            kvd[c * 128 + 2 * n + 1] = kv;
        }
        // per-(key,row) aux
        if (tid < 128) {
            int r = tid >> 6, kk = tid & 63;
            float py = g_pos[(b * NN + n0 + kk) * 2 + 0];
            float px = g_pos[(b * NN + n0 + kk) * 2 + 1];
            if (r == 0) kb_s[kk] = 47.5f * px;
            float gy = (47.5f + (float)(yb * 2 + r) * (95.0f / 63.0f)) - 47.5f * py;
            float yf = floorf(gy);
            float fy = gy - yf;
            int   iy = (int)yf;
            wy0_s[r * 64 + kk] = ((unsigned)iy       <= 190u) ? (1.f - fy) : 0.f;
            wy1_s[r * 64 + kk] = ((unsigned)(iy + 1) <= 190u) ? fy : 0.f;
            ry0_p[r * 64 + kk] = min(max(iy, 0), 190) * RPE_S;
            ry1_p[r * 64 + kk] = min(max(iy + 1, 0), 190) * RPE_S;
        }
        __syncthreads();

        // ---- S = qk (packed over query pairs) ----
        ull s01[4] = {0, 0, 0, 0}, s23[4] = {0, 0, 0, 0};
#pragma unroll 4
        for (int c = 0; c < CC; c++) {
            float4 qv  = *(const float4*)&qsm[c * 128 + mt * 4];
            float4 kd0 = *(const float4*)&kvd[c * 128 + kt * 8];       // k0,k0,k1,k1
            float4 kd1 = *(const float4*)&kvd[c * 128 + kt * 8 + 4];   // k2,k2,k3,k3
            ull q01 = pk2(qv.x, qv.y), q23 = pk2(qv.z, qv.w);
            ull k00 = pk2(kd0.x, kd0.y), k11 = pk2(kd0.z, kd0.w);
            ull k22 = pk2(kd1.x, kd1.y), k33 = pk2(kd1.z, kd1.w);
            fma2(s01[0], q01, k00); fma2(s23[0], q23, k00);
            fma2(s01[1], q01, k11); fma2(s23[1], q23, k11);
            fma2(s01[2], q01, k22); fma2(s23[2], q23, k22);
            fma2(s01[3], q01, k33); fma2(s23[3], q23, k33);
        }
        float s[4][4];
#pragma unroll
        for (int ki = 0; ki < 4; ki++) {
            upk2(s01[ki], s[0][ki], s[1][ki]);
            upk2(s23[ki], s[2][ki], s[3][ki]);
        }

        // ---- add RPE bias (reads from smem-resident table) ----
#pragma unroll
        for (int ki = 0; ki < 4; ki++) {
            int n = kt * 4 + ki;
            float kb  = kb_s[n];
            float wy0 = wy0_s[myrow * 64 + n], wy1 = wy1_s[myrow * 64 + n];
            int   ry0 = ry0_p[myrow * 64 + n], ry1 = ry1_p[myrow * 64 + n];
#pragma unroll
            for (int mi = 0; mi < 4; mi++) {
                float gx = gxq[mi] - kb;
                float xf = floorf(gx);
                float fx = gx - xf;
                int   xi = (int)xf;
                float w0 = ((unsigned)xi       <= 190u) ? (1.f - fx) : 0.f;
                float w1 = ((unsigned)(xi + 1) <= 190u) ? fx : 0.f;
                int x0 = min(max(xi, 0), 190);
                int x1 = min(max(xi + 1, 0), 190);
                float b0 = rpe_s[ry0 + x0] * w0 + rpe_s[ry0 + x1] * w1;
                float b1 = rpe_s[ry1 + x0] * w0 + rpe_s[ry1 + x1] * w1;
                s[mi][ki] += wy0 * b0 + wy1 * b1;
            }
        }

        // ---- online softmax (16-lane reduction over kt) ----
#pragma unroll
        for (int mi = 0; mi < 4; mi++) {
            float tmax = fmaxf(fmaxf(s[mi][0], s[mi][1]), fmaxf(s[mi][2], s[mi][3]));
#pragma unroll
            for (int w = 1; w < 16; w <<= 1)
                tmax = fmaxf(tmax, __shfl_xor_sync(0xffffffffu, tmax, w));
            float nmax = fmaxf(rmax[mi], tmax);
            f[mi] = __expf(rmax[mi] - nmax);
            float p0 = __expf(s[mi][0] - nmax);
            float p1 = __expf(s[mi][1] - nmax);
            float p2 = __expf(s[mi][2] - nmax);
            float p3 = __expf(s[mi][3] - nmax);
            s[mi][0] = p0; s[mi][1] = p1; s[mi][2] = p2; s[mi][3] = p3;
            float ps = p0 + p1 + p2 + p3;
#pragma unroll
            for (int w = 1; w < 16; w <<= 1)
                ps += __shfl_xor_sync(0xffffffffu, ps, w);
            rsum[mi] = rsum[mi] * f[mi] + ps;
            rmax[mi] = nmax;
        }
        // write P transposed: Ps[n][m]
#pragma unroll
        for (int ki = 0; ki < 4; ki++) {
            float4 pv = make_float4(s[0][ki], s[1][ki], s[2][ki], s[3][ki]);
            *(float4*)&Ps[(kt * 4 + ki) * 132 + mt * 4] = pv;
        }

        __syncthreads();    // all S-phase reads of kvd done; Ps complete

        // load V duplicated: kvd[n*96 + 2c{,+1}]
        for (int i = tid; i < CC * 64; i += 512) {
            int c = i >> 6, n = i & 63;
            float vv = g_v[(b * CC + c) * NN + n0 + n];
            kvd[n * 96 + 2 * c]     = vv;
            kvd[n * 96 + 2 * c + 1] = vv;
        }
        __syncthreads();

        // ---- PV (packed over query pairs) ----
        const int ct = tid & 15;
        {
            ull f01 = pk2(f[0], f[1]), f23 = pk2(f[2], f[3]);
#pragma unroll
            for (int j = 0; j < 3; j++) {
                o01[j] = mul2(o01[j], f01);
                o23[j] = mul2(o23[j], f23);
            }
        }
#pragma unroll 4
        for (int n = 0; n < 64; n++) {
            float4 p4 = *(const float4*)&Ps[n * 132 + mt * 4];
            ull p01 = pk2(p4.x, p4.y), p23 = pk2(p4.z, p4.w);
            ull v00 = *(const ull*)&kvd[n * 96 + ct * 6];
            ull v11 = *(const ull*)&kvd[n * 96 + ct * 6 + 2];
            ull v22 = *(const ull*)&kvd[n * 96 + ct * 6 + 4];
            fma2(o01[0], p01, v00); fma2(o23[0], p23, v00);
            fma2(o01[1], p01, v11); fma2(o23[1], p23, v11);
            fma2(o01[2], p01, v22); fma2(o23[2], p23, v22);
        }
    }

    // ---- write partial results ----
    const int ct = tid & 15;
    float o[4][3];
#pragma unroll
    for (int j = 0; j < 3; j++) {
        upk2(o01[j], o[0][j], o[1][j]);
        upk2(o23[j], o[2][j], o[3][j]);
    }
#pragma unroll
    for (int mi = 0; mi < 4; mi++) {
        int m = m0 + mt * 4 + mi;
#pragma unroll
        for (int j = 0; j < 3; j++) {
            int c = ct * 3 + j;
            g_opart[((split * BB + b) * CC + c) * NN + m] = o[mi][j];
        }
        if (ct == 0) {
            g_mpart[(split * BB + b) * NN + m] = rmax[mi];
            g_lpart[(split * BB + b) * NN + m] = rsum[mi];
        }
    }
}

// ---------------- window attention (3 splits x 64 windows x B) ------------------
__global__ void winattn_kernel() {
    int b  = blockIdx.z;
    int sp = blockIdx.y;
    int w  = blockIdx.x;
    int t  = threadIdx.x;

    __shared__ float qsm[64][17];
    __shared__ float vsm[64][17];

    int py, px;
    if (sp == 0)      { int wy = w >> 3, wx = w & 7; py = wy * 8 + (t >> 3); px = wx * 8 + (t & 7); }
    else if (sp == 1) { py = t;  px = w; }
    else              { py = w;  px = t; }
    int pix = py * 64 + px;

    int qbase = (b * 96 + sp * 32) * NN + pix;
#pragma unroll
    for (int c = 0; c < 16; c++) {
        qsm[t][c] = g_x2[qbase + c * NN];
        vsm[t][c] = g_x2[qbase + (16 + c) * NN];
    }
    __syncthreads();

    float qr[16];
#pragma unroll
    for (int c = 0; c < 16; c++) qr[c] = qsm[t][c];

    float lg[64];
    float mx = -1e30f;
    for (int j = 0; j < 64; j++) {
        float d = 0.f;
#pragma unroll
        for (int c = 0; c < 16; c++) d += qr[c] * qsm[j][c];
        lg[j] = d;
        mx = fmaxf(mx, d);
    }
    float s = 0.f;
    for (int j = 0; j < 64; j++) { lg[j] = __expf(lg[j] - mx); s += lg[j]; }
    float inv = 1.f / s;

    float o[16];
#pragma unroll
    for (int c = 0; c < 16; c++) o[c] = 0.f;
    for (int j = 0; j < 64; j++) {
        float p = lg[j] * inv;
#pragma unroll
        for (int c = 0; c < 16; c++) o[c] += p * vsm[j][c];
    }
#pragma unroll
    for (int c = 0; c < 16; c++)
        g_win[(b * CC + sp * 16 + c) * NN + pix] = o[c];
}

// ---------------- final: pout conv + split-KV merge + average (float4) ----------
__global__ void final_kernel(const float* __restrict__ pw, const float* __restrict__ pb,
                             float* __restrict__ out) {
    int idx = blockIdx.x * 256 + threadIdx.x;
    if (idx >= BB * CC * (NN / 4)) return;
    int p4 = idx & (NN / 4 - 1);
    int o  = (idx >> 10) % CC;
    int b  = idx / (CC * (NN / 4));
    float bo = pb[o];
    float4 acc = make_float4(bo, bo, bo, bo);
    const float4* wb = (const float4*)(g_win + b * CC * NN) + p4;
    const float* wr = pw + o * CC;
#pragma unroll 8
    for (int c = 0; c < CC; c++) {
        float4 wv = wb[c * (NN / 4)];
        float w = wr[c];
        acc.x += w * wv.x; acc.y += w * wv.y; acc.z += w * wv.z; acc.w += w * wv.w;
    }

    float4 m0v = ((const float4*)(g_mpart + (0 * BB + b) * NN))[p4];
    float4 m1v = ((const float4*)(g_mpart + (1 * BB + b) * NN))[p4];
    float4 l0v = ((const float4*)(g_lpart + (0 * BB + b) * NN))[p4];
    float4 l1v = ((const float4*)(g_lpart + (1 * BB + b) * NN))[p4];
    float4 o0v = ((const float4*)(g_opart + ((0 * BB + b) * CC + o) * NN))[p4];
    float4 o1v = ((const float4*)(g_opart + ((1 * BB + b) * CC + o) * NN))[p4];

    float4 res;
    {
        float M = fmaxf(m0v.x, m1v.x);
        float e0 = __expf(m0v.x - M), e1 = __expf(m1v.x - M);
        res.x = 0.5f * acc.x + 0.5f * (o0v.x * e0 + o1v.x * e1) / (l0v.x * e0 + l1v.x * e1);
    }
    {
        float M = fmaxf(m0v.y, m1v.y);
        float e0 = __expf(m0v.y - M), e1 = __expf(m1v.y - M);
        res.y = 0.5f * acc.y + 0.5f * (o0v.y * e0 + o1v.y * e1) / (l0v.y * e0 + l1v.y * e1);
    }
    {
        float M = fmaxf(m0v.z, m1v.z);
        float e0 = __expf(m0v.z - M), e1 = __expf(m1v.z - M);
        res.z = 0.5f * acc.z + 0.5f * (o0v.z * e0 + o1v.z * e1) / (l0v.z * e0 + l1v.z * e1);
    }
    {
        float M = fmaxf(m0v.w, m1v.w);
        float e0 = __expf(m0v.w - M), e1 = __expf(m1v.w - M);
        res.w = 0.5f * acc.w + 0.5f * (o0v.w * e0 + o1v.w * e1) / (l0v.w * e0 + l1v.w * e1);
    }
    ((float4*)out)[idx] = res;
}

// ---------------- launch ---------------------------------------------------------
extern "C" void kernel_launch(void* const* d_in, const int* in_sizes, int n_in,
                              void* d_out, int out_size) {
    const float* x        = (const float*)d_in[0];
    const float* Wq       = (const float*)d_in[1];
    const float* bq       = (const float*)d_in[2];
    const float* off_dw_w = (const float*)d_in[3];
    const float* off_dw_b = (const float*)d_in[4];
    const float* off_ln_g = (const float*)d_in[5];
    const float* off_ln_b = (const float*)d_in[6];
    const float* off_pw_w = (const float*)d_in[7];
    const float* Wk       = (const float*)d_in[8];
    const float* bk       = (const float*)d_in[9];
    const float* Wv       = (const float*)d_in[10];
    const float* bv       = (const float*)d_in[11];
    const float* inp_w    = (const float*)d_in[12];
    const float* inp_b    = (const float*)d_in[13];
    const float* bn_g     = (const float*)d_in[14];
    const float* bn_b     = (const float*)d_in[15];
    const float* bn_mean  = (const float*)d_in[16];
    const float* bn_var   = (const float*)d_in[17];
    const float* pout_w   = (const float*)d_in[18];
    const float* pout_b   = (const float*)d_in[19];
    const float* rpe      = (const float*)d_in[20];
    float* out = (float*)d_out;

    cudaFuncSetAttribute(attn_kernel, cudaFuncAttributeMaxDynamicSharedMemorySize,
                         ATTN_SMEM_BYTES);

    conv_q_kernel<<<(BB * CC * (NN / 4) + 255) / 256, 256>>>(x, Wq, bq);
    conv_x2_kernel<<<(BB * 96 * (NN / 4) + 255) / 256, 256>>>(x, inp_w, inp_b,
                                                              bn_g, bn_b, bn_mean, bn_var);
    deform_kernel<<<dim3(HH, BB), 256>>>(x, off_dw_w, off_dw_b,
                                         off_ln_g, off_ln_b, off_pw_w);
    conv_kv_kernel<<<(BB * CC * (NN / 4) + 255) / 256, 256>>>(Wk, bk, Wv, bv);
    attn_kernel<<<dim3(32, NSPLIT, BB), 512, ATTN_SMEM_BYTES>>>(rpe);
    winattn_kernel<<<dim3(64, 3, BB), 64>>>();
    final_kernel<<<(BB * CC * (NN / 4) + 255) / 256, 256>>>(pout_w, pout_b, out);
}

// round 4
// speedup vs baseline: 1.1736x; 1.1736x over previous
#include <cuda_runtime.h>
#include <math.h>

// Problem constants
#define BB 2
#define CC 48
#define HH 64
#define WW 64
#define NN 4096
#define RPE_S 191
#define NSPLIT 2
#define KEYS_PER_SPLIT (NN / NSPLIT)

typedef unsigned long long ull;

// ---------------- scratch (device globals; no allocation allowed) -------------
__device__ float g_q  [BB*CC*NN];
__device__ float g_x2 [BB*96*NN];
__device__ float g_pos[BB*NN*2];
__device__ float g_xs [BB*CC*NN];
__device__ float g_k  [BB*CC*NN];
__device__ float g_v  [BB*CC*NN];
__device__ float g_win[BB*CC*NN];
__device__ float g_opart[NSPLIT*BB*CC*NN];
__device__ float g_mpart[NSPLIT*BB*NN];
__device__ float g_lpart[NSPLIT*BB*NN];

// ---------------- f32x2 packed math helpers ------------------------------------
__device__ __forceinline__ ull pk2(float a, float b) {
    ull r; asm("mov.b64 %0,{%1,%2};" : "=l"(r) : "f"(a), "f"(b)); return r;
}
__device__ __forceinline__ void upk2(ull v, float& a, float& b) {
    asm("mov.b64 {%0,%1},%2;" : "=f"(a), "=f"(b) : "l"(v));
}
__device__ __forceinline__ void fma2(ull& d, ull a, ull b) {
    asm("fma.rn.f32x2 %0,%1,%2,%0;" : "+l"(d) : "l"(a), "l"(b));
}
__device__ __forceinline__ ull mul2(ull a, ull b) {
    ull r; asm("mul.rn.f32x2 %0,%1,%2;" : "=l"(r) : "l"(a), "l"(b)); return r;
}

// ---------------- generic helpers ----------------------------------------------
__device__ __forceinline__ float bilin(const float* __restrict__ img, int H, int W,
                                       float gx, float gy) {
    float x0f = floorf(gx), y0f = floorf(gy);
    int   x0  = (int)x0f,   y0  = (int)y0f;
    float wx  = gx - x0f,   wy  = gy - y0f;
    float acc = 0.f;
#pragma unroll
    for (int dy = 0; dy < 2; dy++) {
        int yc = y0 + dy;
        if (yc < 0 || yc >= H) continue;
        float wyv = dy ? wy : (1.f - wy);
#pragma unroll
        for (int dx = 0; dx < 2; dx++) {
            int xc = x0 + dx;
            if (xc < 0 || xc >= W) continue;
            float wxv = dx ? wx : (1.f - wx);
            acc += img[yc * W + xc] * (wyv * wxv);
        }
    }
    return acc;
}

// ---------------- 1x1 conv: q = Wq x + bq (float4) -----------------------------
__global__ void conv_q_kernel(const float* __restrict__ x, const float* __restrict__ W,
                              const float* __restrict__ bias) {
    int idx = blockIdx.x * 256 + threadIdx.x;
    if (idx >= BB * CC * (NN / 4)) return;
    int p4 = idx & (NN / 4 - 1);
    int o  = (idx >> 10) % CC;
    int b  = idx / (CC * (NN / 4));
    float bo = bias[o];
    float4 acc = make_float4(bo, bo, bo, bo);
    const float4* xb = (const float4*)(x + b * CC * NN) + p4;
    const float* wr = W + o * CC;
#pragma unroll 8
    for (int c = 0; c < CC; c++) {
        float4 xv = xb[c * (NN / 4)];
        float w = wr[c];
        acc.x += w * xv.x; acc.y += w * xv.y; acc.z += w * xv.z; acc.w += w * xv.w;
    }
    ((float4*)g_q)[idx] = acc;
}

// ---------------- 1x1 conv (96ch) + BN ------------------------------------------
__global__ void conv_x2_kernel(const float* __restrict__ x, const float* __restrict__ W,
                               const float* __restrict__ bias,
                               const float* __restrict__ bng, const float* __restrict__ bnb,
                               const float* __restrict__ bnm, const float* __restrict__ bnv) {
    int idx = blockIdx.x * 256 + threadIdx.x;
    if (idx >= BB * 96 * (NN / 4)) return;
    int p4 = idx & (NN / 4 - 1);
    int o  = (idx >> 10) % 96;
    int b  = idx / (96 * (NN / 4));
    float bo = bias[o];
    float4 acc = make_float4(bo, bo, bo, bo);
    const float4* xb = (const float4*)(x + b * CC * NN) + p4;
    const float* wr = W + o * CC;
#pragma unroll 8
    for (int c = 0; c < CC; c++) {
        float4 xv = xb[c * (NN / 4)];
        float w = wr[c];
        acc.x += w * xv.x; acc.y += w * xv.y; acc.z += w * xv.z; acc.w += w * xv.w;
    }
    float sc = rsqrtf(bnv[o] + 1e-5f) * bng[o];
    float sh = bnb[o] - bnm[o] * sc;
    acc.x = acc.x * sc + sh; acc.y = acc.y * sc + sh;
    acc.z = acc.z * sc + sh; acc.w = acc.w * sc + sh;
    ((float4*)g_x2)[idx] = acc;
}

// ---------------- offset head + position + grid-sample x ------------------------
__global__ void deform_kernel(const float* __restrict__ x,
                              const float* __restrict__ dww, const float* __restrict__ dwb,
                              const float* __restrict__ lng, const float* __restrict__ lnb,
                              const float* __restrict__ pww) {
    int b = blockIdx.y;
    int y = blockIdx.x;
    int tid = threadIdx.x;
    __shared__ float ts[CC * WW];
    __shared__ float posr[WW * 2];

    for (int i = tid; i < CC * WW; i += 256) {
        int c = i >> 6, px = i & 63;
        float acc = dwb[c];
        const float* qc = g_q + (b * CC + c) * NN;
        const float* wc = dww + c * 9;
#pragma unroll
        for (int ky = 0; ky < 3; ky++) {
            int yy = y + ky - 1;
            if (yy < 0 || yy > 63) continue;
#pragma unroll
            for (int kx = 0; kx < 3; kx++) {
                int xx = px + kx - 1;
                if (xx < 0 || xx > 63) continue;
                acc += qc[(yy << 6) + xx] * wc[ky * 3 + kx];
            }
        }
        ts[c * 64 + px] = acc;
    }
    __syncthreads();

    if (tid < WW) {
        int px = tid;
        float mu = 0.f;
        for (int c = 0; c < CC; c++) mu += ts[c * 64 + px];
        mu *= (1.f / CC);
        float var = 0.f;
        for (int c = 0; c < CC; c++) { float d = ts[c * 64 + px] - mu; var += d * d; }
        var *= (1.f / CC);
        float rs = rsqrtf(var + 1e-5f);
        float a0 = 0.f, a1 = 0.f;
        for (int c = 0; c < CC; c++) {
            float v = (ts[c * 64 + px] - mu) * rs * lng[c] + lnb[c];
            v = 0.5f * v * (1.f + erff(v * 0.7071067811865475f));
            a0 += pww[c] * v;
            a1 += pww[CC + c] * v;
        }
        float py  = tanhf(a0) * (2.f / 63.f) + ((0.5f + (float)y ) * (2.f / 63.f) - 1.f);
        float pxx = tanhf(a1) * (2.f / 63.f) + ((0.5f + (float)px) * (2.f / 63.f) - 1.f);
        posr[px * 2 + 0] = py;
        posr[px * 2 + 1] = pxx;
        int n = (y << 6) + px;
        g_pos[(b * NN + n) * 2 + 0] = py;
        g_pos[(b * NN + n) * 2 + 1] = pxx;
    }
    __syncthreads();

    for (int i = tid; i < CC * WW; i += 256) {
        int c = i >> 6, px = i & 63;
        float py  = posr[px * 2 + 0];
        float pxx = posr[px * 2 + 1];
        float gx = (pxx + 1.f) * 0.5f * 63.f;
        float gy = (py  + 1.f) * 0.5f * 63.f;
        const float* img = x + (b * CC + c) * NN;
        g_xs[(b * CC + c) * NN + (y << 6) + px] = bilin(img, HH, WW, gx, gy);
    }
}

// ---------------- k,v projections (float4) ---------------------------------------
__global__ void conv_kv_kernel(const float* __restrict__ Wk, const float* __restrict__ bk,
                               const float* __restrict__ Wv, const float* __restrict__ bv) {
    int idx = blockIdx.x * 256 + threadIdx.x;
    if (idx >= BB * CC * (NN / 4)) return;
    int p4 = idx & (NN / 4 - 1);
    int o  = (idx >> 10) % CC;
    int b  = idx / (CC * (NN / 4));
    float bko = bk[o], bvo = bv[o];
    float4 ak = make_float4(bko, bko, bko, bko);
    float4 av = make_float4(bvo, bvo, bvo, bvo);
    const float4* xb = (const float4*)(g_xs + b * CC * NN) + p4;
    const float* wkr = Wk + o * CC;
    const float* wvr = Wv + o * CC;
#pragma unroll 8
    for (int c = 0; c < CC; c++) {
        float4 xv = xb[c * (NN / 4)];
        float wk = wkr[c], wv = wvr[c];
        ak.x += wk * xv.x; ak.y += wk * xv.y; ak.z += wk * xv.z; ak.w += wk * xv.w;
        av.x += wv * xv.x; av.y += wv * xv.y; av.z += wv * xv.z; av.w += wv * xv.w;
    }
    ((float4*)g_k)[idx] = ak;
    ((float4*)g_v)[idx] = av;
}

// ---------------- fused flash attention: layout-free f32x2 packing --------------
// block: 256 threads, 64 queries (one image row), 64-key tiles, split-KV=2.
// smem (dynamic, floats):
#define OFF_QD   0                       // Q duplicated: [c][128]  (q,q pairs)
#define OFF_KV   (OFF_QD + 6144)         // K: [c][64]  /  V dup: [n][96]
#define OFF_PS   (OFF_KV + 6144)         // P: [n][68]
#define OFF_KB   (OFF_PS + 4352)
#define OFF_WY0  (OFF_KB + 64)
#define OFF_WY1  (OFF_WY0 + 64)
#define OFF_RY0  (OFF_WY1 + 64)
#define OFF_RY1  (OFF_RY0 + 64)
#define SMEM_FLOATS (OFF_RY1 + 64)
#define ATTN_SMEM_BYTES (SMEM_FLOATS * 4)

__global__ void __launch_bounds__(256, 3) attn_kernel(const float* __restrict__ rpe) {
    extern __shared__ float sm[];
    float* qd    = sm + OFF_QD;
    float* kvb   = sm + OFF_KV;
    float* Ps    = sm + OFF_PS;
    float* kb_s  = sm + OFF_KB;
    float* wy0_s = sm + OFF_WY0;
    float* wy1_s = sm + OFF_WY1;
    int*   ry0_p = (int*)(sm + OFF_RY0);
    int*   ry1_p = (int*)(sm + OFF_RY1);

    const int y     = blockIdx.x;       // query row
    const int split = blockIdx.y;
    const int b     = blockIdx.z;
    const int tid   = threadIdx.x;
    const int kt    = tid & 15;
    const int mt    = tid >> 4;         // 0..15
    const int m0    = y * 64;

    const float scale = 0.14433756729740643f;   // 1/sqrt(48)

    // load q tile duplicated: qd[c*128 + 2m{,+1}] = q*scale
    for (int i = tid; i < CC * 64; i += 256) {
        int c = i >> 6, m = i & 63;
        float qv = g_q[(b * CC + c) * NN + m0 + m] * scale;
        qd[c * 128 + 2 * m]     = qv;
        qd[c * 128 + 2 * m + 1] = qv;
    }

    float gxq[4];
#pragma unroll
    for (int mi = 0; mi < 4; mi++)
        gxq[mi] = 47.5f + (float)(mt * 4 + mi) * (95.0f / 63.0f);
    const float gyq = 47.5f + (float)y * (95.0f / 63.0f);

    float rmax[4], rsum[4], f[4];
    ull o01[3] = {0, 0, 0}, o23[3] = {0, 0, 0};
#pragma unroll
    for (int mi = 0; mi < 4; mi++) { rmax[mi] = -1e30f; rsum[mi] = 0.f; }

    const int nbase = split * KEYS_PER_SPLIT;
    for (int t = 0; t < KEYS_PER_SPLIT / 64; t++) {
        const int n0 = nbase + t * 64;
        __syncthreads();   // prev PV done with kvb/Ps; aux free

        // load K tile [c][64]
        for (int i = tid; i < CC * 64; i += 256) {
            int c = i >> 6, n = i & 63;
            kvb[c * 64 + n] = g_k[(b * CC + c) * NN + n0 + n];
        }
        // per-key aux: x base + y interpolation (qy constant per block)
        if (tid < 64) {
            float py = g_pos[(b * NN + n0 + tid) * 2 + 0];
            float px = g_pos[(b * NN + n0 + tid) * 2 + 1];
            kb_s[tid] = 47.5f * px;
            float gy = gyq - 47.5f * py;
            float yf = floorf(gy);
            float fy = gy - yf;
            int   iy = (int)yf;
            wy0_s[tid] = ((unsigned)iy       <= 190u) ? (1.f - fy) : 0.f;
            wy1_s[tid] = ((unsigned)(iy + 1) <= 190u) ? fy : 0.f;
            ry0_p[tid] = min(max(iy, 0), 190) * RPE_S;
            ry1_p[tid] = min(max(iy + 1, 0), 190) * RPE_S;
        }
        __syncthreads();

        // ---- S = qk : packed over key pairs, q broadcast pairs from dup smem ----
        ull sA[4] = {0, 0, 0, 0};   // sA[mi] = (s_k0, s_k1)
        ull sB[4] = {0, 0, 0, 0};   // sB[mi] = (s_k2, s_k3)
#pragma unroll 4
        for (int c = 0; c < CC; c++) {
            ulonglong2 qv0 = *(const ulonglong2*)&qd[c * 128 + mt * 8];      // (q0,q0),(q1,q1)
            ulonglong2 qv1 = *(const ulonglong2*)&qd[c * 128 + mt * 8 + 4];  // (q2,q2),(q3,q3)
            ulonglong2 kp  = *(const ulonglong2*)&kvb[c * 64 + kt * 4];      // (k0,k1),(k2,k3)
            fma2(sA[0], qv0.x, kp.x); fma2(sB[0], qv0.x, kp.y);
            fma2(sA[1], qv0.y, kp.x); fma2(sB[1], qv0.y, kp.y);
            fma2(sA[2], qv1.x, kp.x); fma2(sB[2], qv1.x, kp.y);
            fma2(sA[3], qv1.y, kp.x); fma2(sB[3], qv1.y, kp.y);
        }
        float s[4][4];
#pragma unroll
        for (int mi = 0; mi < 4; mi++) {
            upk2(sA[mi], s[mi][0], s[mi][1]);
            upk2(sB[mi], s[mi][2], s[mi][3]);
        }

        // ---- add RPE bias (global/L2 gather; y-interp precomputed) ----
#pragma unroll
        for (int ki = 0; ki < 4; ki++) {
            int n = kt * 4 + ki;
            float kb  = kb_s[n];
            float wy0 = wy0_s[n], wy1 = wy1_s[n];
            int   ry0 = ry0_p[n], ry1 = ry1_p[n];
#pragma unroll
            for (int mi = 0; mi < 4; mi++) {
                float gx = gxq[mi] - kb;
                float xf = floorf(gx);
                float fx = gx - xf;
                int   xi = (int)xf;
                float w0 = ((unsigned)xi       <= 190u) ? (1.f - fx) : 0.f;
                float w1 = ((unsigned)(xi + 1) <= 190u) ? fx : 0.f;
                int x0 = min(max(xi, 0), 190);
                int x1 = min(max(xi + 1, 0), 190);
                float b0 = rpe[ry0 + x0] * w0 + rpe[ry0 + x1] * w1;
                float b1 = rpe[ry1 + x0] * w0 + rpe[ry1 + x1] * w1;
                s[mi][ki] += wy0 * b0 + wy1 * b1;
            }
        }

        // ---- online softmax (16-lane reduction over kt) ----
#pragma unroll
        for (int mi = 0; mi < 4; mi++) {
            float tmax = fmaxf(fmaxf(s[mi][0], s[mi][1]), fmaxf(s[mi][2], s[mi][3]));
#pragma unroll
            for (int w = 1; w < 16; w <<= 1)
                tmax = fmaxf(tmax, __shfl_xor_sync(0xffffffffu, tmax, w));
            float nmax = fmaxf(rmax[mi], tmax);
            f[mi] = __expf(rmax[mi] - nmax);
            float p0 = __expf(s[mi][0] - nmax);
            float p1 = __expf(s[mi][1] - nmax);
            float p2 = __expf(s[mi][2] - nmax);
            float p3 = __expf(s[mi][3] - nmax);
            s[mi][0] = p0; s[mi][1] = p1; s[mi][2] = p2; s[mi][3] = p3;
            float ps = p0 + p1 + p2 + p3;
#pragma unroll
            for (int w = 1; w < 16; w <<= 1)
                ps += __shfl_xor_sync(0xffffffffu, ps, w);
            rsum[mi] = rsum[mi] * f[mi] + ps;
            rmax[mi] = nmax;
        }
        // write P transposed: Ps[n][m]
#pragma unroll
        for (int ki = 0; ki < 4; ki++) {
            float4 pv = make_float4(s[0][ki], s[1][ki], s[2][ki], s[3][ki]);
            *(float4*)&Ps[(kt * 4 + ki) * 68 + mt * 4] = pv;
        }

        __syncthreads();    // S-phase reads of kvb done; Ps complete

        // load V duplicated: kvb[n*96 + 2c{,+1}]
        for (int i = tid; i < CC * 64; i += 256) {
            int c = i >> 6, n = i & 63;
            float vv = g_v[(b * CC + c) * NN + n0 + n];
            kvb[n * 96 + 2 * c]     = vv;
            kvb[n * 96 + 2 * c + 1] = vv;
        }
        __syncthreads();

        // ---- PV: packed over query pairs, v broadcast pairs from dup smem ----
        const int ct = tid & 15;
        {
            ull f01 = pk2(f[0], f[1]), f23 = pk2(f[2], f[3]);
#pragma unroll
            for (int j = 0; j < 3; j++) {
                o01[j] = mul2(o01[j], f01);
                o23[j] = mul2(o23[j], f23);
            }
        }
#pragma unroll 4
        for (int n = 0; n < 64; n++) {
            ulonglong2 pq = *(const ulonglong2*)&Ps[n * 68 + mt * 4];   // (p0,p1),(p2,p3)
            ull v00 = *(const ull*)&kvb[n * 96 + ct * 6];
            ull v11 = *(const ull*)&kvb[n * 96 + ct * 6 + 2];
            ull v22 = *(const ull*)&kvb[n * 96 + ct * 6 + 4];
            fma2(o01[0], pq.x, v00); fma2(o23[0], pq.y, v00);
            fma2(o01[1], pq.x, v11); fma2(o23[1], pq.y, v11);
            fma2(o01[2], pq.x, v22); fma2(o23[2], pq.y, v22);
        }
    }

    // ---- write partial results ----
    const int ct = tid & 15;
    float o[4][3];
#pragma unroll
    for (int j = 0; j < 3; j++) {
        upk2(o01[j], o[0][j], o[1][j]);
        upk2(o23[j], o[2][j], o[3][j]);
    }
#pragma unroll
    for (int mi = 0; mi < 4; mi++) {
        int m = m0 + mt * 4 + mi;
#pragma unroll
        for (int j = 0; j < 3; j++) {
            int c = ct * 3 + j;
            g_opart[((split * BB + b) * CC + c) * NN + m] = o[mi][j];
        }
        if (ct == 0) {
            g_mpart[(split * BB + b) * NN + m] = rmax[mi];
            g_lpart[(split * BB + b) * NN + m] = rsum[mi];
        }
    }
}

// ---------------- window attention (3 splits x 64 windows x B) ------------------
__global__ void winattn_kernel() {
    int b  = blockIdx.z;
    int sp = blockIdx.y;
    int w  = blockIdx.x;
    int t  = threadIdx.x;

    __shared__ float qsm[64][17];
    __shared__ float vsm[64][17];

    int py, px;
    if (sp == 0)      { int wy = w >> 3, wx = w & 7; py = wy * 8 + (t >> 3); px = wx * 8 + (t & 7); }
    else if (sp == 1) { py = t;  px = w; }
    else              { py = w;  px = t; }
    int pix = py * 64 + px;

    int qbase = (b * 96 + sp * 32) * NN + pix;
#pragma unroll
    for (int c = 0; c < 16; c++) {
        qsm[t][c] = g_x2[qbase + c * NN];
        vsm[t][c] = g_x2[qbase + (16 + c) * NN];
    }
    __syncthreads();

    float qr[16];
#pragma unroll
    for (int c = 0; c < 16; c++) qr[c] = qsm[t][c];

    float lg[64];
    float mx = -1e30f;
    for (int j = 0; j < 64; j++) {
        float d = 0.f;
#pragma unroll
        for (int c = 0; c < 16; c++) d += qr[c] * qsm[j][c];
        lg[j] = d;
        mx = fmaxf(mx, d);
    }
    float s = 0.f;
    for (int j = 0; j < 64; j++) { lg[j] = __expf(lg[j] - mx); s += lg[j]; }
    float inv = 1.f / s;

    float o[16];
#pragma unroll
    for (int c = 0; c < 16; c++) o[c] = 0.f;
    for (int j = 0; j < 64; j++) {
        float p = lg[j] * inv;
#pragma unroll
        for (int c = 0; c < 16; c++) o[c] += p * vsm[j][c];
    }
#pragma unroll
    for (int c = 0; c < 16; c++)
        g_win[(b * CC + sp * 16 + c) * NN + pix] = o[c];
}

// ---------------- final: pout conv + split-KV merge + average (float4) ----------
__global__ void final_kernel(const float* __restrict__ pw, const float* __restrict__ pb,
                             float* __restrict__ out) {
    int idx = blockIdx.x * 256 + threadIdx.x;
    if (idx >= BB * CC * (NN / 4)) return;
    int p4 = idx & (NN / 4 - 1);
    int o  = (idx >> 10) % CC;
    int b  = idx / (CC * (NN / 4));
    float bo = pb[o];
    float4 acc = make_float4(bo, bo, bo, bo);
    const float4* wb = (const float4*)(g_win + b * CC * NN) + p4;
    const float* wr = pw + o * CC;
#pragma unroll 8
    for (int c = 0; c < CC; c++) {
        float4 wv = wb[c * (NN / 4)];
        float w = wr[c];
        acc.x += w * wv.x; acc.y += w * wv.y; acc.z += w * wv.z; acc.w += w * wv.w;
    }

    float4 m0v = ((const float4*)(g_mpart + (0 * BB + b) * NN))[p4];
    float4 m1v = ((const float4*)(g_mpart + (1 * BB + b) * NN))[p4];
    float4 l0v = ((const float4*)(g_lpart + (0 * BB + b) * NN))[p4];
    float4 l1v = ((const float4*)(g_lpart + (1 * BB + b) * NN))[p4];
    float4 o0v = ((const float4*)(g_opart + ((0 * BB + b) * CC + o) * NN))[p4];
    float4 o1v = ((const float4*)(g_opart + ((1 * BB + b) * CC + o) * NN))[p4];

    float4 res;
    {
        float M = fmaxf(m0v.x, m1v.x);
        float e0 = __expf(m0v.x - M), e1 = __expf(m1v.x - M);
        res.x = 0.5f * acc.x + 0.5f * (o0v.x * e0 + o1v.x * e1) / (l0v.x * e0 + l1v.x * e1);
    }
    {
        float M = fmaxf(m0v.y, m1v.y);
        float e0 = __expf(m0v.y - M), e1 = __expf(m1v.y - M);
        res.y = 0.5f * acc.y + 0.5f * (o0v.y * e0 + o1v.y * e1) / (l0v.y * e0 + l1v.y * e1);
    }
    {
        float M = fmaxf(m0v.z, m1v.z);
        float e0 = __expf(m0v.z - M), e1 = __expf(m1v.z - M);
        res.z = 0.5f * acc.z + 0.5f * (o0v.z * e0 + o1v.z * e1) / (l0v.z * e0 + l1v.z * e1);
    }
    {
        float M = fmaxf(m0v.w, m1v.w);
        float e0 = __expf(m0v.w - M), e1 = __expf(m1v.w - M);
        res.w = 0.5f * acc.w + 0.5f * (o0v.w * e0 + o1v.w * e1) / (l0v.w * e0 + l1v.w * e1);
    }
    ((float4*)out)[idx] = res;
}

// ---------------- launch ---------------------------------------------------------
extern "C" void kernel_launch(void* const* d_in, const int* in_sizes, int n_in,
                              void* d_out, int out_size) {
    const float* x        = (const float*)d_in[0];
    const float* Wq       = (const float*)d_in[1];
    const float* bq       = (const float*)d_in[2];
    const float* off_dw_w = (const float*)d_in[3];
    const float* off_dw_b = (const float*)d_in[4];
    const float* off_ln_g = (const float*)d_in[5];
    const float* off_ln_b = (const float*)d_in[6];
    const float* off_pw_w = (const float*)d_in[7];
    const float* Wk       = (const float*)d_in[8];
    const float* bk       = (const float*)d_in[9];
    const float* Wv       = (const float*)d_in[10];
    const float* bv       = (const float*)d_in[11];
    const float* inp_w    = (const float*)d_in[12];
    const float* inp_b    = (const float*)d_in[13];
    const float* bn_g     = (const float*)d_in[14];
    const float* bn_b     = (const float*)d_in[15];
    const float* bn_mean  = (const float*)d_in[16];
    const float* bn_var   = (const float*)d_in[17];
    const float* pout_w   = (const float*)d_in[18];
    const float* pout_b   = (const float*)d_in[19];
    const float* rpe      = (const float*)d_in[20];
    float* out = (float*)d_out;

    cudaFuncSetAttribute(attn_kernel, cudaFuncAttributeMaxDynamicSharedMemorySize,
                         ATTN_SMEM_BYTES);

    conv_q_kernel<<<(BB * CC * (NN / 4) + 255) / 256, 256>>>(x, Wq, bq);
    conv_x2_kernel<<<(BB * 96 * (NN / 4) + 255) / 256, 256>>>(x, inp_w, inp_b,
                                                              bn_g, bn_b, bn_mean, bn_var);
    deform_kernel<<<dim3(HH, BB), 256>>>(x, off_dw_w, off_dw_b,
                                         off_ln_g, off_ln_b, off_pw_w);
    conv_kv_kernel<<<(BB * CC * (NN / 4) + 255) / 256, 256>>>(Wk, bk, Wv, bv);
    attn_kernel<<<dim3(64, NSPLIT, BB), 256, ATTN_SMEM_BYTES>>>(rpe);
    winattn_kernel<<<dim3(64, 3, BB), 64>>>();
    final_kernel<<<(BB * CC * (NN / 4) + 255) / 256, 256>>>(pout_w, pout_b, out);
}

// round 5
// speedup vs baseline: 1.5282x; 1.3021x over previous
#include <cuda_runtime.h>
#include <math.h>

// Problem constants
#define BB 2
#define CC 48
#define HH 64
#define WW 64
#define NN 4096
#define RPE_S 191
#define NSPLIT 2
#define KEYS_PER_SPLIT (NN / NSPLIT)

// ---------------- scratch (device globals; no allocation allowed) -------------
__device__ float g_q  [BB*CC*NN];
__device__ float g_x2 [BB*96*NN];
__device__ float g_pos[BB*NN*2];
__device__ float g_xs [BB*CC*NN];
__device__ float g_k  [BB*CC*NN];
__device__ float g_v  [BB*CC*NN];
__device__ float g_win[BB*CC*NN];
__device__ float g_opart[NSPLIT*BB*CC*NN];
__device__ float g_mpart[NSPLIT*BB*NN];
__device__ float g_lpart[NSPLIT*BB*NN];

// ---------------- generic helpers ----------------------------------------------
__device__ __forceinline__ float bilin(const float* __restrict__ img, int H, int W,
                                       float gx, float gy) {
    float x0f = floorf(gx), y0f = floorf(gy);
    int   x0  = (int)x0f,   y0  = (int)y0f;
    float wx  = gx - x0f,   wy  = gy - y0f;
    float acc = 0.f;
#pragma unroll
    for (int dy = 0; dy < 2; dy++) {
        int yc = y0 + dy;
        if (yc < 0 || yc >= H) continue;
        float wyv = dy ? wy : (1.f - wy);
#pragma unroll
        for (int dx = 0; dx < 2; dx++) {
            int xc = x0 + dx;
            if (xc < 0 || xc >= W) continue;
            float wxv = dx ? wx : (1.f - wx);
            acc += img[yc * W + xc] * (wyv * wxv);
        }
    }
    return acc;
}

// ---------------- 1x1 conv: q = Wq x + bq (float4) -----------------------------
__global__ void conv_q_kernel(const float* __restrict__ x, const float* __restrict__ W,
                              const float* __restrict__ bias) {
    int idx = blockIdx.x * 256 + threadIdx.x;
    if (idx >= BB * CC * (NN / 4)) return;
    int p4 = idx & (NN / 4 - 1);
    int o  = (idx >> 10) % CC;
    int b  = idx / (CC * (NN / 4));
    float bo = bias[o];
    float4 acc = make_float4(bo, bo, bo, bo);
    const float4* xb = (const float4*)(x + b * CC * NN) + p4;
    const float* wr = W + o * CC;
#pragma unroll 8
    for (int c = 0; c < CC; c++) {
        float4 xv = xb[c * (NN / 4)];
        float w = wr[c];
        acc.x += w * xv.x; acc.y += w * xv.y; acc.z += w * xv.z; acc.w += w * xv.w;
    }
    ((float4*)g_q)[idx] = acc;
}

// ---------------- 1x1 conv (96ch) + BN ------------------------------------------
__global__ void conv_x2_kernel(const float* __restrict__ x, const float* __restrict__ W,
                               const float* __restrict__ bias,
                               const float* __restrict__ bng, const float* __restrict__ bnb,
                               const float* __restrict__ bnm, const float* __restrict__ bnv) {
    int idx = blockIdx.x * 256 + threadIdx.x;
    if (idx >= BB * 96 * (NN / 4)) return;
    int p4 = idx & (NN / 4 - 1);
    int o  = (idx >> 10) % 96;
    int b  = idx / (96 * (NN / 4));
    float bo = bias[o];
    float4 acc = make_float4(bo, bo, bo, bo);
    const float4* xb = (const float4*)(x + b * CC * NN) + p4;
    const float* wr = W + o * CC;
#pragma unroll 8
    for (int c = 0; c < CC; c++) {
        float4 xv = xb[c * (NN / 4)];
        float w = wr[c];
        acc.x += w * xv.x; acc.y += w * xv.y; acc.z += w * xv.z; acc.w += w * xv.w;
    }
    float sc = rsqrtf(bnv[o] + 1e-5f) * bng[o];
    float sh = bnb[o] - bnm[o] * sc;
    acc.x = acc.x * sc + sh; acc.y = acc.y * sc + sh;
    acc.z = acc.z * sc + sh; acc.w = acc.w * sc + sh;
    ((float4*)g_x2)[idx] = acc;
}

// ---------------- offset head + position + grid-sample x ------------------------
__global__ void deform_kernel(const float* __restrict__ x,
                              const float* __restrict__ dww, const float* __restrict__ dwb,
                              const float* __restrict__ lng, const float* __restrict__ lnb,
                              const float* __restrict__ pww) {
    int b = blockIdx.y;
    int y = blockIdx.x;
    int tid = threadIdx.x;
    __shared__ float ts[CC * WW];
    __shared__ float posr[WW * 2];

    for (int i = tid; i < CC * WW; i += 256) {
        int c = i >> 6, px = i & 63;
        float acc = dwb[c];
        const float* qc = g_q + (b * CC + c) * NN;
        const float* wc = dww + c * 9;
#pragma unroll
        for (int ky = 0; ky < 3; ky++) {
            int yy = y + ky - 1;
            if (yy < 0 || yy > 63) continue;
#pragma unroll
            for (int kx = 0; kx < 3; kx++) {
                int xx = px + kx - 1;
                if (xx < 0 || xx > 63) continue;
                acc += qc[(yy << 6) + xx] * wc[ky * 3 + kx];
            }
        }
        ts[c * 64 + px] = acc;
    }
    __syncthreads();

    if (tid < WW) {
        int px = tid;
        float mu = 0.f;
        for (int c = 0; c < CC; c++) mu += ts[c * 64 + px];
        mu *= (1.f / CC);
        float var = 0.f;
        for (int c = 0; c < CC; c++) { float d = ts[c * 64 + px] - mu; var += d * d; }
        var *= (1.f / CC);
        float rs = rsqrtf(var + 1e-5f);
        float a0 = 0.f, a1 = 0.f;
        for (int c = 0; c < CC; c++) {
            float v = (ts[c * 64 + px] - mu) * rs * lng[c] + lnb[c];
            v = 0.5f * v * (1.f + erff(v * 0.7071067811865475f));
            a0 += pww[c] * v;
            a1 += pww[CC + c] * v;
        }
        float py  = tanhf(a0) * (2.f / 63.f) + ((0.5f + (float)y ) * (2.f / 63.f) - 1.f);
        float pxx = tanhf(a1) * (2.f / 63.f) + ((0.5f + (float)px) * (2.f / 63.f) - 1.f);
        posr[px * 2 + 0] = py;
        posr[px * 2 + 1] = pxx;
        int n = (y << 6) + px;
        g_pos[(b * NN + n) * 2 + 0] = py;
        g_pos[(b * NN + n) * 2 + 1] = pxx;
    }
    __syncthreads();

    for (int i = tid; i < CC * WW; i += 256) {
        int c = i >> 6, px = i & 63;
        float py  = posr[px * 2 + 0];
        float pxx = posr[px * 2 + 1];
        float gx = (pxx + 1.f) * 0.5f * 63.f;
        float gy = (py  + 1.f) * 0.5f * 63.f;
        const float* img = x + (b * CC + c) * NN;
        g_xs[(b * CC + c) * NN + (y << 6) + px] = bilin(img, HH, WW, gx, gy);
    }
}

// ---------------- k,v projections (float4) ---------------------------------------
__global__ void conv_kv_kernel(const float* __restrict__ Wk, const float* __restrict__ bk,
                               const float* __restrict__ Wv, const float* __restrict__ bv) {
    int idx = blockIdx.x * 256 + threadIdx.x;
    if (idx >= BB * CC * (NN / 4)) return;
    int p4 = idx & (NN / 4 - 1);
    int o  = (idx >> 10) % CC;
    int b  = idx / (CC * (NN / 4));
    float bko = bk[o], bvo = bv[o];
    float4 ak = make_float4(bko, bko, bko, bko);
    float4 av = make_float4(bvo, bvo, bvo, bvo);
    const float4* xb = (const float4*)(g_xs + b * CC * NN) + p4;
    const float* wkr = Wk + o * CC;
    const float* wvr = Wv + o * CC;
#pragma unroll 8
    for (int c = 0; c < CC; c++) {
        float4 xv = xb[c * (NN / 4)];
        float wk = wkr[c], wv = wvr[c];
        ak.x += wk * xv.x; ak.y += wk * xv.y; ak.z += wk * xv.z; ak.w += wk * xv.w;
        av.x += wv * xv.x; av.y += wv * xv.y; av.z += wv * xv.z; av.w += wv * xv.w;
    }
    ((float4*)g_k)[idx] = ak;
    ((float4*)g_v)[idx] = av;
}

// ---------------- fused flash attention (R2 base + coalesced bias phase) --------
// block: 256 threads, 64 queries (one image row), 64-key tiles, split-KV=2.
// Phase A: bias -> Ps[n][m]; warp owns 8 keys, lanes sweep consecutive queries
//          (coalesced rpe gathers: ~6-7 sectors per warp load vs 16 rows before).
// Phase B: S = QK (4x4 register tile) + bias from Ps, softmax, P overwrites Ps.
// PV phase: thread = (ct = tid&15 -> 3 channels, mt -> 4 queries).
__global__ void __launch_bounds__(256, 2) attn_kernel(const float* __restrict__ rpe) {
    const int y     = blockIdx.x;       // query row (64 queries m0..m0+63)
    const int split = blockIdx.y;
    const int b     = blockIdx.z;
    const int tid   = threadIdx.x;
    const int kt    = tid & 15;
    const int mt    = tid >> 4;
    const int m0    = y * 64;
    const int wid   = tid >> 5;
    const int lane  = tid & 31;

    __shared__ __align__(16) float qsm[CC * 64];     // [c][m]
    __shared__ __align__(16) float kvbuf[64 * 49];   // k: [c][n] / v: [n][c]
    __shared__ __align__(16) float Ps[64 * 68];      // bias, then P: [n][m]

    const float scale = 0.14433756729740643f;        // 1/sqrt(48)

    // load q tile (pre-scaled), layout [c][m]
    for (int i = tid; i < CC * 64; i += 256) {
        int c = i >> 6, m = i & 63;
        qsm[c * 64 + m] = g_q[(b * CC + c) * NN + m0 + m] * scale;
    }

    const float gyq  = 47.5f + (float)y * (95.0f / 63.0f);
    const float step = 95.0f / 63.0f;

    float rmax[4], rsum[4], f[4];
    float o[4][3];
#pragma unroll
    for (int mi = 0; mi < 4; mi++) {
        rmax[mi] = -1e30f; rsum[mi] = 0.f;
        o[mi][0] = o[mi][1] = o[mi][2] = 0.f;
    }

    const int nbase = split * KEYS_PER_SPLIT;
    for (int t = 0; t < KEYS_PER_SPLIT / 64; t++) {
        const int n0 = nbase + t * 64;
        __syncthreads();   // prev PV done with kvbuf/Ps

        // load K tile [c][n]
        for (int i = tid; i < CC * 64; i += 256) {
            int c = i >> 6, n = i & 63;
            kvbuf[c * 64 + n] = g_k[(b * CC + c) * NN + n0 + n];
        }

        // ---- phase A: bias -> Ps[n][m] (warp: 8 keys; lanes: queries) ----
#pragma unroll
        for (int kk = 0; kk < 8; kk++) {
            int n = wid * 8 + kk;
            float py = g_pos[(b * NN + n0 + n) * 2 + 0];   // broadcast
            float px = g_pos[(b * NN + n0 + n) * 2 + 1];
            float kb = 47.5f * px;
            float gy = gyq - 47.5f * py;
            float yf = floorf(gy);
            float fy = gy - yf;
            int   iy = (int)yf;
            float wy0 = ((unsigned)iy       <= 190u) ? (1.f - fy) : 0.f;
            float wy1 = ((unsigned)(iy + 1) <= 190u) ? fy : 0.f;
            const float* r0 = rpe + min(max(iy, 0), 190) * RPE_S;
            const float* r1 = rpe + min(max(iy + 1, 0), 190) * RPE_S;
#pragma unroll
            for (int h = 0; h < 2; h++) {
                int m = h * 32 + lane;
                float gx = 47.5f + (float)m * step - kb;
                float xf = floorf(gx);
                float fx = gx - xf;
                int   xi = (int)xf;
                float w0 = ((unsigned)xi       <= 190u) ? (1.f - fx) : 0.f;
                float w1 = ((unsigned)(xi + 1) <= 190u) ? fx : 0.f;
                int x0 = min(max(xi, 0), 190);
                int x1 = min(max(xi + 1, 0), 190);
                float b0 = r0[x0] * w0 + r0[x1] * w1;
                float b1 = r1[x0] * w0 + r1[x1] * w1;
                Ps[n * 68 + m] = wy0 * b0 + wy1 * b1;
            }
        }
        __syncthreads();

        // ---- phase B: S = qk (4x4 register tile) + bias ----
        float s[4][4];
#pragma unroll
        for (int a = 0; a < 4; a++)
#pragma unroll
            for (int bb2 = 0; bb2 < 4; bb2++) s[a][bb2] = 0.f;

#pragma unroll 8
        for (int c = 0; c < CC; c++) {
            float4 qv = *(const float4*)&qsm[c * 64 + mt * 4];
            float4 kv = *(const float4*)&kvbuf[c * 64 + kt * 4];
            s[0][0] += qv.x * kv.x; s[0][1] += qv.x * kv.y; s[0][2] += qv.x * kv.z; s[0][3] += qv.x * kv.w;
            s[1][0] += qv.y * kv.x; s[1][1] += qv.y * kv.y; s[1][2] += qv.y * kv.z; s[1][3] += qv.y * kv.w;
            s[2][0] += qv.z * kv.x; s[2][1] += qv.z * kv.y; s[2][2] += qv.z * kv.z; s[2][3] += qv.z * kv.w;
            s[3][0] += qv.w * kv.x; s[3][1] += qv.w * kv.y; s[3][2] += qv.w * kv.z; s[3][3] += qv.w * kv.w;
        }
#pragma unroll
        for (int ki = 0; ki < 4; ki++) {
            float4 bv = *(const float4*)&Ps[(kt * 4 + ki) * 68 + mt * 4];
            s[0][ki] += bv.x; s[1][ki] += bv.y; s[2][ki] += bv.z; s[3][ki] += bv.w;
        }

        // ---- online softmax (16-lane reduction over kt) ----
#pragma unroll
        for (int mi = 0; mi < 4; mi++) {
            float tmax = fmaxf(fmaxf(s[mi][0], s[mi][1]), fmaxf(s[mi][2], s[mi][3]));
#pragma unroll
            for (int w = 1; w < 16; w <<= 1)
                tmax = fmaxf(tmax, __shfl_xor_sync(0xffffffffu, tmax, w));
            float nmax = fmaxf(rmax[mi], tmax);
            f[mi] = __expf(rmax[mi] - nmax);
            float p0 = __expf(s[mi][0] - nmax);
            float p1 = __expf(s[mi][1] - nmax);
            float p2 = __expf(s[mi][2] - nmax);
            float p3 = __expf(s[mi][3] - nmax);
            s[mi][0] = p0; s[mi][1] = p1; s[mi][2] = p2; s[mi][3] = p3;
            float ps = p0 + p1 + p2 + p3;
#pragma unroll
            for (int w = 1; w < 16; w <<= 1)
                ps += __shfl_xor_sync(0xffffffffu, ps, w);
            rsum[mi] = rsum[mi] * f[mi] + ps;
            rmax[mi] = nmax;
        }
        // write P (each thread overwrites exactly the Ps cells it read)
#pragma unroll
        for (int ki = 0; ki < 4; ki++) {
            float4 pv = make_float4(s[0][ki], s[1][ki], s[2][ki], s[3][ki]);
            *(float4*)&Ps[(kt * 4 + ki) * 68 + mt * 4] = pv;
        }

        __syncthreads();    // S-phase reads of kvbuf done; Ps complete

        // load V tile into the same buffer, layout [n][c] (padded 49)
        for (int i = tid; i < CC * 64; i += 256) {
            int c = i >> 6, n = i & 63;
            kvbuf[n * 49 + c] = g_v[(b * CC + c) * NN + n0 + n];
        }
        __syncthreads();

        // ---- PV: thread = (ct = tid&15 -> 3 channels, mt -> 4 queries) ----
        const int ct = tid & 15;
#pragma unroll
        for (int mi = 0; mi < 4; mi++) {
#pragma unroll
            for (int j = 0; j < 3; j++) o[mi][j] *= f[mi];
        }
#pragma unroll 2
        for (int n = 0; n < 64; n++) {
            float4 p4 = *(const float4*)&Ps[n * 68 + mt * 4];
            float v0 = kvbuf[n * 49 + ct * 3 + 0];
            float v1 = kvbuf[n * 49 + ct * 3 + 1];
            float v2 = kvbuf[n * 49 + ct * 3 + 2];
            o[0][0] += p4.x * v0; o[0][1] += p4.x * v1; o[0][2] += p4.x * v2;
            o[1][0] += p4.y * v0; o[1][1] += p4.y * v1; o[1][2] += p4.y * v2;
            o[2][0] += p4.z * v0; o[2][1] += p4.z * v1; o[2][2] += p4.z * v2;
            o[3][0] += p4.w * v0; o[3][1] += p4.w * v1; o[3][2] += p4.w * v2;
        }
    }

    // ---- write partial results ----
    const int ct = tid & 15;
#pragma unroll
    for (int mi = 0; mi < 4; mi++) {
        int m = m0 + mt * 4 + mi;
#pragma unroll
        for (int j = 0; j < 3; j++) {
            int c = ct * 3 + j;
            g_opart[((split * BB + b) * CC + c) * NN + m] = o[mi][j];
        }
        if (ct == 0) {
            g_mpart[(split * BB + b) * NN + m] = rmax[mi];
            g_lpart[(split * BB + b) * NN + m] = rsum[mi];
        }
    }
}

// ---------------- window attention (3 splits x 64 windows x B) ------------------
__global__ void winattn_kernel() {
    int b  = blockIdx.z;
    int sp = blockIdx.y;
    int w  = blockIdx.x;
    int t  = threadIdx.x;

    __shared__ float qsm[64][17];
    __shared__ float vsm[64][17];

    int py, px;
    if (sp == 0)      { int wy = w >> 3, wx = w & 7; py = wy * 8 + (t >> 3); px = wx * 8 + (t & 7); }
    else if (sp == 1) { py = t;  px = w; }
    else              { py = w;  px = t; }
    int pix = py * 64 + px;

    int qbase = (b * 96 + sp * 32) * NN + pix;
#pragma unroll
    for (int c = 0; c < 16; c++) {
        qsm[t][c] = g_x2[qbase + c * NN];
        vsm[t][c] = g_x2[qbase + (16 + c) * NN];
    }
    __syncthreads();

    float qr[16];
#pragma unroll
    for (int c = 0; c < 16; c++) qr[c] = qsm[t][c];

    float lg[64];
    float mx = -1e30f;
    for (int j = 0; j < 64; j++) {
        float d = 0.f;
#pragma unroll
        for (int c = 0; c < 16; c++) d += qr[c] * qsm[j][c];
        lg[j] = d;
        mx = fmaxf(mx, d);
    }
    float s = 0.f;
    for (int j = 0; j < 64; j++) { lg[j] = __expf(lg[j] - mx); s += lg[j]; }
    float inv = 1.f / s;

    float o[16];
#pragma unroll
    for (int c = 0; c < 16; c++) o[c] = 0.f;
    for (int j = 0; j < 64; j++) {
        float p = lg[j] * inv;
#pragma unroll
        for (int c = 0; c < 16; c++) o[c] += p * vsm[j][c];
    }
#pragma unroll
    for (int c = 0; c < 16; c++)
        g_win[(b * CC + sp * 16 + c) * NN + pix] = o[c];
}

// ---------------- final: pout conv + split-KV merge + average (float4) ----------
__global__ void final_kernel(const float* __restrict__ pw, const float* __restrict__ pb,
                             float* __restrict__ out) {
    int idx = blockIdx.x * 256 + threadIdx.x;
    if (idx >= BB * CC * (NN / 4)) return;
    int p4 = idx & (NN / 4 - 1);
    int o  = (idx >> 10) % CC;
    int b  = idx / (CC * (NN / 4));
    float bo = pb[o];
    float4 acc = make_float4(bo, bo, bo, bo);
    const float4* wb = (const float4*)(g_win + b * CC * NN) + p4;
    const float* wr = pw + o * CC;
#pragma unroll 8
    for (int c = 0; c < CC; c++) {
        float4 wv = wb[c * (NN / 4)];
        float w = wr[c];
        acc.x += w * wv.x; acc.y += w * wv.y; acc.z += w * wv.z; acc.w += w * wv.w;
    }

    float4 m0v = ((const float4*)(g_mpart + (0 * BB + b) * NN))[p4];
    float4 m1v = ((const float4*)(g_mpart + (1 * BB + b) * NN))[p4];
    float4 l0v = ((const float4*)(g_lpart + (0 * BB + b) * NN))[p4];
    float4 l1v = ((const float4*)(g_lpart + (1 * BB + b) * NN))[p4];
    float4 o0v = ((const float4*)(g_opart + ((0 * BB + b) * CC + o) * NN))[p4];
    float4 o1v = ((const float4*)(g_opart + ((1 * BB + b) * CC + o) * NN))[p4];

    float4 res;
    {
        float M = fmaxf(m0v.x, m1v.x);
        float e0 = __expf(m0v.x - M), e1 = __expf(m1v.x - M);
        res.x = 0.5f * acc.x + 0.5f * (o0v.x * e0 + o1v.x * e1) / (l0v.x * e0 + l1v.x * e1);
    }
    {
        float M = fmaxf(m0v.y, m1v.y);
        float e0 = __expf(m0v.y - M), e1 = __expf(m1v.y - M);
        res.y = 0.5f * acc.y + 0.5f * (o0v.y * e0 + o1v.y * e1) / (l0v.y * e0 + l1v.y * e1);
    }
    {
        float M = fmaxf(m0v.z, m1v.z);
        float e0 = __expf(m0v.z - M), e1 = __expf(m1v.z - M);
        res.z = 0.5f * acc.z + 0.5f * (o0v.z * e0 + o1v.z * e1) / (l0v.z * e0 + l1v.z * e1);
    }
    {
        float M = fmaxf(m0v.w, m1v.w);
        float e0 = __expf(m0v.w - M), e1 = __expf(m1v.w - M);
        res.w = 0.5f * acc.w + 0.5f * (o0v.w * e0 + o1v.w * e1) / (l0v.w * e0 + l1v.w * e1);
    }
    ((float4*)out)[idx] = res;
}

// ---------------- launch ---------------------------------------------------------
extern "C" void kernel_launch(void* const* d_in, const int* in_sizes, int n_in,
                              void* d_out, int out_size) {
    const float* x        = (const float*)d_in[0];
    const float* Wq       = (const float*)d_in[1];
    const float* bq       = (const float*)d_in[2];
    const float* off_dw_w = (const float*)d_in[3];
    const float* off_dw_b = (const float*)d_in[4];
    const float* off_ln_g = (const float*)d_in[5];
    const float* off_ln_b = (const float*)d_in[6];
    const float* off_pw_w = (const float*)d_in[7];
    const float* Wk       = (const float*)d_in[8];
    const float* bk       = (const float*)d_in[9];
    const float* Wv       = (const float*)d_in[10];
    const float* bv       = (const float*)d_in[11];
    const float* inp_w    = (const float*)d_in[12];
    const float* inp_b    = (const float*)d_in[13];
    const float* bn_g     = (const float*)d_in[14];
    const float* bn_b     = (const float*)d_in[15];
    const float* bn_mean  = (const float*)d_in[16];
    const float* bn_var   = (const float*)d_in[17];
    const float* pout_w   = (const float*)d_in[18];
    const float* pout_b   = (const float*)d_in[19];
    const float* rpe      = (const float*)d_in[20];
    float* out = (float*)d_out;

    conv_q_kernel<<<(BB * CC * (NN / 4) + 255) / 256, 256>>>(x, Wq, bq);
    conv_x2_kernel<<<(BB * 96 * (NN / 4) + 255) / 256, 256>>>(x, inp_w, inp_b,
                                                              bn_g, bn_b, bn_mean, bn_var);
    deform_kernel<<<dim3(HH, BB), 256>>>(x, off_dw_w, off_dw_b,
                                         off_ln_g, off_ln_b, off_pw_w);
    conv_kv_kernel<<<(BB * CC * (NN / 4) + 255) / 256, 256>>>(Wk, bk, Wv, bv);
    attn_kernel<<<dim3(64, NSPLIT, BB), 256>>>(rpe);
    winattn_kernel<<<dim3(64, 3, BB), 64>>>();
    final_kernel<<<(BB * CC * (NN / 4) + 255) / 256, 256>>>(pout_w, pout_b, out);
}

// round 6
// speedup vs baseline: 2.0543x; 1.3443x over previous
#include <cuda_runtime.h>
#include <math.h>
#include <stdint.h>

// Problem constants
#define BB 2
#define CC 48
#define HH 64
#define WW 64
#define NN 4096
#define RPE_S 191
#define NSPLIT 4
#define KEYS_PER_SPLIT (NN / NSPLIT)

// ---------------- scratch (device globals; no allocation allowed) -------------
__device__ float g_q  [BB*CC*NN];
__device__ float g_x2 [BB*96*NN];
__device__ float g_pos[BB*NN*2];
__device__ float g_xs [BB*CC*NN];
__device__ float g_k  [BB*CC*NN];
__device__ float g_v  [BB*CC*NN];
__device__ float g_win[BB*CC*NN];
__device__ float g_opart[NSPLIT*BB*CC*NN];
__device__ float g_mpart[NSPLIT*BB*NN];
__device__ float g_lpart[NSPLIT*BB*NN];

// ---------------- tf32 MMA helpers ----------------------------------------------
__device__ __forceinline__ uint32_t f2tf(float f) {
    uint32_t r; asm("cvt.rna.tf32.f32 %0, %1;" : "=r"(r) : "f"(f)); return r;
}
__device__ __forceinline__ void mma_tf32(float* c,
                                         uint32_t a0, uint32_t a1, uint32_t a2, uint32_t a3,
                                         uint32_t b0, uint32_t b1) {
    asm("mma.sync.aligned.m16n8k8.row.col.f32.tf32.tf32.f32 "
        "{%0,%1,%2,%3}, {%4,%5,%6,%7}, {%8,%9}, {%0,%1,%2,%3};"
        : "+f"(c[0]), "+f"(c[1]), "+f"(c[2]), "+f"(c[3])
        : "r"(a0), "r"(a1), "r"(a2), "r"(a3), "r"(b0), "r"(b1));
}

// ---------------- generic helpers ----------------------------------------------
__device__ __forceinline__ float bilin(const float* __restrict__ img, int H, int W,
                                       float gx, float gy) {
    float x0f = floorf(gx), y0f = floorf(gy);
    int   x0  = (int)x0f,   y0  = (int)y0f;
    float wx  = gx - x0f,   wy  = gy - y0f;
    float acc = 0.f;
#pragma unroll
    for (int dy = 0; dy < 2; dy++) {
        int yc = y0 + dy;
        if (yc < 0 || yc >= H) continue;
        float wyv = dy ? wy : (1.f - wy);
#pragma unroll
        for (int dx = 0; dx < 2; dx++) {
            int xc = x0 + dx;
            if (xc < 0 || xc >= W) continue;
            float wxv = dx ? wx : (1.f - wx);
            acc += img[yc * W + xc] * (wyv * wxv);
        }
    }
    return acc;
}

// ---------------- 1x1 conv: q = Wq x + bq (float4) -----------------------------
__global__ void conv_q_kernel(const float* __restrict__ x, const float* __restrict__ W,
                              const float* __restrict__ bias) {
    int idx = blockIdx.x * 256 + threadIdx.x;
    if (idx >= BB * CC * (NN / 4)) return;
    int p4 = idx & (NN / 4 - 1);
    int o  = (idx >> 10) % CC;
    int b  = idx / (CC * (NN / 4));
    float bo = bias[o];
    float4 acc = make_float4(bo, bo, bo, bo);
    const float4* xb = (const float4*)(x + b * CC * NN) + p4;
    const float* wr = W + o * CC;
#pragma unroll 8
    for (int c = 0; c < CC; c++) {
        float4 xv = xb[c * (NN / 4)];
        float w = wr[c];
        acc.x += w * xv.x; acc.y += w * xv.y; acc.z += w * xv.z; acc.w += w * xv.w;
    }
    ((float4*)g_q)[idx] = acc;
}

// ---------------- 1x1 conv (96ch) + BN ------------------------------------------
__global__ void conv_x2_kernel(const float* __restrict__ x, const float* __restrict__ W,
                               const float* __restrict__ bias,
                               const float* __restrict__ bng, const float* __restrict__ bnb,
                               const float* __restrict__ bnm, const float* __restrict__ bnv) {
    int idx = blockIdx.x * 256 + threadIdx.x;
    if (idx >= BB * 96 * (NN / 4)) return;
    int p4 = idx & (NN / 4 - 1);
    int o  = (idx >> 10) % 96;
    int b  = idx / (96 * (NN / 4));
    float bo = bias[o];
    float4 acc = make_float4(bo, bo, bo, bo);
    const float4* xb = (const float4*)(x + b * CC * NN) + p4;
    const float* wr = W + o * CC;
#pragma unroll 8
    for (int c = 0; c < CC; c++) {
        float4 xv = xb[c * (NN / 4)];
        float w = wr[c];
        acc.x += w * xv.x; acc.y += w * xv.y; acc.z += w * xv.z; acc.w += w * xv.w;
    }
    float sc = rsqrtf(bnv[o] + 1e-5f) * bng[o];
    float sh = bnb[o] - bnm[o] * sc;
    acc.x = acc.x * sc + sh; acc.y = acc.y * sc + sh;
    acc.z = acc.z * sc + sh; acc.w = acc.w * sc + sh;
    ((float4*)g_x2)[idx] = acc;
}

// ---------------- offset head + position + grid-sample x ------------------------
__global__ void deform_kernel(const float* __restrict__ x,
                              const float* __restrict__ dww, const float* __restrict__ dwb,
                              const float* __restrict__ lng, const float* __restrict__ lnb,
                              const float* __restrict__ pww) {
    int b = blockIdx.y;
    int y = blockIdx.x;
    int tid = threadIdx.x;
    __shared__ float ts[CC * WW];
    __shared__ float posr[WW * 2];

    for (int i = tid; i < CC * WW; i += 256) {
        int c = i >> 6, px = i & 63;
        float acc = dwb[c];
        const float* qc = g_q + (b * CC + c) * NN;
        const float* wc = dww + c * 9;
#pragma unroll
        for (int ky = 0; ky < 3; ky++) {
            int yy = y + ky - 1;
            if (yy < 0 || yy > 63) continue;
#pragma unroll
            for (int kx = 0; kx < 3; kx++) {
                int xx = px + kx - 1;
                if (xx < 0 || xx > 63) continue;
                acc += qc[(yy << 6) + xx] * wc[ky * 3 + kx];
            }
        }
        ts[c * 64 + px] = acc;
    }
    __syncthreads();

    if (tid < WW) {
        int px = tid;
        float mu = 0.f;
        for (int c = 0; c < CC; c++) mu += ts[c * 64 + px];
        mu *= (1.f / CC);
        float var = 0.f;
        for (int c = 0; c < CC; c++) { float d = ts[c * 64 + px] - mu; var += d * d; }
        var *= (1.f / CC);
        float rs = rsqrtf(var + 1e-5f);
        float a0 = 0.f, a1 = 0.f;
        for (int c = 0; c < CC; c++) {
            float v = (ts[c * 64 + px] - mu) * rs * lng[c] + lnb[c];
            v = 0.5f * v * (1.f + erff(v * 0.7071067811865475f));
            a0 += pww[c] * v;
            a1 += pww[CC + c] * v;
        }
        float py  = tanhf(a0) * (2.f / 63.f) + ((0.5f + (float)y ) * (2.f / 63.f) - 1.f);
        float pxx = tanhf(a1) * (2.f / 63.f) + ((0.5f + (float)px) * (2.f / 63.f) - 1.f);
        posr[px * 2 + 0] = py;
        posr[px * 2 + 1] = pxx;
        int n = (y << 6) + px;
        g_pos[(b * NN + n) * 2 + 0] = py;
        g_pos[(b * NN + n) * 2 + 1] = pxx;
    }
    __syncthreads();

    for (int i = tid; i < CC * WW; i += 256) {
        int c = i >> 6, px = i & 63;
        float py  = posr[px * 2 + 0];
        float pxx = posr[px * 2 + 1];
        float gx = (pxx + 1.f) * 0.5f * 63.f;
        float gy = (py  + 1.f) * 0.5f * 63.f;
        const float* img = x + (b * CC + c) * NN;
        g_xs[(b * CC + c) * NN + (y << 6) + px] = bilin(img, HH, WW, gx, gy);
    }
}

// ---------------- k,v projections (float4) ---------------------------------------
__global__ void conv_kv_kernel(const float* __restrict__ Wk, const float* __restrict__ bk,
                               const float* __restrict__ Wv, const float* __restrict__ bv) {
    int idx = blockIdx.x * 256 + threadIdx.x;
    if (idx >= BB * CC * (NN / 4)) return;
    int p4 = idx & (NN / 4 - 1);
    int o  = (idx >> 10) % CC;
    int b  = idx / (CC * (NN / 4));
    float bko = bk[o], bvo = bv[o];
    float4 ak = make_float4(bko, bko, bko, bko);
    float4 av = make_float4(bvo, bvo, bvo, bvo);
    const float4* xb = (const float4*)(g_xs + b * CC * NN) + p4;
    const float* wkr = Wk + o * CC;
    const float* wvr = Wv + o * CC;
#pragma unroll 8
    for (int c = 0; c < CC; c++) {
        float4 xv = xb[c * (NN / 4)];
        float wk = wkr[c], wv = wvr[c];
        ak.x += wk * xv.x; ak.y += wk * xv.y; ak.z += wk * xv.z; ak.w += wk * xv.w;
        av.x += wv * xv.x; av.y += wv * xv.y; av.z += wv * xv.z; av.w += wv * xv.w;
    }
    ((float4*)g_k)[idx] = ak;
    ((float4*)g_v)[idx] = av;
}

// ---------------- fused flash attention: tf32 tensor-core MMA -------------------
// block: 256 threads (8 warps) = 128 queries (2 image rows); 64-key tiles;
// split-KV=4.  Warp w owns query strip [w*16, w*16+16) x all 64 keys.
// S = QK^T via m16n8k8 tf32 MMA with C initialized from the RPE bias (computed
// into Ps[m][n] by a coalesced per-key sweep).  P -> smem (tf32), PV via MMA.
// smem offsets (floats):
#define AOF_QS 0                        // 128 x 49
#define AOF_KS (AOF_QS + 128*49)        // 48 x 65
#define AOF_VS (AOF_KS + 48*65)         // 64 x 49
#define AOF_PS (AOF_VS + 64*49)         // 128 x 66 (bias, then P)
#define ATTN_SMEM_FLOATS (AOF_PS + 128*66)
#define ATTN_SMEM_BYTES (ATTN_SMEM_FLOATS * 4)

__global__ void __launch_bounds__(256, 2) attn_kernel(const float* __restrict__ rpe) {
    extern __shared__ float sm[];
    float* Qs = sm + AOF_QS;
    float* Ks = sm + AOF_KS;
    float* Vs = sm + AOF_VS;
    float* Ps = sm + AOF_PS;
    const uint32_t* Qu = (const uint32_t*)Qs;
    const uint32_t* Ku = (const uint32_t*)Ks;
    const uint32_t* Vu = (const uint32_t*)Vs;
    const uint32_t* Pu = (const uint32_t*)Ps;

    const int yb    = blockIdx.x;       // query rows 2*yb, 2*yb+1
    const int split = blockIdx.y;
    const int b     = blockIdx.z;
    const int tid   = threadIdx.x;
    const int warp  = tid >> 5;
    const int lane  = tid & 31;
    const int gid   = lane >> 2;        // 0..7
    const int tig   = lane & 3;         // 0..3
    const int m0    = yb * 128;
    const int qrow  = warp * 16 + gid;  // A-frag row (and +8)

    const float scale = 0.14433756729740643f;   // 1/sqrt(48)
    const float step  = 95.0f / 63.0f;

    // load Q tile [m][c] (stride 49), scaled, tf32
    for (int i = tid; i < CC * 128; i += 256) {
        int c = i >> 7, m = i & 127;
        Qs[m * 49 + c] = __uint_as_float(f2tf(g_q[(b * CC + c) * NN + m0 + m] * scale));
    }

    float rmax0 = -1e30f, rmax1 = -1e30f, rsum0 = 0.f, rsum1 = 0.f;
    float o[6][4];
#pragma unroll
    for (int nb = 0; nb < 6; nb++)
#pragma unroll
        for (int j = 0; j < 4; j++) o[nb][j] = 0.f;

    const int nbase = split * KEYS_PER_SPLIT;
    for (int t = 0; t < KEYS_PER_SPLIT / 64; t++) {
        const int n0 = nbase + t * 64;
        __syncthreads();    // prev PV done with Ps/Vs; Ks free

        // load K tile [c][n] (stride 65), tf32
        for (int i = tid; i < CC * 64; i += 256) {
            int c = i >> 6, n = i & 63;
            Ks[c * 65 + n] = __uint_as_float(f2tf(g_k[(b * CC + c) * NN + n0 + n]));
        }

        // bias -> Ps[m][n] (stride 66): warp owns 8 keys, lanes sweep queries
#pragma unroll
        for (int kk = 0; kk < 8; kk++) {
            int n = warp * 8 + kk;
            float py = g_pos[(b * NN + n0 + n) * 2 + 0];
            float px = g_pos[(b * NN + n0 + n) * 2 + 1];
            float kbx = 47.5f * px;
            float wy0[2], wy1[2];
            int   ry0[2], ry1[2];
#pragma unroll
            for (int r = 0; r < 2; r++) {
                float gy = 47.5f + (float)(yb * 2 + r) * step - 47.5f * py;
                float yf = floorf(gy);
                float fy = gy - yf;
                int   iy = (int)yf;
                wy0[r] = ((unsigned)iy       <= 190u) ? (1.f - fy) : 0.f;
                wy1[r] = ((unsigned)(iy + 1) <= 190u) ? fy : 0.f;
                ry0[r] = min(max(iy, 0), 190) * RPE_S;
                ry1[r] = min(max(iy + 1, 0), 190) * RPE_S;
            }
#pragma unroll
            for (int it = 0; it < 4; it++) {
                int m = it * 32 + lane;
                int r = it >> 1;
                float gx = 47.5f + (float)(m & 63) * step - kbx;
                float xf = floorf(gx);
                float fx = gx - xf;
                int   xi = (int)xf;
                float w0 = ((unsigned)xi       <= 190u) ? (1.f - fx) : 0.f;
                float w1 = ((unsigned)(xi + 1) <= 190u) ? fx : 0.f;
                int x0 = min(max(xi, 0), 190);
                int x1 = min(max(xi + 1, 0), 190);
                float b0 = rpe[ry0[r] + x0] * w0 + rpe[ry0[r] + x1] * w1;
                float b1 = rpe[ry1[r] + x0] * w0 + rpe[ry1[r] + x1] * w1;
                Ps[m * 66 + n] = wy0[r] * b0 + wy1[r] * b1;
            }
        }
        __syncthreads();

        // load V tile [n][c] (stride 49), tf32
        for (int i = tid; i < CC * 64; i += 256) {
            int c = i >> 6, n = i & 63;
            Vs[n * 49 + c] = __uint_as_float(f2tf(g_v[(b * CC + c) * NN + n0 + n]));
        }

        // ---- S = QK^T + bias : init C from bias (C-frag positions) ----
        float cS[8][4];
#pragma unroll
        for (int nb = 0; nb < 8; nb++) {
            int col = nb * 8 + 2 * tig;
            cS[nb][0] = Ps[qrow * 66 + col];
            cS[nb][1] = Ps[qrow * 66 + col + 1];
            cS[nb][2] = Ps[(qrow + 8) * 66 + col];
            cS[nb][3] = Ps[(qrow + 8) * 66 + col + 1];
        }
#pragma unroll
        for (int kb = 0; kb < 6; kb++) {
            uint32_t a0 = Qu[qrow * 49 + kb * 8 + tig];
            uint32_t a1 = Qu[(qrow + 8) * 49 + kb * 8 + tig];
            uint32_t a2 = Qu[qrow * 49 + kb * 8 + tig + 4];
            uint32_t a3 = Qu[(qrow + 8) * 49 + kb * 8 + tig + 4];
#pragma unroll
            for (int nb = 0; nb < 8; nb++) {
                uint32_t b0 = Ku[(kb * 8 + tig) * 65 + nb * 8 + gid];
                uint32_t b1 = Ku[(kb * 8 + tig + 4) * 65 + nb * 8 + gid];
                mma_tf32(cS[nb], a0, a1, a2, a3, b0, b1);
            }
        }

        // ---- online softmax (rows qrow, qrow+8) ----
        float tmax0 = -1e30f, tmax1 = -1e30f;
#pragma unroll
        for (int nb = 0; nb < 8; nb++) {
            tmax0 = fmaxf(tmax0, fmaxf(cS[nb][0], cS[nb][1]));
            tmax1 = fmaxf(tmax1, fmaxf(cS[nb][2], cS[nb][3]));
        }
        tmax0 = fmaxf(tmax0, __shfl_xor_sync(0xffffffffu, tmax0, 1));
        tmax0 = fmaxf(tmax0, __shfl_xor_sync(0xffffffffu, tmax0, 2));
        tmax1 = fmaxf(tmax1, __shfl_xor_sync(0xffffffffu, tmax1, 1));
        tmax1 = fmaxf(tmax1, __shfl_xor_sync(0xffffffffu, tmax1, 2));
        float nmax0 = fmaxf(rmax0, tmax0);
        float nmax1 = fmaxf(rmax1, tmax1);
        float f0 = __expf(rmax0 - nmax0);
        float f1 = __expf(rmax1 - nmax1);
        rmax0 = nmax0; rmax1 = nmax1;

        float psum0 = 0.f, psum1 = 0.f;
#pragma unroll
        for (int nb = 0; nb < 8; nb++) {
            float p0 = __expf(cS[nb][0] - nmax0);
            float p1 = __expf(cS[nb][1] - nmax0);
            float p2 = __expf(cS[nb][2] - nmax1);
            float p3 = __expf(cS[nb][3] - nmax1);
            psum0 += p0 + p1;
            psum1 += p2 + p3;
            int col = nb * 8 + 2 * tig;
            float2 w0 = make_float2(__uint_as_float(f2tf(p0)), __uint_as_float(f2tf(p1)));
            float2 w1 = make_float2(__uint_as_float(f2tf(p2)), __uint_as_float(f2tf(p3)));
            *(float2*)&Ps[qrow * 66 + col]       = w0;    // stride 66 even -> 8B aligned
            *(float2*)&Ps[(qrow + 8) * 66 + col] = w1;
        }
        psum0 += __shfl_xor_sync(0xffffffffu, psum0, 1);
        psum0 += __shfl_xor_sync(0xffffffffu, psum0, 2);
        psum1 += __shfl_xor_sync(0xffffffffu, psum1, 1);
        psum1 += __shfl_xor_sync(0xffffffffu, psum1, 2);
        rsum0 = rsum0 * f0 + psum0;
        rsum1 = rsum1 * f1 + psum1;

        // rescale O accumulators
#pragma unroll
        for (int nb = 0; nb < 6; nb++) {
            o[nb][0] *= f0; o[nb][1] *= f0;
            o[nb][2] *= f1; o[nb][3] *= f1;
        }
        __syncthreads();    // Ps(P) + Vs ready for everyone

        // ---- PV: O += P x V ----
#pragma unroll
        for (int kb = 0; kb < 8; kb++) {
            uint32_t a0 = Pu[qrow * 66 + kb * 8 + tig];
            uint32_t a1 = Pu[(qrow + 8) * 66 + kb * 8 + tig];
            uint32_t a2 = Pu[qrow * 66 + kb * 8 + tig + 4];
            uint32_t a3 = Pu[(qrow + 8) * 66 + kb * 8 + tig + 4];
#pragma unroll
            for (int nb = 0; nb < 6; nb++) {
                uint32_t b0 = Vu[(kb * 8 + tig) * 49 + nb * 8 + gid];
                uint32_t b1 = Vu[(kb * 8 + tig + 4) * 49 + nb * 8 + gid];
                mma_tf32(o[nb], a0, a1, a2, a3, b0, b1);
            }
        }
    }

    // ---- write partial results ----
    const int mA = m0 + qrow;
    const int mB = mA + 8;
    float* op = g_opart + (split * BB + b) * CC * NN;
#pragma unroll
    for (int nb = 0; nb < 6; nb++) {
        int ch = nb * 8 + 2 * tig;
        op[ch * NN + mA]       = o[nb][0];
        op[(ch + 1) * NN + mA] = o[nb][1];
        op[ch * NN + mB]       = o[nb][2];
        op[(ch + 1) * NN + mB] = o[nb][3];
    }
    if (tig == 0) {
        g_mpart[(split * BB + b) * NN + mA] = rmax0;
        g_mpart[(split * BB + b) * NN + mB] = rmax1;
        g_lpart[(split * BB + b) * NN + mA] = rsum0;
        g_lpart[(split * BB + b) * NN + mB] = rsum1;
    }
}

// ---------------- window attention (3 splits x 64 windows x B) ------------------
__global__ void winattn_kernel() {
    int b  = blockIdx.z;
    int sp = blockIdx.y;
    int w  = blockIdx.x;
    int t  = threadIdx.x;

    __shared__ float qsm[64][17];
    __shared__ float vsm[64][17];

    int py, px;
    if (sp == 0)      { int wy = w >> 3, wx = w & 7; py = wy * 8 + (t >> 3); px = wx * 8 + (t & 7); }
    else if (sp == 1) { py = t;  px = w; }
    else              { py = w;  px = t; }
    int pix = py * 64 + px;

    int qbase = (b * 96 + sp * 32) * NN + pix;
#pragma unroll
    for (int c = 0; c < 16; c++) {
        qsm[t][c] = g_x2[qbase + c * NN];
        vsm[t][c] = g_x2[qbase + (16 + c) * NN];
    }
    __syncthreads();

    float qr[16];
#pragma unroll
    for (int c = 0; c < 16; c++) qr[c] = qsm[t][c];

    float lg[64];
    float mx = -1e30f;
    for (int j = 0; j < 64; j++) {
        float d = 0.f;
#pragma unroll
        for (int c = 0; c < 16; c++) d += qr[c] * qsm[j][c];
        lg[j] = d;
        mx = fmaxf(mx, d);
    }
    float s = 0.f;
    for (int j = 0; j < 64; j++) { lg[j] = __expf(lg[j] - mx); s += lg[j]; }
    float inv = 1.f / s;

    float o[16];
#pragma unroll
    for (int c = 0; c < 16; c++) o[c] = 0.f;
    for (int j = 0; j < 64; j++) {
        float p = lg[j] * inv;
#pragma unroll
        for (int c = 0; c < 16; c++) o[c] += p * vsm[j][c];
    }
#pragma unroll
    for (int c = 0; c < 16; c++)
        g_win[(b * CC + sp * 16 + c) * NN + pix] = o[c];
}

// ---------------- final: pout conv + split-KV merge (4 splits) + average --------
__global__ void final_kernel(const float* __restrict__ pw, const float* __restrict__ pb,
                             float* __restrict__ out) {
    int idx = blockIdx.x * 256 + threadIdx.x;
    if (idx >= BB * CC * NN) return;
    int p = idx & (NN - 1);
    int o = (idx >> 12) % CC;
    int b = idx / (CC * NN);
    float acc = pb[o];
    const float* wb = g_win + b * CC * NN + p;
    const float* wr = pw + o * CC;
#pragma unroll 8
    for (int c = 0; c < CC; c++) acc += wr[c] * wb[c * NN];

    float M = -1e30f;
#pragma unroll
    for (int s = 0; s < NSPLIT; s++)
        M = fmaxf(M, g_mpart[(s * BB + b) * NN + p]);
    float l = 0.f, ov = 0.f;
#pragma unroll
    for (int s = 0; s < NSPLIT; s++) {
        float e = __expf(g_mpart[(s * BB + b) * NN + p] - M);
        l  += g_lpart[(s * BB + b) * NN + p] * e;
        ov += g_opart[((s * BB + b) * CC + o) * NN + p] * e;
    }
    out[idx] = 0.5f * acc + 0.5f * ov / l;
}

// ---------------- launch ---------------------------------------------------------
extern "C" void kernel_launch(void* const* d_in, const int* in_sizes, int n_in,
                              void* d_out, int out_size) {
    const float* x        = (const float*)d_in[0];
    const float* Wq       = (const float*)d_in[1];
    const float* bq       = (const float*)d_in[2];
    const float* off_dw_w = (const float*)d_in[3];
    const float* off_dw_b = (const float*)d_in[4];
    const float* off_ln_g = (const float*)d_in[5];
    const float* off_ln_b = (const float*)d_in[6];
    const float* off_pw_w = (const float*)d_in[7];
    const float* Wk       = (const float*)d_in[8];
    const float* bk       = (const float*)d_in[9];
    const float* Wv       = (const float*)d_in[10];
    const float* bv       = (const float*)d_in[11];
    const float* inp_w    = (const float*)d_in[12];
    const float* inp_b    = (const float*)d_in[13];
    const float* bn_g     = (const float*)d_in[14];
    const float* bn_b     = (const float*)d_in[15];
    const float* bn_mean  = (const float*)d_in[16];
    const float* bn_var   = (const float*)d_in[17];
    const float* pout_w   = (const float*)d_in[18];
    const float* pout_b   = (const float*)d_in[19];
    const float* rpe      = (const float*)d_in[20];
    float* out = (float*)d_out;

    cudaFuncSetAttribute(attn_kernel, cudaFuncAttributeMaxDynamicSharedMemorySize,
                         ATTN_SMEM_BYTES);

    conv_q_kernel<<<(BB * CC * (NN / 4) + 255) / 256, 256>>>(x, Wq, bq);
    conv_x2_kernel<<<(BB * 96 * (NN / 4) + 255) / 256, 256>>>(x, inp_w, inp_b,
                                                              bn_g, bn_b, bn_mean, bn_var);
    deform_kernel<<<dim3(HH, BB), 256>>>(x, off_dw_w, off_dw_b,
                                         off_ln_g, off_ln_b, off_pw_w);
    conv_kv_kernel<<<(BB * CC * (NN / 4) + 255) / 256, 256>>>(Wk, bk, Wv, bv);
    attn_kernel<<<dim3(NN / 128, NSPLIT, BB), 256, ATTN_SMEM_BYTES>>>(rpe);
    winattn_kernel<<<dim3(64, 3, BB), 64>>>();
    final_kernel<<<(BB * CC * NN + 255) / 256, 256>>>(pout_w, pout_b, out);
}

// round 7
// speedup vs baseline: 2.2651x; 1.1026x over previous
#include <cuda_runtime.h>
#include <math.h>
#include <stdint.h>

// Problem constants
#define BB 2
#define CC 48
#define HH 64
#define WW 64
#define NN 4096
#define RPE_S 191
#define NSPLIT 4
#define KEYS_PER_SPLIT (NN / NSPLIT)

// ---------------- scratch (device globals; no allocation allowed) -------------
__device__ float g_q  [BB*CC*NN];
__device__ float g_x2 [BB*96*NN];
__device__ float g_pos[BB*NN*2];
__device__ float g_xs [BB*CC*NN];
__device__ float g_k  [BB*CC*NN];
__device__ float g_v  [BB*CC*NN];
__device__ float g_win[BB*CC*NN];
__device__ float g_opart[NSPLIT*BB*CC*NN];
__device__ float g_mpart[NSPLIT*BB*NN];
__device__ float g_lpart[NSPLIT*BB*NN];

// ---------------- tf32 MMA helpers ----------------------------------------------
__device__ __forceinline__ uint32_t f2tf(float f) {
    uint32_t r; asm("cvt.rna.tf32.f32 %0, %1;" : "=r"(r) : "f"(f)); return r;
}
__device__ __forceinline__ void mma_tf32(float* c,
                                         uint32_t a0, uint32_t a1, uint32_t a2, uint32_t a3,
                                         uint32_t b0, uint32_t b1) {
    asm("mma.sync.aligned.m16n8k8.row.col.f32.tf32.tf32.f32 "
        "{%0,%1,%2,%3}, {%4,%5,%6,%7}, {%8,%9}, {%0,%1,%2,%3};"
        : "+f"(c[0]), "+f"(c[1]), "+f"(c[2]), "+f"(c[3])
        : "r"(a0), "r"(a1), "r"(a2), "r"(a3), "r"(b0), "r"(b1));
}

// ---------------- generic helpers ----------------------------------------------
__device__ __forceinline__ float bilin(const float* __restrict__ img, int H, int W,
                                       float gx, float gy) {
    float x0f = floorf(gx), y0f = floorf(gy);
    int   x0  = (int)x0f,   y0  = (int)y0f;
    float wx  = gx - x0f,   wy  = gy - y0f;
    float acc = 0.f;
#pragma unroll
    for (int dy = 0; dy < 2; dy++) {
        int yc = y0 + dy;
        if (yc < 0 || yc >= H) continue;
        float wyv = dy ? wy : (1.f - wy);
#pragma unroll
        for (int dx = 0; dx < 2; dx++) {
            int xc = x0 + dx;
            if (xc < 0 || xc >= W) continue;
            float wxv = dx ? wx : (1.f - wx);
            acc += img[yc * W + xc] * (wyv * wxv);
        }
    }
    return acc;
}

// ---------------- 1x1 conv: q = Wq x + bq (4 outputs x 4 pixels / thread) ------
__global__ void conv_q_kernel(const float* __restrict__ x, const float* __restrict__ W,
                              const float* __restrict__ bias) {
    int idx = blockIdx.x * 256 + threadIdx.x;
    if (idx >= BB * (CC / 4) * (NN / 4)) return;
    int p4 = idx & (NN / 4 - 1);
    int og = (idx >> 10) % (CC / 4);
    int b  = idx / ((CC / 4) * (NN / 4));
    float4 acc[4];
#pragma unroll
    for (int u = 0; u < 4; u++) {
        float bo = bias[og * 4 + u];
        acc[u] = make_float4(bo, bo, bo, bo);
    }
    const float4* xb = (const float4*)(x + b * CC * NN) + p4;
#pragma unroll 4
    for (int c = 0; c < CC; c++) {
        float4 xv = xb[c * (NN / 4)];
#pragma unroll
        for (int u = 0; u < 4; u++) {
            float w = W[(og * 4 + u) * CC + c];
            acc[u].x += w * xv.x; acc[u].y += w * xv.y;
            acc[u].z += w * xv.z; acc[u].w += w * xv.w;
        }
    }
#pragma unroll
    for (int u = 0; u < 4; u++)
        ((float4*)g_q)[(b * CC + og * 4 + u) * (NN / 4) + p4] = acc[u];
}

// ---------------- 1x1 conv (96ch) + BN (4 outputs / thread) ---------------------
__global__ void conv_x2_kernel(const float* __restrict__ x, const float* __restrict__ W,
                               const float* __restrict__ bias,
                               const float* __restrict__ bng, const float* __restrict__ bnb,
                               const float* __restrict__ bnm, const float* __restrict__ bnv) {
    int idx = blockIdx.x * 256 + threadIdx.x;
    if (idx >= BB * 24 * (NN / 4)) return;
    int p4 = idx & (NN / 4 - 1);
    int og = (idx >> 10) % 24;
    int b  = idx / (24 * (NN / 4));
    float4 acc[4];
#pragma unroll
    for (int u = 0; u < 4; u++) {
        float bo = bias[og * 4 + u];
        acc[u] = make_float4(bo, bo, bo, bo);
    }
    const float4* xb = (const float4*)(x + b * CC * NN) + p4;
#pragma unroll 4
    for (int c = 0; c < CC; c++) {
        float4 xv = xb[c * (NN / 4)];
#pragma unroll
        for (int u = 0; u < 4; u++) {
            float w = W[(og * 4 + u) * CC + c];
            acc[u].x += w * xv.x; acc[u].y += w * xv.y;
            acc[u].z += w * xv.z; acc[u].w += w * xv.w;
        }
    }
#pragma unroll
    for (int u = 0; u < 4; u++) {
        int o = og * 4 + u;
        float sc = rsqrtf(bnv[o] + 1e-5f) * bng[o];
        float sh = bnb[o] - bnm[o] * sc;
        acc[u].x = acc[u].x * sc + sh; acc[u].y = acc[u].y * sc + sh;
        acc[u].z = acc[u].z * sc + sh; acc[u].w = acc[u].w * sc + sh;
        ((float4*)g_x2)[(b * 96 + o) * (NN / 4) + p4] = acc[u];
    }
}

// ---------------- offset head + position + grid-sample x ------------------------
// 256 threads: dw-conv phase as before; LN/GELU phase = 4 threads per pixel.
__global__ void deform_kernel(const float* __restrict__ x,
                              const float* __restrict__ dww, const float* __restrict__ dwb,
                              const float* __restrict__ lng, const float* __restrict__ lnb,
                              const float* __restrict__ pww) {
    int b = blockIdx.y;
    int y = blockIdx.x;
    int tid = threadIdx.x;
    __shared__ float ts[CC * WW];
    __shared__ float posr[WW * 2];
    __shared__ float redA[4][WW];
    __shared__ float redB[4][WW];

    for (int i = tid; i < CC * WW; i += 256) {
        int c = i >> 6, px = i & 63;
        float acc = dwb[c];
        const float* qc = g_q + (b * CC + c) * NN;
        const float* wc = dww + c * 9;
#pragma unroll
        for (int ky = 0; ky < 3; ky++) {
            int yy = y + ky - 1;
            if (yy < 0 || yy > 63) continue;
#pragma unroll
            for (int kx = 0; kx < 3; kx++) {
                int xx = px + kx - 1;
                if (xx < 0 || xx > 63) continue;
                acc += qc[(yy << 6) + xx] * wc[ky * 3 + kx];
            }
        }
        ts[c * 64 + px] = acc;
    }
    __syncthreads();

    const int sub = tid >> 6;     // 0..3 -> channels sub*12..sub*12+11
    const int px  = tid & 63;
    {
        float s = 0.f;
#pragma unroll
        for (int j = 0; j < 12; j++) s += ts[(sub * 12 + j) * 64 + px];
        redA[sub][px] = s;
    }
    __syncthreads();
    float mu = (redA[0][px] + redA[1][px] + redA[2][px] + redA[3][px]) * (1.f / 48.f);
    {
        float v2 = 0.f;
#pragma unroll
        for (int j = 0; j < 12; j++) {
            float d = ts[(sub * 12 + j) * 64 + px] - mu;
            v2 += d * d;
        }
        redB[sub][px] = v2;
    }
    __syncthreads();
    float rs = rsqrtf((redB[0][px] + redB[1][px] + redB[2][px] + redB[3][px]) * (1.f / 48.f)
                      + 1e-5f);
    {
        float a0 = 0.f, a1 = 0.f;
#pragma unroll
        for (int j = 0; j < 12; j++) {
            int c = sub * 12 + j;
            float v = (ts[c * 64 + px] - mu) * rs * lng[c] + lnb[c];
            v = 0.5f * v * (1.f + erff(v * 0.7071067811865475f));
            a0 += pww[c] * v;
            a1 += pww[CC + c] * v;
        }
        redA[sub][px] = a0;
        redB[sub][px] = a1;
    }
    __syncthreads();
    if (tid < WW) {
        float a0 = redA[0][px] + redA[1][px] + redA[2][px] + redA[3][px];
        float a1 = redB[0][px] + redB[1][px] + redB[2][px] + redB[3][px];
        float py  = tanhf(a0) * (2.f / 63.f) + ((0.5f + (float)y ) * (2.f / 63.f) - 1.f);
        float pxx = tanhf(a1) * (2.f / 63.f) + ((0.5f + (float)px) * (2.f / 63.f) - 1.f);
        posr[px * 2 + 0] = py;
        posr[px * 2 + 1] = pxx;
        int n = (y << 6) + px;
        g_pos[(b * NN + n) * 2 + 0] = py;
        g_pos[(b * NN + n) * 2 + 1] = pxx;
    }
    __syncthreads();

    for (int i = tid; i < CC * WW; i += 256) {
        int c = i >> 6, p = i & 63;
        float py  = posr[p * 2 + 0];
        float pxx = posr[p * 2 + 1];
        float gx = (pxx + 1.f) * 0.5f * 63.f;
        float gy = (py  + 1.f) * 0.5f * 63.f;
        const float* img = x + (b * CC + c) * NN;
        g_xs[(b * CC + c) * NN + (y << 6) + p] = bilin(img, HH, WW, gx, gy);
    }
}

// ---------------- k,v projections (2k+2v outputs / thread) ----------------------
__global__ void conv_kv_kernel(const float* __restrict__ Wk, const float* __restrict__ bk,
                               const float* __restrict__ Wv, const float* __restrict__ bv) {
    int idx = blockIdx.x * 256 + threadIdx.x;
    if (idx >= BB * 24 * (NN / 4)) return;
    int p4 = idx & (NN / 4 - 1);
    int og = (idx >> 10) % 24;
    int b  = idx / (24 * (NN / 4));
    float4 ak[2], av[2];
#pragma unroll
    for (int u = 0; u < 2; u++) {
        float bko = bk[og * 2 + u], bvo = bv[og * 2 + u];
        ak[u] = make_float4(bko, bko, bko, bko);
        av[u] = make_float4(bvo, bvo, bvo, bvo);
    }
    const float4* xb = (const float4*)(g_xs + b * CC * NN) + p4;
#pragma unroll 4
    for (int c = 0; c < CC; c++) {
        float4 xv = xb[c * (NN / 4)];
#pragma unroll
        for (int u = 0; u < 2; u++) {
            float wk = Wk[(og * 2 + u) * CC + c];
            float wv = Wv[(og * 2 + u) * CC + c];
            ak[u].x += wk * xv.x; ak[u].y += wk * xv.y; ak[u].z += wk * xv.z; ak[u].w += wk * xv.w;
            av[u].x += wv * xv.x; av[u].y += wv * xv.y; av[u].z += wv * xv.z; av[u].w += wv * xv.w;
        }
    }
#pragma unroll
    for (int u = 0; u < 2; u++) {
        ((float4*)g_k)[(b * CC + og * 2 + u) * (NN / 4) + p4] = ak[u];
        ((float4*)g_v)[(b * CC + og * 2 + u) * (NN / 4) + p4] = av[u];
    }
}

// ---------------- fused flash attention: tf32 MMA, swizzled smem ----------------
// block: 256 threads (8 warps) = 128 queries; 64-key tiles; split-KV=4.
// Qs stride 52 (A-frag loads conflict-free); Ks swizzled n^((c&3)<<3), stride 64
// (B-frag loads conflict-free); Vs stride 49; Ps stride 66 (bias then P).
#define AOF_QS 0                        // 128 x 52
#define AOF_KS (AOF_QS + 128*52)        // 48 x 64 swizzled
#define AOF_VS (AOF_KS + 48*64)         // 64 x 49
#define AOF_PS (AOF_VS + 64*49)         // 128 x 66
#define ATTN_SMEM_FLOATS (AOF_PS + 128*66)
#define ATTN_SMEM_BYTES (ATTN_SMEM_FLOATS * 4)

__global__ void __launch_bounds__(256, 2) attn_kernel(const float* __restrict__ rpe) {
    extern __shared__ float sm[];
    float* Qs = sm + AOF_QS;
    float* Ks = sm + AOF_KS;
    float* Vs = sm + AOF_VS;
    float* Ps = sm + AOF_PS;
    const uint32_t* Qu = (const uint32_t*)Qs;
    const uint32_t* Ku = (const uint32_t*)Ks;
    const uint32_t* Vu = (const uint32_t*)Vs;
    const uint32_t* Pu = (const uint32_t*)Ps;

    const int yb    = blockIdx.x;
    const int split = blockIdx.y;
    const int b     = blockIdx.z;
    const int tid   = threadIdx.x;
    const int warp  = tid >> 5;
    const int lane  = tid & 31;
    const int gid   = lane >> 2;
    const int tig   = lane & 3;
    const int m0    = yb * 128;
    const int qrow  = warp * 16 + gid;

    const float scale = 0.14433756729740643f;
    const float step  = 95.0f / 63.0f;

    // load Q tile [m][c] (stride 52), scaled, tf32
    for (int i = tid; i < CC * 128; i += 256) {
        int c = i >> 7, m = i & 127;
        Qs[m * 52 + c] = __uint_as_float(f2tf(g_q[(b * CC + c) * NN + m0 + m] * scale));
    }

    float rmax0 = -1e30f, rmax1 = -1e30f, rsum0 = 0.f, rsum1 = 0.f;
    float o[6][4];
#pragma unroll
    for (int nb = 0; nb < 6; nb++)
#pragma unroll
        for (int j = 0; j < 4; j++) o[nb][j] = 0.f;

    const int nbase = split * KEYS_PER_SPLIT;
    for (int t = 0; t < KEYS_PER_SPLIT / 64; t++) {
        const int n0 = nbase + t * 64;
        __syncthreads();

        // load K tile swizzled: Ks[c*64 + (n ^ ((c&3)<<3))], tf32
        for (int i = tid; i < CC * 64; i += 256) {
            int c = i >> 6, n = i & 63;
            Ks[c * 64 + (n ^ ((c & 3) << 3))] =
                __uint_as_float(f2tf(g_k[(b * CC + c) * NN + n0 + n]));
        }

        // bias -> Ps[m][n] (stride 66): warp owns 8 keys, lanes sweep queries
#pragma unroll
        for (int kk = 0; kk < 8; kk++) {
            int n = warp * 8 + kk;
            float py = g_pos[(b * NN + n0 + n) * 2 + 0];
            float px = g_pos[(b * NN + n0 + n) * 2 + 1];
            float kbx = 47.5f * px;
            float wy0[2], wy1[2];
            int   ry0[2], ry1[2];
#pragma unroll
            for (int r = 0; r < 2; r++) {
                float gy = 47.5f + (float)(yb * 2 + r) * step - 47.5f * py;
                float yf = floorf(gy);
                float fy = gy - yf;
                int   iy = (int)yf;
                wy0[r] = ((unsigned)iy       <= 190u) ? (1.f - fy) : 0.f;
                wy1[r] = ((unsigned)(iy + 1) <= 190u) ? fy : 0.f;
                ry0[r] = min(max(iy, 0), 190) * RPE_S;
                ry1[r] = min(max(iy + 1, 0), 190) * RPE_S;
            }
#pragma unroll
            for (int it = 0; it < 4; it++) {
                int m = it * 32 + lane;
                int r = it >> 1;
                float gx = 47.5f + (float)(m & 63) * step - kbx;
                float xf = floorf(gx);
                float fx = gx - xf;
                int   xi = (int)xf;
                float w0 = ((unsigned)xi       <= 190u) ? (1.f - fx) : 0.f;
                float w1 = ((unsigned)(xi + 1) <= 190u) ? fx : 0.f;
                int x0 = min(max(xi, 0), 190);
                int x1 = min(max(xi + 1, 0), 190);
                float b0 = rpe[ry0[r] + x0] * w0 + rpe[ry0[r] + x1] * w1;
                float b1 = rpe[ry1[r] + x0] * w0 + rpe[ry1[r] + x1] * w1;
                Ps[m * 66 + n] = wy0[r] * b0 + wy1[r] * b1;
            }
        }
        __syncthreads();

        // load V tile [n][c] (stride 49), tf32 (overlaps with S MMA issue)
        for (int i = tid; i < CC * 64; i += 256) {
            int c = i >> 6, n = i & 63;
            Vs[n * 49 + c] = __uint_as_float(f2tf(g_v[(b * CC + c) * NN + n0 + n]));
        }

        // ---- S = QK^T + bias : init C from bias (float2 reads) ----
        float cS[8][4];
#pragma unroll
        for (int nb = 0; nb < 8; nb++) {
            int col = nb * 8 + 2 * tig;
            float2 bA = *(const float2*)&Ps[qrow * 66 + col];
            float2 bB = *(const float2*)&Ps[(qrow + 8) * 66 + col];
            cS[nb][0] = bA.x; cS[nb][1] = bA.y;
            cS[nb][2] = bB.x; cS[nb][3] = bB.y;
        }
#pragma unroll
        for (int kb = 0; kb < 6; kb++) {
            uint32_t a0 = Qu[qrow * 52 + kb * 8 + tig];
            uint32_t a1 = Qu[(qrow + 8) * 52 + kb * 8 + tig];
            uint32_t a2 = Qu[qrow * 52 + kb * 8 + tig + 4];
            uint32_t a3 = Qu[(qrow + 8) * 52 + kb * 8 + tig + 4];
            const int sw = tig << 3;
#pragma unroll
            for (int nb = 0; nb < 8; nb++) {
                uint32_t b0 = Ku[(kb * 8 + tig) * 64 + ((nb * 8 + gid) ^ sw)];
                uint32_t b1 = Ku[(kb * 8 + tig + 4) * 64 + ((nb * 8 + gid) ^ sw)];
                mma_tf32(cS[nb], a0, a1, a2, a3, b0, b1);
            }
        }

        // ---- online softmax (rows qrow, qrow+8) ----
        float tmax0 = -1e30f, tmax1 = -1e30f;
#pragma unroll
        for (int nb = 0; nb < 8; nb++) {
            tmax0 = fmaxf(tmax0, fmaxf(cS[nb][0], cS[nb][1]));
            tmax1 = fmaxf(tmax1, fmaxf(cS[nb][2], cS[nb][3]));
        }
        tmax0 = fmaxf(tmax0, __shfl_xor_sync(0xffffffffu, tmax0, 1));
        tmax0 = fmaxf(tmax0, __shfl_xor_sync(0xffffffffu, tmax0, 2));
        tmax1 = fmaxf(tmax1, __shfl_xor_sync(0xffffffffu, tmax1, 1));
        tmax1 = fmaxf(tmax1, __shfl_xor_sync(0xffffffffu, tmax1, 2));
        float nmax0 = fmaxf(rmax0, tmax0);
        float nmax1 = fmaxf(rmax1, tmax1);
        float f0 = __expf(rmax0 - nmax0);
        float f1 = __expf(rmax1 - nmax1);
        rmax0 = nmax0; rmax1 = nmax1;

        float psum0 = 0.f, psum1 = 0.f;
#pragma unroll
        for (int nb = 0; nb < 8; nb++) {
            float p0 = __expf(cS[nb][0] - nmax0);
            float p1 = __expf(cS[nb][1] - nmax0);
            float p2 = __expf(cS[nb][2] - nmax1);
            float p3 = __expf(cS[nb][3] - nmax1);
            psum0 += p0 + p1;
            psum1 += p2 + p3;
            int col = nb * 8 + 2 * tig;
            float2 w0 = make_float2(__uint_as_float(f2tf(p0)), __uint_as_float(f2tf(p1)));
            float2 w1 = make_float2(__uint_as_float(f2tf(p2)), __uint_as_float(f2tf(p3)));
            *(float2*)&Ps[qrow * 66 + col]       = w0;
            *(float2*)&Ps[(qrow + 8) * 66 + col] = w1;
        }
        psum0 += __shfl_xor_sync(0xffffffffu, psum0, 1);
        psum0 += __shfl_xor_sync(0xffffffffu, psum0, 2);
        psum1 += __shfl_xor_sync(0xffffffffu, psum1, 1);
        psum1 += __shfl_xor_sync(0xffffffffu, psum1, 2);
        rsum0 = rsum0 * f0 + psum0;
        rsum1 = rsum1 * f1 + psum1;

#pragma unroll
        for (int nb = 0; nb < 6; nb++) {
            o[nb][0] *= f0; o[nb][1] *= f0;
            o[nb][2] *= f1; o[nb][3] *= f1;
        }
        __syncthreads();

        // ---- PV: O += P x V ----
#pragma unroll
        for (int kb = 0; kb < 8; kb++) {
            uint32_t a0 = Pu[qrow * 66 + kb * 8 + tig];
            uint32_t a1 = Pu[(qrow + 8) * 66 + kb * 8 + tig];
            uint32_t a2 = Pu[qrow * 66 + kb * 8 + tig + 4];
            uint32_t a3 = Pu[(qrow + 8) * 66 + kb * 8 + tig + 4];
#pragma unroll
            for (int nb = 0; nb < 6; nb++) {
                uint32_t b0 = Vu[(kb * 8 + tig) * 49 + nb * 8 + gid];
                uint32_t b1 = Vu[(kb * 8 + tig + 4) * 49 + nb * 8 + gid];
                mma_tf32(o[nb], a0, a1, a2, a3, b0, b1);
            }
        }
    }

    // ---- write partial results ----
    const int mA = m0 + qrow;
    const int mB = mA + 8;
    float* op = g_opart + (split * BB + b) * CC * NN;
#pragma unroll
    for (int nb = 0; nb < 6; nb++) {
        int ch = nb * 8 + 2 * tig;
        op[ch * NN + mA]       = o[nb][0];
        op[(ch + 1) * NN + mA] = o[nb][1];
        op[ch * NN + mB]       = o[nb][2];
        op[(ch + 1) * NN + mB] = o[nb][3];
    }
    if (tig == 0) {
        g_mpart[(split * BB + b) * NN + mA] = rmax0;
        g_mpart[(split * BB + b) * NN + mB] = rmax1;
        g_lpart[(split * BB + b) * NN + mA] = rsum0;
        g_lpart[(split * BB + b) * NN + mB] = rsum1;
    }
}

// ---------------- window attention (3 splits x 64 windows x B) ------------------
__global__ void winattn_kernel() {
    int b  = blockIdx.z;
    int sp = blockIdx.y;
    int w  = blockIdx.x;
    int t  = threadIdx.x;

    __shared__ float qsm[64][17];
    __shared__ float vsm[64][17];

    int py, px;
    if (sp == 0)      { int wy = w >> 3, wx = w & 7; py = wy * 8 + (t >> 3); px = wx * 8 + (t & 7); }
    else if (sp == 1) { py = t;  px = w; }
    else              { py = w;  px = t; }
    int pix = py * 64 + px;

    int qbase = (b * 96 + sp * 32) * NN + pix;
#pragma unroll
    for (int c = 0; c < 16; c++) {
        qsm[t][c] = g_x2[qbase + c * NN];
        vsm[t][c] = g_x2[qbase + (16 + c) * NN];
    }
    __syncthreads();

    float qr[16];
#pragma unroll
    for (int c = 0; c < 16; c++) qr[c] = qsm[t][c];

    float lg[64];
    float mx = -1e30f;
    for (int j = 0; j < 64; j++) {
        float d = 0.f;
#pragma unroll
        for (int c = 0; c < 16; c++) d += qr[c] * qsm[j][c];
        lg[j] = d;
        mx = fmaxf(mx, d);
    }
    float s = 0.f;
    for (int j = 0; j < 64; j++) { lg[j] = __expf(lg[j] - mx); s += lg[j]; }
    float inv = 1.f / s;

    float o[16];
#pragma unroll
    for (int c = 0; c < 16; c++) o[c] = 0.f;
    for (int j = 0; j < 64; j++) {
        float p = lg[j] * inv;
#pragma unroll
        for (int c = 0; c < 16; c++) o[c] += p * vsm[j][c];
    }
#pragma unroll
    for (int c = 0; c < 16; c++)
        g_win[(b * CC + sp * 16 + c) * NN + pix] = o[c];
}

// ---------------- final: pout conv (4 outputs) + split merge + average ----------
__global__ void final_kernel(const float* __restrict__ pw, const float* __restrict__ pb,
                             float* __restrict__ out) {
    int idx = blockIdx.x * 256 + threadIdx.x;
    if (idx >= BB * (CC / 4) * (NN / 4)) return;
    int p4 = idx & (NN / 4 - 1);
    int og = (idx >> 10) % (CC / 4);
    int b  = idx / ((CC / 4) * (NN / 4));
    float4 acc[4];
#pragma unroll
    for (int u = 0; u < 4; u++) {
        float bo = pb[og * 4 + u];
        acc[u] = make_float4(bo, bo, bo, bo);
    }
    const float4* wb = (const float4*)(g_win + b * CC * NN) + p4;
#pragma unroll 4
    for (int c = 0; c < CC; c++) {
        float4 wv = wb[c * (NN / 4)];
#pragma unroll
        for (int u = 0; u < 4; u++) {
            float w = pw[(og * 4 + u) * CC + c];
            acc[u].x += w * wv.x; acc[u].y += w * wv.y;
            acc[u].z += w * wv.z; acc[u].w += w * wv.w;
        }
    }

    // split merge weights (shared across the 4 channels)
    float4 mv[NSPLIT], ev[NSPLIT];
    float4 M = make_float4(-1e30f, -1e30f, -1e30f, -1e30f);
#pragma unroll
    for (int s = 0; s < NSPLIT; s++) {
        mv[s] = ((const float4*)(g_mpart + (s * BB + b) * NN))[p4];
        M.x = fmaxf(M.x, mv[s].x); M.y = fmaxf(M.y, mv[s].y);
        M.z = fmaxf(M.z, mv[s].z); M.w = fmaxf(M.w, mv[s].w);
    }
    float4 l = make_float4(0.f, 0.f, 0.f, 0.f);
#pragma unroll
    for (int s = 0; s < NSPLIT; s++) {
        ev[s].x = __expf(mv[s].x - M.x);
        ev[s].y = __expf(mv[s].y - M.y);
        ev[s].z = __expf(mv[s].z - M.z);
        ev[s].w = __expf(mv[s].w - M.w);
        float4 lv = ((const float4*)(g_lpart + (s * BB + b) * NN))[p4];
        l.x += lv.x * ev[s].x; l.y += lv.y * ev[s].y;
        l.z += lv.z * ev[s].z; l.w += lv.w * ev[s].w;
    }
    float4 il = make_float4(0.5f / l.x, 0.5f / l.y, 0.5f / l.z, 0.5f / l.w);

#pragma unroll
    for (int u = 0; u < 4; u++) {
        int o = og * 4 + u;
        float4 ov = make_float4(0.f, 0.f, 0.f, 0.f);
#pragma unroll
        for (int s = 0; s < NSPLIT; s++) {
            float4 opv = ((const float4*)(g_opart + ((s * BB + b) * CC + o) * NN))[p4];
            ov.x += opv.x * ev[s].x; ov.y += opv.y * ev[s].y;
            ov.z += opv.z * ev[s].z; ov.w += opv.w * ev[s].w;
        }
        float4 res;
        res.x = 0.5f * acc[u].x + ov.x * il.x;
        res.y = 0.5f * acc[u].y + ov.y * il.y;
        res.z = 0.5f * acc[u].z + ov.z * il.z;
        res.w = 0.5f * acc[u].w + ov.w * il.w;
        ((float4*)out)[(b * CC + o) * (NN / 4) + p4] = res;
    }
}

// ---------------- launch ---------------------------------------------------------
extern "C" void kernel_launch(void* const* d_in, const int* in_sizes, int n_in,
                              void* d_out, int out_size) {
    const float* x        = (const float*)d_in[0];
    const float* Wq       = (const float*)d_in[1];
    const float* bq       = (const float*)d_in[2];
    const float* off_dw_w = (const float*)d_in[3];
    const float* off_dw_b = (const float*)d_in[4];
    const float* off_ln_g = (const float*)d_in[5];
    const float* off_ln_b = (const float*)d_in[6];
    const float* off_pw_w = (const float*)d_in[7];
    const float* Wk       = (const float*)d_in[8];
    const float* bk       = (const float*)d_in[9];
    const float* Wv       = (const float*)d_in[10];
    const float* bv       = (const float*)d_in[11];
    const float* inp_w    = (const float*)d_in[12];
    const float* inp_b    = (const float*)d_in[13];
    const float* bn_g     = (const float*)d_in[14];
    const float* bn_b     = (const float*)d_in[15];
    const float* bn_mean  = (const float*)d_in[16];
    const float* bn_var   = (const float*)d_in[17];
    const float* pout_w   = (const float*)d_in[18];
    const float* pout_b   = (const float*)d_in[19];
    const float* rpe      = (const float*)d_in[20];
    float* out = (float*)d_out;

    cudaFuncSetAttribute(attn_kernel, cudaFuncAttributeMaxDynamicSharedMemorySize,
                         ATTN_SMEM_BYTES);

    conv_q_kernel<<<(BB * (CC/4) * (NN/4) + 255) / 256, 256>>>(x, Wq, bq);
    conv_x2_kernel<<<(BB * 24 * (NN/4) + 255) / 256, 256>>>(x, inp_w, inp_b,
                                                            bn_g, bn_b, bn_mean, bn_var);
    deform_kernel<<<dim3(HH, BB), 256>>>(x, off_dw_w, off_dw_b,
                                         off_ln_g, off_ln_b, off_pw_w);
    conv_kv_kernel<<<(BB * 24 * (NN/4) + 255) / 256, 256>>>(Wk, bk, Wv, bv);
    attn_kernel<<<dim3(NN / 128, NSPLIT, BB), 256, ATTN_SMEM_BYTES>>>(rpe);
    winattn_kernel<<<dim3(64, 3, BB), 64>>>();
    final_kernel<<<(BB * (CC/4) * (NN/4) + 255) / 256, 256>>>(pout_w, pout_b, out);
}

// round 8
// speedup vs baseline: 2.4647x; 1.0881x over previous
#include <cuda_runtime.h>
#include <math.h>
#include <stdint.h>

// Problem constants
#define BB 2
#define CC 48
#define HH 64
#define WW 64
#define NN 4096
#define RPE_S 191
#define NSPLIT 4
#define KEYS_PER_SPLIT (NN / NSPLIT)

// padded rpe: row r = logical y = r-2 (r in [0,194)), col xc = logical x = xc-2
// element = (rpe_z[y][x], rpe_z[y+1][x]);  stride 196 float2
#define RP_ROWS 194
#define RP_STRIDE 196

// ---------------- scratch (device globals; no allocation allowed) -------------
__device__ float  g_q  [BB*CC*NN];
__device__ float  g_x2 [BB*96*NN];
__device__ float  g_pos[BB*NN*2];
__device__ float  g_xs [BB*CC*NN];
__device__ float  g_k  [BB*CC*NN];
__device__ float  g_v  [BB*CC*NN];
__device__ float  g_win[BB*CC*NN];
__device__ float  g_opart[NSPLIT*BB*CC*NN];
__device__ float  g_mpart[NSPLIT*BB*NN];
__device__ float  g_lpart[NSPLIT*BB*NN];
__device__ float2 g_rpe2[RP_ROWS*RP_STRIDE];

// ---------------- tf32 MMA helpers ----------------------------------------------
__device__ __forceinline__ uint32_t f2tf(float f) {
    uint32_t r; asm("cvt.rna.tf32.f32 %0, %1;" : "=r"(r) : "f"(f)); return r;
}
__device__ __forceinline__ void mma_tf32(float* c,
                                         uint32_t a0, uint32_t a1, uint32_t a2, uint32_t a3,
                                         uint32_t b0, uint32_t b1) {
    asm("mma.sync.aligned.m16n8k8.row.col.f32.tf32.tf32.f32 "
        "{%0,%1,%2,%3}, {%4,%5,%6,%7}, {%8,%9}, {%0,%1,%2,%3};"
        : "+f"(c[0]), "+f"(c[1]), "+f"(c[2]), "+f"(c[3])
        : "r"(a0), "r"(a1), "r"(a2), "r"(a3), "r"(b0), "r"(b1));
}

// ---------------- rpe padding prep ------------------------------------------------
__global__ void rpe_pad_kernel(const float* __restrict__ rpe) {
    int idx = blockIdx.x * 256 + threadIdx.x;
    if (idx >= RP_ROWS * RP_STRIDE) return;
    int r  = idx / RP_STRIDE;
    int xc = idx - r * RP_STRIDE;
    int y = r - 2, x = xc - 2;
    float a = 0.f, b = 0.f;
    if (x >= 0 && x <= 190) {
        if (y     >= 0 && y     <= 190) a = rpe[y * RPE_S + x];
        if (y + 1 >= 0 && y + 1 <= 190) b = rpe[(y + 1) * RPE_S + x];
    }
    g_rpe2[idx] = make_float2(a, b);
}

// ---------------- generic helpers ----------------------------------------------
__device__ __forceinline__ float bilin(const float* __restrict__ img, int H, int W,
                                       float gx, float gy) {
    float x0f = floorf(gx), y0f = floorf(gy);
    int   x0  = (int)x0f,   y0  = (int)y0f;
    float wx  = gx - x0f,   wy  = gy - y0f;
    float acc = 0.f;
#pragma unroll
    for (int dy = 0; dy < 2; dy++) {
        int yc = y0 + dy;
        if (yc < 0 || yc >= H) continue;
        float wyv = dy ? wy : (1.f - wy);
#pragma unroll
        for (int dx = 0; dx < 2; dx++) {
            int xc = x0 + dx;
            if (xc < 0 || xc >= W) continue;
            float wxv = dx ? wx : (1.f - wx);
            acc += img[yc * W + xc] * (wyv * wxv);
        }
    }
    return acc;
}

// ---------------- fused q + x2 projections (4 outs x 2 px / thread) -------------
// groups: og in [0,36): og<12 -> q channels og*4.., else x2 channels (og-12)*4..
__global__ void proj_kernel(const float* __restrict__ x,
                            const float* __restrict__ Wq, const float* __restrict__ bq,
                            const float* __restrict__ Wx, const float* __restrict__ bx,
                            const float* __restrict__ bng, const float* __restrict__ bnb,
                            const float* __restrict__ bnm, const float* __restrict__ bnv) {
    int idx = blockIdx.x * 256 + threadIdx.x;
    if (idx >= BB * 36 * (NN / 2)) return;
    int p2 = idx & (NN / 2 - 1);
    int og = (idx >> 11) % 36;
    int b  = idx / (36 * (NN / 2));
    const bool isq = og < 12;
    const int  o0  = (isq ? og : og - 12) * 4;
    const float* W  = isq ? Wq : Wx;
    const float* bi = isq ? bq : bx;

    float2 acc[4];
#pragma unroll
    for (int u = 0; u < 4; u++) {
        float bo = bi[o0 + u];
        acc[u] = make_float2(bo, bo);
    }
    const float2* xb = (const float2*)(x + b * CC * NN) + p2;
#pragma unroll 4
    for (int c = 0; c < CC; c++) {
        float2 xv = xb[c * (NN / 2)];
#pragma unroll
        for (int u = 0; u < 4; u++) {
            float w = W[(o0 + u) * CC + c];
            acc[u].x += w * xv.x; acc[u].y += w * xv.y;
        }
    }
    if (isq) {
#pragma unroll
        for (int u = 0; u < 4; u++)
            ((float2*)g_q)[(b * CC + o0 + u) * (NN / 2) + p2] = acc[u];
    } else {
#pragma unroll
        for (int u = 0; u < 4; u++) {
            int o = o0 + u;
            float sc = rsqrtf(bnv[o] + 1e-5f) * bng[o];
            float sh = bnb[o] - bnm[o] * sc;
            acc[u].x = acc[u].x * sc + sh; acc[u].y = acc[u].y * sc + sh;
            ((float2*)g_x2)[(b * 96 + o) * (NN / 2) + p2] = acc[u];
        }
    }
}

// ---------------- offset head + position + grid-sample x (512 thr) --------------
__global__ void deform_kernel(const float* __restrict__ x,
                              const float* __restrict__ dww, const float* __restrict__ dwb,
                              const float* __restrict__ lng, const float* __restrict__ lnb,
                              const float* __restrict__ pww) {
    int b = blockIdx.y;
    int y = blockIdx.x;
    int tid = threadIdx.x;
    __shared__ float ts[CC * WW];
    __shared__ float posr[WW * 2];
    __shared__ float redA[8][WW];
    __shared__ float redB[8][WW];

    for (int i = tid; i < CC * WW; i += 512) {
        int c = i >> 6, px = i & 63;
        float acc = dwb[c];
        const float* qc = g_q + (b * CC + c) * NN;
        const float* wc = dww + c * 9;
#pragma unroll
        for (int ky = 0; ky < 3; ky++) {
            int yy = y + ky - 1;
            if (yy < 0 || yy > 63) continue;
#pragma unroll
            for (int kx = 0; kx < 3; kx++) {
                int xx = px + kx - 1;
                if (xx < 0 || xx > 63) continue;
                acc += qc[(yy << 6) + xx] * wc[ky * 3 + kx];
            }
        }
        ts[c * 64 + px] = acc;
    }
    __syncthreads();

    const int sub = tid >> 6;     // 0..7 -> channels sub*6..sub*6+5
    const int px  = tid & 63;
    {
        float s = 0.f;
#pragma unroll
        for (int j = 0; j < 6; j++) s += ts[(sub * 6 + j) * 64 + px];
        redA[sub][px] = s;
    }
    __syncthreads();
    float mu = 0.f;
#pragma unroll
    for (int u = 0; u < 8; u++) mu += redA[u][px];
    mu *= (1.f / 48.f);
    {
        float v2 = 0.f;
#pragma unroll
        for (int j = 0; j < 6; j++) {
            float d = ts[(sub * 6 + j) * 64 + px] - mu;
            v2 += d * d;
        }
        redB[sub][px] = v2;
    }
    __syncthreads();
    float var = 0.f;
#pragma unroll
    for (int u = 0; u < 8; u++) var += redB[u][px];
    float rs = rsqrtf(var * (1.f / 48.f) + 1e-5f);
    {
        float a0 = 0.f, a1 = 0.f;
#pragma unroll
        for (int j = 0; j < 6; j++) {
            int c = sub * 6 + j;
            float v = (ts[c * 64 + px] - mu) * rs * lng[c] + lnb[c];
            v = 0.5f * v * (1.f + erff(v * 0.7071067811865475f));
            a0 += pww[c] * v;
            a1 += pww[CC + c] * v;
        }
        redA[sub][px] = a0;
        redB[sub][px] = a1;
    }
    __syncthreads();
    if (tid < WW) {
        float a0 = 0.f, a1 = 0.f;
#pragma unroll
        for (int u = 0; u < 8; u++) { a0 += redA[u][px]; a1 += redB[u][px]; }
        float py  = tanhf(a0) * (2.f / 63.f) + ((0.5f + (float)y ) * (2.f / 63.f) - 1.f);
        float pxx = tanhf(a1) * (2.f / 63.f) + ((0.5f + (float)px) * (2.f / 63.f) - 1.f);
        posr[px * 2 + 0] = py;
        posr[px * 2 + 1] = pxx;
        int n = (y << 6) + px;
        g_pos[(b * NN + n) * 2 + 0] = py;
        g_pos[(b * NN + n) * 2 + 1] = pxx;
    }
    __syncthreads();

    for (int i = tid; i < CC * WW; i += 512) {
        int c = i >> 6, p = i & 63;
        float py  = posr[p * 2 + 0];
        float pxx = posr[p * 2 + 1];
        float gx = (pxx + 1.f) * 0.5f * 63.f;
        float gy = (py  + 1.f) * 0.5f * 63.f;
        const float* img = x + (b * CC + c) * NN;
        g_xs[(b * CC + c) * NN + (y << 6) + p] = bilin(img, HH, WW, gx, gy);
    }
}

// ---------------- k,v projections (4k+4v outs x 2 px / thread) -------------------
__global__ void conv_kv_kernel(const float* __restrict__ Wk, const float* __restrict__ bk,
                               const float* __restrict__ Wv, const float* __restrict__ bv) {
    int idx = blockIdx.x * 256 + threadIdx.x;
    if (idx >= BB * 12 * (NN / 2)) return;
    int p2 = idx & (NN / 2 - 1);
    int og = (idx >> 11) % 12;
    int b  = idx / (12 * (NN / 2));
    float2 ak[4], av[4];
#pragma unroll
    for (int u = 0; u < 4; u++) {
        float bko = bk[og * 4 + u], bvo = bv[og * 4 + u];
        ak[u] = make_float2(bko, bko);
        av[u] = make_float2(bvo, bvo);
    }
    const float2* xb = (const float2*)(g_xs + b * CC * NN) + p2;
#pragma unroll 4
    for (int c = 0; c < CC; c++) {
        float2 xv = xb[c * (NN / 2)];
#pragma unroll
        for (int u = 0; u < 4; u++) {
            float wk = Wk[(og * 4 + u) * CC + c];
            float wv = Wv[(og * 4 + u) * CC + c];
            ak[u].x += wk * xv.x; ak[u].y += wk * xv.y;
            av[u].x += wv * xv.x; av[u].y += wv * xv.y;
        }
    }
#pragma unroll
    for (int u = 0; u < 4; u++) {
        ((float2*)g_k)[(b * CC + og * 4 + u) * (NN / 2) + p2] = ak[u];
        ((float2*)g_v)[(b * CC + og * 4 + u) * (NN / 2) + p2] = av[u];
    }
}

// ---------------- fused flash attention: tf32 MMA, padded rpe --------------------
#define AOF_QS 0                        // 128 x 52
#define AOF_KS (AOF_QS + 128*52)        // 48 x 64 swizzled
#define AOF_VS (AOF_KS + 48*64)         // 64 x 49
#define AOF_PS (AOF_VS + 64*49)         // 128 x 66
#define ATTN_SMEM_FLOATS (AOF_PS + 128*66)
#define ATTN_SMEM_BYTES (ATTN_SMEM_FLOATS * 4)

__global__ void __launch_bounds__(256, 2) attn_kernel() {
    extern __shared__ float sm[];
    float* Qs = sm + AOF_QS;
    float* Ks = sm + AOF_KS;
    float* Vs = sm + AOF_VS;
    float* Ps = sm + AOF_PS;
    const uint32_t* Qu = (const uint32_t*)Qs;
    const uint32_t* Ku = (const uint32_t*)Ks;
    const uint32_t* Vu = (const uint32_t*)Vs;
    const uint32_t* Pu = (const uint32_t*)Ps;

    const int yb    = blockIdx.x;
    const int split = blockIdx.y;
    const int b     = blockIdx.z;
    const int tid   = threadIdx.x;
    const int warp  = tid >> 5;
    const int lane  = tid & 31;
    const int gid   = lane >> 2;
    const int tig   = lane & 3;
    const int m0    = yb * 128;
    const int qrow  = warp * 16 + gid;

    const float scale = 0.14433756729740643f;
    const float step  = 95.0f / 63.0f;

    // load Q tile [m][c] (stride 52), scaled, tf32
    for (int i = tid; i < CC * 128; i += 256) {
        int c = i >> 7, m = i & 127;
        Qs[m * 52 + c] = __uint_as_float(f2tf(g_q[(b * CC + c) * NN + m0 + m] * scale));
    }

    float rmax0 = -1e30f, rmax1 = -1e30f, rsum0 = 0.f, rsum1 = 0.f;
    float o[6][4];
#pragma unroll
    for (int nb = 0; nb < 6; nb++)
#pragma unroll
        for (int j = 0; j < 4; j++) o[nb][j] = 0.f;

    const int nbase = split * KEYS_PER_SPLIT;
    for (int t = 0; t < KEYS_PER_SPLIT / 64; t++) {
        const int n0 = nbase + t * 64;
        __syncthreads();

        // load K tile swizzled: Ks[c*64 + (n ^ ((c&3)<<3))], tf32
        for (int i = tid; i < CC * 64; i += 256) {
            int c = i >> 6, n = i & 63;
            Ks[c * 64 + (n ^ ((c & 3) << 3))] =
                __uint_as_float(f2tf(g_k[(b * CC + c) * NN + n0 + n]));
        }

        // bias -> Ps[m][n] (stride 66): padded interleaved rpe, zero clamp logic
#pragma unroll
        for (int kk = 0; kk < 8; kk++) {
            int n = warp * 8 + kk;
            float py = g_pos[(b * NN + n0 + n) * 2 + 0];
            float px = g_pos[(b * NN + n0 + n) * 2 + 1];
            float kbx = 47.5f * px;
            float fy[2];
            const float2* row[2];
#pragma unroll
            for (int r = 0; r < 2; r++) {
                float gy = 47.5f + (float)(yb * 2 + r) * step - 47.5f * py;
                float yf = floorf(gy);
                int   iy = (int)yf;
                fy[r] = gy - yf;
                iy = min(max(iy, -2), 191);
                row[r] = g_rpe2 + (iy + 2) * RP_STRIDE;
            }
#pragma unroll
            for (int it = 0; it < 4; it++) {
                int m = it * 32 + lane;
                int r = it >> 1;
                float gx = 47.5f + (float)(m & 63) * step - kbx;
                float xf = floorf(gx);
                float fx = gx - xf;
                int   xi = (int)xf;
                xi = min(max(xi, -2), 192);
                float2 v0 = row[r][xi + 2];
                float2 v1 = row[r][xi + 3];
                float b0 = fmaf(fx, v1.x - v0.x, v0.x);
                float b1 = fmaf(fx, v1.y - v0.y, v0.y);
                Ps[m * 66 + n] = fmaf(fy[r], b1 - b0, b0);
            }
        }
        __syncthreads();

        // load V tile [n][c] (stride 49), tf32
        for (int i = tid; i < CC * 64; i += 256) {
            int c = i >> 6, n = i & 63;
            Vs[n * 49 + c] = __uint_as_float(f2tf(g_v[(b * CC + c) * NN + n0 + n]));
        }

        // ---- S = QK^T + bias : init C from bias ----
        float cS[8][4];
#pragma unroll
        for (int nb = 0; nb < 8; nb++) {
            int col = nb * 8 + 2 * tig;
            float2 bA = *(const float2*)&Ps[qrow * 66 + col];
            float2 bB = *(const float2*)&Ps[(qrow + 8) * 66 + col];
            cS[nb][0] = bA.x; cS[nb][1] = bA.y;
            cS[nb][2] = bB.x; cS[nb][3] = bB.y;
        }
#pragma unroll
        for (int kb = 0; kb < 6; kb++) {
            uint32_t a0 = Qu[qrow * 52 + kb * 8 + tig];
            uint32_t a1 = Qu[(qrow + 8) * 52 + kb * 8 + tig];
            uint32_t a2 = Qu[qrow * 52 + kb * 8 + tig + 4];
            uint32_t a3 = Qu[(qrow + 8) * 52 + kb * 8 + tig + 4];
            const int sw = tig << 3;
#pragma unroll
            for (int nb = 0; nb < 8; nb++) {
                uint32_t b0 = Ku[(kb * 8 + tig) * 64 + ((nb * 8 + gid) ^ sw)];
                uint32_t b1 = Ku[(kb * 8 + tig + 4) * 64 + ((nb * 8 + gid) ^ sw)];
                mma_tf32(cS[nb], a0, a1, a2, a3, b0, b1);
            }
        }

        // ---- online softmax ----
        float tmax0 = -1e30f, tmax1 = -1e30f;
#pragma unroll
        for (int nb = 0; nb < 8; nb++) {
            tmax0 = fmaxf(tmax0, fmaxf(cS[nb][0], cS[nb][1]));
            tmax1 = fmaxf(tmax1, fmaxf(cS[nb][2], cS[nb][3]));
        }
        tmax0 = fmaxf(tmax0, __shfl_xor_sync(0xffffffffu, tmax0, 1));
        tmax0 = fmaxf(tmax0, __shfl_xor_sync(0xffffffffu, tmax0, 2));
        tmax1 = fmaxf(tmax1, __shfl_xor_sync(0xffffffffu, tmax1, 1));
        tmax1 = fmaxf(tmax1, __shfl_xor_sync(0xffffffffu, tmax1, 2));
        float nmax0 = fmaxf(rmax0, tmax0);
        float nmax1 = fmaxf(rmax1, tmax1);
        float f0 = __expf(rmax0 - nmax0);
        float f1 = __expf(rmax1 - nmax1);
        rmax0 = nmax0; rmax1 = nmax1;

        float psum0 = 0.f, psum1 = 0.f;
#pragma unroll
        for (int nb = 0; nb < 8; nb++) {
            float p0 = __expf(cS[nb][0] - nmax0);
            float p1 = __expf(cS[nb][1] - nmax0);
            float p2 = __expf(cS[nb][2] - nmax1);
            float p3 = __expf(cS[nb][3] - nmax1);
            psum0 += p0 + p1;
            psum1 += p2 + p3;
            int col = nb * 8 + 2 * tig;
            float2 w0 = make_float2(__uint_as_float(f2tf(p0)), __uint_as_float(f2tf(p1)));
            float2 w1 = make_float2(__uint_as_float(f2tf(p2)), __uint_as_float(f2tf(p3)));
            *(float2*)&Ps[qrow * 66 + col]       = w0;
            *(float2*)&Ps[(qrow + 8) * 66 + col] = w1;
        }
        psum0 += __shfl_xor_sync(0xffffffffu, psum0, 1);
        psum0 += __shfl_xor_sync(0xffffffffu, psum0, 2);
        psum1 += __shfl_xor_sync(0xffffffffu, psum1, 1);
        psum1 += __shfl_xor_sync(0xffffffffu, psum1, 2);
        rsum0 = rsum0 * f0 + psum0;
        rsum1 = rsum1 * f1 + psum1;

#pragma unroll
        for (int nb = 0; nb < 6; nb++) {
            o[nb][0] *= f0; o[nb][1] *= f0;
            o[nb][2] *= f1; o[nb][3] *= f1;
        }
        __syncthreads();

        // ---- PV: O += P x V ----
#pragma unroll
        for (int kb = 0; kb < 8; kb++) {
            uint32_t a0 = Pu[qrow * 66 + kb * 8 + tig];
            uint32_t a1 = Pu[(qrow + 8) * 66 + kb * 8 + tig];
            uint32_t a2 = Pu[qrow * 66 + kb * 8 + tig + 4];
            uint32_t a3 = Pu[(qrow + 8) * 66 + kb * 8 + tig + 4];
#pragma unroll
            for (int nb = 0; nb < 6; nb++) {
                uint32_t b0 = Vu[(kb * 8 + tig) * 49 + nb * 8 + gid];
                uint32_t b1 = Vu[(kb * 8 + tig + 4) * 49 + nb * 8 + gid];
                mma_tf32(o[nb], a0, a1, a2, a3, b0, b1);
            }
        }
    }

    // ---- write partial results ----
    const int mA = m0 + qrow;
    const int mB = mA + 8;
    float* op = g_opart + (split * BB + b) * CC * NN;
#pragma unroll
    for (int nb = 0; nb < 6; nb++) {
        int ch = nb * 8 + 2 * tig;
        op[ch * NN + mA]       = o[nb][0];
        op[(ch + 1) * NN + mA] = o[nb][1];
        op[ch * NN + mB]       = o[nb][2];
        op[(ch + 1) * NN + mB] = o[nb][3];
    }
    if (tig == 0) {
        g_mpart[(split * BB + b) * NN + mA] = rmax0;
        g_mpart[(split * BB + b) * NN + mB] = rmax1;
        g_lpart[(split * BB + b) * NN + mA] = rsum0;
        g_lpart[(split * BB + b) * NN + mB] = rsum1;
    }
}

// ---------------- window attention (3 splits x 64 windows x B) ------------------
__global__ void winattn_kernel() {
    int b  = blockIdx.z;
    int sp = blockIdx.y;
    int w  = blockIdx.x;
    int t  = threadIdx.x;

    __shared__ float qsm[64][17];
    __shared__ float vsm[64][17];

    int py, px;
    if (sp == 0)      { int wy = w >> 3, wx = w & 7; py = wy * 8 + (t >> 3); px = wx * 8 + (t & 7); }
    else if (sp == 1) { py = t;  px = w; }
    else              { py = w;  px = t; }
    int pix = py * 64 + px;

    int qbase = (b * 96 + sp * 32) * NN + pix;
#pragma unroll
    for (int c = 0; c < 16; c++) {
        qsm[t][c] = g_x2[qbase + c * NN];
        vsm[t][c] = g_x2[qbase + (16 + c) * NN];
    }
    __syncthreads();

    float qr[16];
#pragma unroll
    for (int c = 0; c < 16; c++) qr[c] = qsm[t][c];

    float lg[64];
    float mx = -1e30f;
    for (int j = 0; j < 64; j++) {
        float d = 0.f;
#pragma unroll
        for (int c = 0; c < 16; c++) d += qr[c] * qsm[j][c];
        lg[j] = d;
        mx = fmaxf(mx, d);
    }
    float s = 0.f;
    for (int j = 0; j < 64; j++) { lg[j] = __expf(lg[j] - mx); s += lg[j]; }
    float inv = 1.f / s;

    float o[16];
#pragma unroll
    for (int c = 0; c < 16; c++) o[c] = 0.f;
    for (int j = 0; j < 64; j++) {
        float p = lg[j] * inv;
#pragma unroll
        for (int c = 0; c < 16; c++) o[c] += p * vsm[j][c];
    }
#pragma unroll
    for (int c = 0; c < 16; c++)
        g_win[(b * CC + sp * 16 + c) * NN + pix] = o[c];
}

// ---------------- final: pout conv (4 outputs) + split merge + average ----------
__global__ void final_kernel(const float* __restrict__ pw, const float* __restrict__ pb,
                             float* __restrict__ out) {
    int idx = blockIdx.x * 256 + threadIdx.x;
    if (idx >= BB * (CC / 4) * (NN / 4)) return;
    int p4 = idx & (NN / 4 - 1);
    int og = (idx >> 10) % (CC / 4);
    int b  = idx / ((CC / 4) * (NN / 4));
    float4 acc[4];
#pragma unroll
    for (int u = 0; u < 4; u++) {
        float bo = pb[og * 4 + u];
        acc[u] = make_float4(bo, bo, bo, bo);
    }
    const float4* wb = (const float4*)(g_win + b * CC * NN) + p4;
#pragma unroll 4
    for (int c = 0; c < CC; c++) {
        float4 wv = wb[c * (NN / 4)];
#pragma unroll
        for (int u = 0; u < 4; u++) {
            float w = pw[(og * 4 + u) * CC + c];
            acc[u].x += w * wv.x; acc[u].y += w * wv.y;
            acc[u].z += w * wv.z; acc[u].w += w * wv.w;
        }
    }

    float4 mv[NSPLIT], ev[NSPLIT];
    float4 M = make_float4(-1e30f, -1e30f, -1e30f, -1e30f);
#pragma unroll
    for (int s = 0; s < NSPLIT; s++) {
        mv[s] = ((const float4*)(g_mpart + (s * BB + b) * NN))[p4];
        M.x = fmaxf(M.x, mv[s].x); M.y = fmaxf(M.y, mv[s].y);
        M.z = fmaxf(M.z, mv[s].z); M.w = fmaxf(M.w, mv[s].w);
    }
    float4 l = make_float4(0.f, 0.f, 0.f, 0.f);
#pragma unroll
    for (int s = 0; s < NSPLIT; s++) {
        ev[s].x = __expf(mv[s].x - M.x);
        ev[s].y = __expf(mv[s].y - M.y);
        ev[s].z = __expf(mv[s].z - M.z);
        ev[s].w = __expf(mv[s].w - M.w);
        float4 lv = ((const float4*)(g_lpart + (s * BB + b) * NN))[p4];
        l.x += lv.x * ev[s].x; l.y += lv.y * ev[s].y;
        l.z += lv.z * ev[s].z; l.w += lv.w * ev[s].w;
    }
    float4 il = make_float4(0.5f / l.x, 0.5f / l.y, 0.5f / l.z, 0.5f / l.w);

#pragma unroll
    for (int u = 0; u < 4; u++) {
        int o = og * 4 + u;
        float4 ov = make_float4(0.f, 0.f, 0.f, 0.f);
#pragma unroll
        for (int s = 0; s < NSPLIT; s++) {
            float4 opv = ((const float4*)(g_opart + ((s * BB + b) * CC + o) * NN))[p4];
            ov.x += opv.x * ev[s].x; ov.y += opv.y * ev[s].y;
            ov.z += opv.z * ev[s].z; ov.w += opv.w * ev[s].w;
        }
        float4 res;
        res.x = 0.5f * acc[u].x + ov.x * il.x;
        res.y = 0.5f * acc[u].y + ov.y * il.y;
        res.z = 0.5f * acc[u].z + ov.z * il.z;
        res.w = 0.5f * acc[u].w + ov.w * il.w;
        ((float4*)out)[(b * CC + o) * (NN / 4) + p4] = res;
    }
}

// ---------------- launch ---------------------------------------------------------
extern "C" void kernel_launch(void* const* d_in, const int* in_sizes, int n_in,
                              void* d_out, int out_size) {
    const float* x        = (const float*)d_in[0];
    const float* Wq       = (const float*)d_in[1];
    const float* bq       = (const float*)d_in[2];
    const float* off_dw_w = (const float*)d_in[3];
    const float* off_dw_b = (const float*)d_in[4];
    const float* off_ln_g = (const float*)d_in[5];
    const float* off_ln_b = (const float*)d_in[6];
    const float* off_pw_w = (const float*)d_in[7];
    const float* Wk       = (const float*)d_in[8];
    const float* bk       = (const float*)d_in[9];
    const float* Wv       = (const float*)d_in[10];
    const float* bv       = (const float*)d_in[11];
    const float* inp_w    = (const float*)d_in[12];
    const float* inp_b    = (const float*)d_in[13];
    const float* bn_g     = (const float*)d_in[14];
    const float* bn_b     = (const float*)d_in[15];
    const float* bn_mean  = (const float*)d_in[16];
    const float* bn_var   = (const float*)d_in[17];
    const float* pout_w   = (const float*)d_in[18];
    const float* pout_b   = (const float*)d_in[19];
    const float* rpe      = (const float*)d_in[20];
    float* out = (float*)d_out;

    cudaFuncSetAttribute(attn_kernel, cudaFuncAttributeMaxDynamicSharedMemorySize,
                         ATTN_SMEM_BYTES);

    rpe_pad_kernel<<<(RP_ROWS * RP_STRIDE + 255) / 256, 256>>>(rpe);
    proj_kernel<<<(BB * 36 * (NN / 2) + 255) / 256, 256>>>(x, Wq, bq, inp_w, inp_b,
                                                           bn_g, bn_b, bn_mean, bn_var);
    deform_kernel<<<dim3(HH, BB), 512>>>(x, off_dw_w, off_dw_b,
                                         off_ln_g, off_ln_b, off_pw_w);
    conv_kv_kernel<<<(BB * 12 * (NN / 2) + 255) / 256, 256>>>(Wk, bk, Wv, bv);
    attn_kernel<<<dim3(NN / 128, NSPLIT, BB), 256, ATTN_SMEM_BYTES>>>();
    winattn_kernel<<<dim3(64, 3, BB), 64>>>();
    final_kernel<<<(BB * (CC / 4) * (NN / 4) + 255) / 256, 256>>>(pout_w, pout_b, out);
}

// round 9
// speedup vs baseline: 2.5955x; 1.0531x over previous
#include <cuda_runtime.h>
#include <math.h>
#include <stdint.h>

// Problem constants
#define BB 2
#define CC 48
#define HH 64
#define WW 64
#define NN 4096
#define RPE_S 191
#define NSPLIT 4
#define KEYS_PER_SPLIT (NN / NSPLIT)

#define RP_ROWS 194
#define RP_STRIDE 196

// ---------------- scratch (device globals; no allocation allowed) -------------
__device__ float  g_q  [BB*CC*NN];
__device__ float  g_x2 [BB*96*NN];
__device__ float  g_pos[BB*NN*2];
__device__ float  g_xs [BB*CC*NN];
__device__ float  g_k  [BB*CC*NN];
__device__ float  g_v  [BB*CC*NN];
__device__ float  g_win[BB*CC*NN];
__device__ float  g_opart[NSPLIT*BB*CC*NN];
__device__ float  g_mpart[NSPLIT*BB*NN];
__device__ float  g_lpart[NSPLIT*BB*NN];
__device__ float2 g_rpe2[RP_ROWS*RP_STRIDE];

// ---------------- tf32 MMA helpers ----------------------------------------------
__device__ __forceinline__ uint32_t f2tf(float f) {
    uint32_t r; asm("cvt.rna.tf32.f32 %0, %1;" : "=r"(r) : "f"(f)); return r;
}
__device__ __forceinline__ void mma_tf32(float* c,
                                         uint32_t a0, uint32_t a1, uint32_t a2, uint32_t a3,
                                         uint32_t b0, uint32_t b1) {
    asm("mma.sync.aligned.m16n8k8.row.col.f32.tf32.tf32.f32 "
        "{%0,%1,%2,%3}, {%4,%5,%6,%7}, {%8,%9}, {%0,%1,%2,%3};"
        : "+f"(c[0]), "+f"(c[1]), "+f"(c[2]), "+f"(c[3])
        : "r"(a0), "r"(a1), "r"(a2), "r"(a3), "r"(b0), "r"(b1));
}

// ---------------- shared 48x48 GEMM tile (128 pixels per block) -------------------
// Xs: [128][52] tf32 (pixel-major A operand).  Ws: [48][64] swizzled tf32 B operand
// Ws[c*64 + (o ^ ((c&3)<<3))] = W[o][c] * sc[o].   bias_s[48] = folded bias.
struct ConvSmem {
    float Xs[128 * 52];
    float Ws[48 * 64];
    float bias_s[48];
    float sc_s[48];
};

__device__ __forceinline__ void conv_fill(ConvSmem& S, const float* __restrict__ srcb,
                                          int m0, const float* __restrict__ W, int tid) {
    for (int i = tid; i < CC * 128; i += 256) {
        int c = i >> 7, m = i & 127;
        S.Xs[m * 52 + c] = __uint_as_float(f2tf(srcb[c * NN + m0 + m]));
    }
    for (int i = tid; i < 48 * 64; i += 256) {
        int c = i >> 6, o = i & 63;
        float v = (o < 48) ? W[o * CC + c] * S.sc_s[o] : 0.f;
        S.Ws[c * 64 + (o ^ ((c & 3) << 3))] = __uint_as_float(f2tf(v));
    }
}

// compute 48-out GEMM for this warp; cS[6][4] initialized from bias
__device__ __forceinline__ void conv_mma(const ConvSmem& S, float cS[6][4],
                                         int qrow, int tig, int gid) {
    const uint32_t* Xu = (const uint32_t*)S.Xs;
    const uint32_t* Wu = (const uint32_t*)S.Ws;
#pragma unroll
    for (int nb = 0; nb < 6; nb++) {
        int col = nb * 8 + 2 * tig;
        cS[nb][0] = cS[nb][2] = S.bias_s[col];
        cS[nb][1] = cS[nb][3] = S.bias_s[col + 1];
    }
    const int sw = tig << 3;
#pragma unroll
    for (int kb = 0; kb < 6; kb++) {
        uint32_t a0 = Xu[qrow * 52 + kb * 8 + tig];
        uint32_t a1 = Xu[(qrow + 8) * 52 + kb * 8 + tig];
        uint32_t a2 = Xu[qrow * 52 + kb * 8 + tig + 4];
        uint32_t a3 = Xu[(qrow + 8) * 52 + kb * 8 + tig + 4];
#pragma unroll
        for (int nb = 0; nb < 6; nb++) {
            uint32_t b0 = Wu[(kb * 8 + tig) * 64 + ((nb * 8 + gid) ^ sw)];
            uint32_t b1 = Wu[(kb * 8 + tig + 4) * 64 + ((nb * 8 + gid) ^ sw)];
            mma_tf32(cS[nb], a0, a1, a2, a3, b0, b1);
        }
    }
}

// ---------------- stage1: q + x2(BN) projections + rpe pad ------------------------
// grid (32, 7): y<6 -> job=y>>1 (0:q 1:x2lo 2:x2hi), b=y&1;  y==6 -> rpe pad
__global__ void __launch_bounds__(256, 2) stage1_kernel(
    const float* __restrict__ x,
    const float* __restrict__ Wq, const float* __restrict__ bq,
    const float* __restrict__ inp_w, const float* __restrict__ inp_b,
    const float* __restrict__ bng, const float* __restrict__ bnb,
    const float* __restrict__ bnm, const float* __restrict__ bnv,
    const float* __restrict__ rpe) {
    const int tid = threadIdx.x;
    if (blockIdx.y == 6) {
        for (int idx = blockIdx.x * 256 + tid; idx < RP_ROWS * RP_STRIDE; idx += 32 * 256) {
            int r  = idx / RP_STRIDE;
            int xc = idx - r * RP_STRIDE;
            int yy = r - 2, xx = xc - 2;
            float a = 0.f, bb = 0.f;
            if (xx >= 0 && xx <= 190) {
                if (yy     >= 0 && yy     <= 190) a  = rpe[yy * RPE_S + xx];
                if (yy + 1 >= 0 && yy + 1 <= 190) bb = rpe[(yy + 1) * RPE_S + xx];
            }
            g_rpe2[idx] = make_float2(a, bb);
        }
        return;
    }
    __shared__ ConvSmem S;
    const int job = blockIdx.y >> 1;
    const int b   = blockIdx.y & 1;
    const int m0  = blockIdx.x * 128;

    const float* W;
    const float* bi;
    const float* srcb = x + b * CC * NN;
    float* dstb;
    int bnoff = -1;
    if (job == 0)      { W = Wq;              bi = bq;          dstb = g_q  + b * CC * NN; }
    else if (job == 1) { W = inp_w;           bi = inp_b;       dstb = g_x2 + b * 96 * NN;            bnoff = 0;  }
    else               { W = inp_w + 48 * CC; bi = inp_b + 48;  dstb = g_x2 + (b * 96 + 48) * NN;     bnoff = 48; }

    if (tid < 48) {
        if (bnoff < 0) { S.sc_s[tid] = 1.f; S.bias_s[tid] = bi[tid]; }
        else {
            float sc = rsqrtf(bnv[bnoff + tid] + 1e-5f) * bng[bnoff + tid];
            S.sc_s[tid]   = sc;
            S.bias_s[tid] = (bi[tid] - bnm[bnoff + tid]) * sc + bnb[bnoff + tid];
        }
    }
    __syncthreads();
    conv_fill(S, srcb, m0, W, tid);
    __syncthreads();

    const int warp = tid >> 5, lane = tid & 31;
    const int gid = lane >> 2, tig = lane & 3;
    const int qrow = warp * 16 + gid;
    float cS[6][4];
    conv_mma(S, cS, qrow, tig, gid);

#pragma unroll
    for (int nb = 0; nb < 6; nb++) {
        int col = nb * 8 + 2 * tig;
        dstb[col * NN + m0 + qrow]           = cS[nb][0];
        dstb[(col + 1) * NN + m0 + qrow]     = cS[nb][1];
        dstb[col * NN + m0 + qrow + 8]       = cS[nb][2];
        dstb[(col + 1) * NN + m0 + qrow + 8] = cS[nb][3];
    }
}

// ---------------- stage2: k,v projections -----------------------------------------
// grid (32, 4): job=y>>1 (0:k 1:v), b=y&1
__global__ void __launch_bounds__(256, 2) stage2_kernel(
    const float* __restrict__ Wk, const float* __restrict__ bk,
    const float* __restrict__ Wv, const float* __restrict__ bv) {
    __shared__ ConvSmem S;
    const int tid = threadIdx.x;
    const int job = blockIdx.y >> 1;
    const int b   = blockIdx.y & 1;
    const int m0  = blockIdx.x * 128;
    const float* W  = job ? Wv : Wk;
    const float* bi = job ? bv : bk;
    float* dstb = (job ? g_v : g_k) + b * CC * NN;
    const float* srcb = g_xs + b * CC * NN;

    if (tid < 48) { S.sc_s[tid] = 1.f; S.bias_s[tid] = bi[tid]; }
    __syncthreads();
    conv_fill(S, srcb, m0, W, tid);
    __syncthreads();

    const int warp = tid >> 5, lane = tid & 31;
    const int gid = lane >> 2, tig = lane & 3;
    const int qrow = warp * 16 + gid;
    float cS[6][4];
    conv_mma(S, cS, qrow, tig, gid);

#pragma unroll
    for (int nb = 0; nb < 6; nb++) {
        int col = nb * 8 + 2 * tig;
        dstb[col * NN + m0 + qrow]           = cS[nb][0];
        dstb[(col + 1) * NN + m0 + qrow]     = cS[nb][1];
        dstb[col * NN + m0 + qrow + 8]       = cS[nb][2];
        dstb[(col + 1) * NN + m0 + qrow + 8] = cS[nb][3];
    }
}

// ---------------- offset head + position + grid-sample x (512 thr) --------------
__global__ void deform_kernel(const float* __restrict__ x,
                              const float* __restrict__ dww, const float* __restrict__ dwb,
                              const float* __restrict__ lng, const float* __restrict__ lnb,
                              const float* __restrict__ pww) {
    int b = blockIdx.y;
    int y = blockIdx.x;
    int tid = threadIdx.x;
    __shared__ float ts[CC * WW];
    __shared__ float posr[WW * 2];
    __shared__ float redA[8][WW];
    __shared__ float redB[8][WW];

    for (int i = tid; i < CC * WW; i += 512) {
        int c = i >> 6, px = i & 63;
        float acc = dwb[c];
        const float* qc = g_q + (b * CC + c) * NN;
        const float* wc = dww + c * 9;
#pragma unroll
        for (int ky = 0; ky < 3; ky++) {
            int yy = y + ky - 1;
            if (yy < 0 || yy > 63) continue;
#pragma unroll
            for (int kx = 0; kx < 3; kx++) {
                int xx = px + kx - 1;
                if (xx < 0 || xx > 63) continue;
                acc += qc[(yy << 6) + xx] * wc[ky * 3 + kx];
            }
        }
        ts[c * 64 + px] = acc;
    }
    __syncthreads();

    const int sub = tid >> 6;
    const int px  = tid & 63;
    {
        float s = 0.f;
#pragma unroll
        for (int j = 0; j < 6; j++) s += ts[(sub * 6 + j) * 64 + px];
        redA[sub][px] = s;
    }
    __syncthreads();
    float mu = 0.f;
#pragma unroll
    for (int u = 0; u < 8; u++) mu += redA[u][px];
    mu *= (1.f / 48.f);
    {
        float v2 = 0.f;
#pragma unroll
        for (int j = 0; j < 6; j++) {
            float d = ts[(sub * 6 + j) * 64 + px] - mu;
            v2 += d * d;
        }
        redB[sub][px] = v2;
    }
    __syncthreads();
    float var = 0.f;
#pragma unroll
    for (int u = 0; u < 8; u++) var += redB[u][px];
    float rs = rsqrtf(var * (1.f / 48.f) + 1e-5f);
    {
        float a0 = 0.f, a1 = 0.f;
#pragma unroll
        for (int j = 0; j < 6; j++) {
            int c = sub * 6 + j;
            float v = (ts[c * 64 + px] - mu) * rs * lng[c] + lnb[c];
            v = 0.5f * v * (1.f + erff(v * 0.7071067811865475f));
            a0 += pww[c] * v;
            a1 += pww[CC + c] * v;
        }
        redA[sub][px] = a0;
        redB[sub][px] = a1;
    }
    __syncthreads();
    if (tid < WW) {
        float a0 = 0.f, a1 = 0.f;
#pragma unroll
        for (int u = 0; u < 8; u++) { a0 += redA[u][px]; a1 += redB[u][px]; }
        float py  = tanhf(a0) * (2.f / 63.f) + ((0.5f + (float)y ) * (2.f / 63.f) - 1.f);
        float pxx = tanhf(a1) * (2.f / 63.f) + ((0.5f + (float)px) * (2.f / 63.f) - 1.f);
        posr[px * 2 + 0] = py;
        posr[px * 2 + 1] = pxx;
        int n = (y << 6) + px;
        g_pos[(b * NN + n) * 2 + 0] = py;
        g_pos[(b * NN + n) * 2 + 1] = pxx;
    }
    __syncthreads();

    for (int i = tid; i < CC * WW; i += 512) {
        int c = i >> 6, p = i & 63;
        float py  = posr[p * 2 + 0];
        float pxx = posr[p * 2 + 1];
        float gx = (pxx + 1.f) * 0.5f * 63.f;
        float gy = (py  + 1.f) * 0.5f * 63.f;
        const float* img = x + (b * CC + c) * NN;
        // bilinear, zero padding
        float x0f = floorf(gx), y0f = floorf(gy);
        int   x0 = (int)x0f, y0 = (int)y0f;
        float wx = gx - x0f, wy = gy - y0f;
        float acc = 0.f;
#pragma unroll
        for (int dy = 0; dy < 2; dy++) {
            int yc = y0 + dy;
            if (yc < 0 || yc >= HH) continue;
            float wyv = dy ? wy : (1.f - wy);
#pragma unroll
            for (int dx = 0; dx < 2; dx++) {
                int xc = x0 + dx;
                if (xc < 0 || xc >= WW) continue;
                float wxv = dx ? wx : (1.f - wx);
                acc += img[yc * WW + xc] * (wyv * wxv);
            }
        }
        g_xs[(b * CC + c) * NN + (y << 6) + p] = acc;
    }
}

// ---------------- fused flash attention: tf32 MMA, padded rpe --------------------
#define AOF_QS 0                        // 128 x 52
#define AOF_KS (AOF_QS + 128*52)        // 48 x 64 swizzled
#define AOF_VS (AOF_KS + 48*64)         // 64 x 49
#define AOF_PS (AOF_VS + 64*49)         // 128 x 66
#define ATTN_SMEM_FLOATS (AOF_PS + 128*66)
#define ATTN_SMEM_BYTES (ATTN_SMEM_FLOATS * 4)

__global__ void __launch_bounds__(256, 2) attn_kernel() {
    extern __shared__ float sm[];
    float* Qs = sm + AOF_QS;
    float* Ks = sm + AOF_KS;
    float* Vs = sm + AOF_VS;
    float* Ps = sm + AOF_PS;
    const uint32_t* Qu = (const uint32_t*)Qs;
    const uint32_t* Ku = (const uint32_t*)Ks;
    const uint32_t* Vu = (const uint32_t*)Vs;
    const uint32_t* Pu = (const uint32_t*)Ps;

    const int yb    = blockIdx.x;
    const int split = blockIdx.y;
    const int b     = blockIdx.z;
    const int tid   = threadIdx.x;
    const int warp  = tid >> 5;
    const int lane  = tid & 31;
    const int gid   = lane >> 2;
    const int tig   = lane & 3;
    const int m0    = yb * 128;
    const int qrow  = warp * 16 + gid;

    const float scale = 0.14433756729740643f;
    const float step  = 95.0f / 63.0f;

    for (int i = tid; i < CC * 128; i += 256) {
        int c = i >> 7, m = i & 127;
        Qs[m * 52 + c] = __uint_as_float(f2tf(g_q[(b * CC + c) * NN + m0 + m] * scale));
    }

    float rmax0 = -1e30f, rmax1 = -1e30f, rsum0 = 0.f, rsum1 = 0.f;
    float o[6][4];
#pragma unroll
    for (int nb = 0; nb < 6; nb++)
#pragma unroll
        for (int j = 0; j < 4; j++) o[nb][j] = 0.f;

    const int nbase = split * KEYS_PER_SPLIT;
    for (int t = 0; t < KEYS_PER_SPLIT / 64; t++) {
        const int n0 = nbase + t * 64;
        __syncthreads();

        for (int i = tid; i < CC * 64; i += 256) {
            int c = i >> 6, n = i & 63;
            Ks[c * 64 + (n ^ ((c & 3) << 3))] =
                __uint_as_float(f2tf(g_k[(b * CC + c) * NN + n0 + n]));
        }

#pragma unroll
        for (int kk = 0; kk < 8; kk++) {
            int n = warp * 8 + kk;
            float py = g_pos[(b * NN + n0 + n) * 2 + 0];
            float px = g_pos[(b * NN + n0 + n) * 2 + 1];
            float kbx = 47.5f * px;
            float fy[2];
            const float2* row[2];
#pragma unroll
            for (int r = 0; r < 2; r++) {
                float gy = 47.5f + (float)(yb * 2 + r) * step - 47.5f * py;
                float yf = floorf(gy);
                int   iy = (int)yf;
                fy[r] = gy - yf;
                iy = min(max(iy, -2), 191);
                row[r] = g_rpe2 + (iy + 2) * RP_STRIDE;
            }
#pragma unroll
            for (int it = 0; it < 4; it++) {
                int m = it * 32 + lane;
                int r = it >> 1;
                float gx = 47.5f + (float)(m & 63) * step - kbx;
                float xf = floorf(gx);
                float fx = gx - xf;
                int   xi = (int)xf;
                xi = min(max(xi, -2), 192);
                float2 v0 = row[r][xi + 2];
                float2 v1 = row[r][xi + 3];
                float b0 = fmaf(fx, v1.x - v0.x, v0.x);
                float b1 = fmaf(fx, v1.y - v0.y, v0.y);
                Ps[m * 66 + n] = fmaf(fy[r], b1 - b0, b0);
            }
        }
        __syncthreads();

        for (int i = tid; i < CC * 64; i += 256) {
            int c = i >> 6, n = i & 63;
            Vs[n * 49 + c] = __uint_as_float(f2tf(g_v[(b * CC + c) * NN + n0 + n]));
        }

        float cS[8][4];
#pragma unroll
        for (int nb = 0; nb < 8; nb++) {
            int col = nb * 8 + 2 * tig;
            float2 bA = *(const float2*)&Ps[qrow * 66 + col];
            float2 bB = *(const float2*)&Ps[(qrow + 8) * 66 + col];
            cS[nb][0] = bA.x; cS[nb][1] = bA.y;
            cS[nb][2] = bB.x; cS[nb][3] = bB.y;
        }
#pragma unroll
        for (int kb = 0; kb < 6; kb++) {
            uint32_t a0 = Qu[qrow * 52 + kb * 8 + tig];
            uint32_t a1 = Qu[(qrow + 8) * 52 + kb * 8 + tig];
            uint32_t a2 = Qu[qrow * 52 + kb * 8 + tig + 4];
            uint32_t a3 = Qu[(qrow + 8) * 52 + kb * 8 + tig + 4];
            const int sw = tig << 3;
#pragma unroll
            for (int nb = 0; nb < 8; nb++) {
                uint32_t b0 = Ku[(kb * 8 + tig) * 64 + ((nb * 8 + gid) ^ sw)];
                uint32_t b1 = Ku[(kb * 8 + tig + 4) * 64 + ((nb * 8 + gid) ^ sw)];
                mma_tf32(cS[nb], a0, a1, a2, a3, b0, b1);
            }
        }

        float tmax0 = -1e30f, tmax1 = -1e30f;
#pragma unroll
        for (int nb = 0; nb < 8; nb++) {
            tmax0 = fmaxf(tmax0, fmaxf(cS[nb][0], cS[nb][1]));
            tmax1 = fmaxf(tmax1, fmaxf(cS[nb][2], cS[nb][3]));
        }
        tmax0 = fmaxf(tmax0, __shfl_xor_sync(0xffffffffu, tmax0, 1));
        tmax0 = fmaxf(tmax0, __shfl_xor_sync(0xffffffffu, tmax0, 2));
        tmax1 = fmaxf(tmax1, __shfl_xor_sync(0xffffffffu, tmax1, 1));
        tmax1 = fmaxf(tmax1, __shfl_xor_sync(0xffffffffu, tmax1, 2));
        float nmax0 = fmaxf(rmax0, tmax0);
        float nmax1 = fmaxf(rmax1, tmax1);
        float f0 = __expf(rmax0 - nmax0);
        float f1 = __expf(rmax1 - nmax1);
        rmax0 = nmax0; rmax1 = nmax1;

        float psum0 = 0.f, psum1 = 0.f;
#pragma unroll
        for (int nb = 0; nb < 8; nb++) {
            float p0 = __expf(cS[nb][0] - nmax0);
            float p1 = __expf(cS[nb][1] - nmax0);
            float p2 = __expf(cS[nb][2] - nmax1);
            float p3 = __expf(cS[nb][3] - nmax1);
            psum0 += p0 + p1;
            psum1 += p2 + p3;
            int col = nb * 8 + 2 * tig;
            float2 w0 = make_float2(__uint_as_float(f2tf(p0)), __uint_as_float(f2tf(p1)));
            float2 w1 = make_float2(__uint_as_float(f2tf(p2)), __uint_as_float(f2tf(p3)));
            *(float2*)&Ps[qrow * 66 + col]       = w0;
            *(float2*)&Ps[(qrow + 8) * 66 + col] = w1;
        }
        psum0 += __shfl_xor_sync(0xffffffffu, psum0, 1);
        psum0 += __shfl_xor_sync(0xffffffffu, psum0, 2);
        psum1 += __shfl_xor_sync(0xffffffffu, psum1, 1);
        psum1 += __shfl_xor_sync(0xffffffffu, psum1, 2);
        rsum0 = rsum0 * f0 + psum0;
        rsum1 = rsum1 * f1 + psum1;

#pragma unroll
        for (int nb = 0; nb < 6; nb++) {
            o[nb][0] *= f0; o[nb][1] *= f0;
            o[nb][2] *= f1; o[nb][3] *= f1;
        }
        __syncthreads();

#pragma unroll
        for (int kb = 0; kb < 8; kb++) {
            uint32_t a0 = Pu[qrow * 66 + kb * 8 + tig];
            uint32_t a1 = Pu[(qrow + 8) * 66 + kb * 8 + tig];
            uint32_t a2 = Pu[qrow * 66 + kb * 8 + tig + 4];
            uint32_t a3 = Pu[(qrow + 8) * 66 + kb * 8 + tig + 4];
#pragma unroll
            for (int nb = 0; nb < 6; nb++) {
                uint32_t b0 = Vu[(kb * 8 + tig) * 49 + nb * 8 + gid];
                uint32_t b1 = Vu[(kb * 8 + tig + 4) * 49 + nb * 8 + gid];
                mma_tf32(o[nb], a0, a1, a2, a3, b0, b1);
            }
        }
    }

    const int mA = m0 + qrow;
    const int mB = mA + 8;
    float* op = g_opart + (split * BB + b) * CC * NN;
#pragma unroll
    for (int nb = 0; nb < 6; nb++) {
        int ch = nb * 8 + 2 * tig;
        op[ch * NN + mA]       = o[nb][0];
        op[(ch + 1) * NN + mA] = o[nb][1];
        op[ch * NN + mB]       = o[nb][2];
        op[(ch + 1) * NN + mB] = o[nb][3];
    }
    if (tig == 0) {
        g_mpart[(split * BB + b) * NN + mA] = rmax0;
        g_mpart[(split * BB + b) * NN + mB] = rmax1;
        g_lpart[(split * BB + b) * NN + mA] = rsum0;
        g_lpart[(split * BB + b) * NN + mB] = rsum1;
    }
}

// ---------------- window attention (3 splits x 64 windows x B) ------------------
__global__ void winattn_kernel() {
    int b  = blockIdx.z;
    int sp = blockIdx.y;
    int w  = blockIdx.x;
    int t  = threadIdx.x;

    __shared__ float qsm[64][17];
    __shared__ float vsm[64][17];

    int py, px;
    if (sp == 0)      { int wy = w >> 3, wx = w & 7; py = wy * 8 + (t >> 3); px = wx * 8 + (t & 7); }
    else if (sp == 1) { py = t;  px = w; }
    else              { py = w;  px = t; }
    int pix = py * 64 + px;

    int qbase = (b * 96 + sp * 32) * NN + pix;
#pragma unroll
    for (int c = 0; c < 16; c++) {
        qsm[t][c] = g_x2[qbase + c * NN];
        vsm[t][c] = g_x2[qbase + (16 + c) * NN];
    }
    __syncthreads();

    float qr[16];
#pragma unroll
    for (int c = 0; c < 16; c++) qr[c] = qsm[t][c];

    float lg[64];
    float mx = -1e30f;
    for (int j = 0; j < 64; j++) {
        float d = 0.f;
#pragma unroll
        for (int c = 0; c < 16; c++) d += qr[c] * qsm[j][c];
        lg[j] = d;
        mx = fmaxf(mx, d);
    }
    float s = 0.f;
    for (int j = 0; j < 64; j++) { lg[j] = __expf(lg[j] - mx); s += lg[j]; }
    float inv = 1.f / s;

    float o[16];
#pragma unroll
    for (int c = 0; c < 16; c++) o[c] = 0.f;
    for (int j = 0; j < 64; j++) {
        float p = lg[j] * inv;
#pragma unroll
        for (int c = 0; c < 16; c++) o[c] += p * vsm[j][c];
    }
#pragma unroll
    for (int c = 0; c < 16; c++)
        g_win[(b * CC + sp * 16 + c) * NN + pix] = o[c];
}

// ---------------- final: MMA pout conv + split merge + average -------------------
// grid (32, 2): b = blockIdx.y
__global__ void __launch_bounds__(256, 2) final_kernel(
    const float* __restrict__ pw, const float* __restrict__ pb,
    float* __restrict__ out) {
    __shared__ ConvSmem S;
    const int tid = threadIdx.x;
    const int b   = blockIdx.y;
    const int m0  = blockIdx.x * 128;

    if (tid < 48) { S.sc_s[tid] = 1.f; S.bias_s[tid] = pb[tid]; }
    __syncthreads();
    conv_fill(S, g_win + b * CC * NN, m0, pw, tid);
    __syncthreads();

    const int warp = tid >> 5, lane = tid & 31;
    const int gid = lane >> 2, tig = lane & 3;
    const int qrow = warp * 16 + gid;
    float cS[6][4];
    conv_mma(S, cS, qrow, tig, gid);

    const int mA = m0 + qrow;
    const int mB = mA + 8;

    // per-pixel merge factors for both rows
    float eA[NSPLIT], eB[NSPLIT];
    {
        float MA = -1e30f, MB = -1e30f;
        float mvA[NSPLIT], mvB[NSPLIT];
#pragma unroll
        for (int s = 0; s < NSPLIT; s++) {
            mvA[s] = g_mpart[(s * BB + b) * NN + mA];
            mvB[s] = g_mpart[(s * BB + b) * NN + mB];
            MA = fmaxf(MA, mvA[s]); MB = fmaxf(MB, mvB[s]);
        }
        float lA = 0.f, lB = 0.f;
#pragma unroll
        for (int s = 0; s < NSPLIT; s++) {
            eA[s] = __expf(mvA[s] - MA);
            eB[s] = __expf(mvB[s] - MB);
            lA += g_lpart[(s * BB + b) * NN + mA] * eA[s];
            lB += g_lpart[(s * BB + b) * NN + mB] * eB[s];
        }
        float ilA = 0.5f / lA, ilB = 0.5f / lB;
#pragma unroll
        for (int s = 0; s < NSPLIT; s++) { eA[s] *= ilA; eB[s] *= ilB; }
    }

#pragma unroll
    for (int nb = 0; nb < 6; nb++) {
        int col = nb * 8 + 2 * tig;
#pragma unroll
        for (int j = 0; j < 2; j++) {
            int ch = col + j;
            float odA = 0.f, odB = 0.f;
#pragma unroll
            for (int s = 0; s < NSPLIT; s++) {
                odA += g_opart[((s * BB + b) * CC + ch) * NN + mA] * eA[s];
                odB += g_opart[((s * BB + b) * CC + ch) * NN + mB] * eB[s];
            }
            out[(b * CC + ch) * NN + mA] = 0.5f * cS[nb][j]     + odA;
            out[(b * CC + ch) * NN + mB] = 0.5f * cS[nb][2 + j] + odB;
        }
    }
}

// ---------------- launch ---------------------------------------------------------
extern "C" void kernel_launch(void* const* d_in, const int* in_sizes, int n_in,
                              void* d_out, int out_size) {
    const float* x        = (const float*)d_in[0];
    const float* Wq       = (const float*)d_in[1];
    const float* bq       = (const float*)d_in[2];
    const float* off_dw_w = (const float*)d_in[3];
    const float* off_dw_b = (const float*)d_in[4];
    const float* off_ln_g = (const float*)d_in[5];
    const float* off_ln_b = (const float*)d_in[6];
    const float* off_pw_w = (const float*)d_in[7];
    const float* Wk       = (const float*)d_in[8];
    const float* bk       = (const float*)d_in[9];
    const float* Wv       = (const float*)d_in[10];
    const float* bv       = (const float*)d_in[11];
    const float* inp_w    = (const float*)d_in[12];
    const float* inp_b    = (const float*)d_in[13];
    const float* bn_g     = (const float*)d_in[14];
    const float* bn_b     = (const float*)d_in[15];
    const float* bn_mean  = (const float*)d_in[16];
    const float* bn_var   = (const float*)d_in[17];
    const float* pout_w   = (const float*)d_in[18];
    const float* pout_b   = (const float*)d_in[19];
    const float* rpe      = (const float*)d_in[20];
    float* out = (float*)d_out;

    cudaFuncSetAttribute(attn_kernel, cudaFuncAttributeMaxDynamicSharedMemorySize,
                         ATTN_SMEM_BYTES);

    stage1_kernel<<<dim3(32, 7), 256>>>(x, Wq, bq, inp_w, inp_b,
                                        bn_g, bn_b, bn_mean, bn_var, rpe);
    deform_kernel<<<dim3(HH, BB), 512>>>(x, off_dw_w, off_dw_b,
                                         off_ln_g, off_ln_b, off_pw_w);
    stage2_kernel<<<dim3(32, 4), 256>>>(Wk, bk, Wv, bv);
    attn_kernel<<<dim3(NN / 128, NSPLIT, BB), 256, ATTN_SMEM_BYTES>>>();
    winattn_kernel<<<dim3(64, 3, BB), 64>>>();
    final_kernel<<<dim3(32, BB), 256>>>(pout_w, pout_b, out);
}

// round 10
// speedup vs baseline: 2.7191x; 1.0477x over previous
#include <cuda_runtime.h>
#include <math.h>
#include <stdint.h>

// Problem constants
#define BB 2
#define CC 48
#define HH 64
#define WW 64
#define NN 4096
#define RPE_S 191
#define NSPLIT 4
#define KEYS_PER_SPLIT (NN / NSPLIT)

#define RP_ROWS 194
#define RP_STRIDE 196

// ---------------- scratch (device globals; no allocation allowed) -------------
__device__ float  g_q  [BB*CC*NN];
__device__ float  g_x2 [BB*96*NN];
__device__ float  g_pos[BB*NN*2];
__device__ float  g_xs [BB*CC*NN];
__device__ float  g_k  [BB*CC*NN];
__device__ float  g_v  [BB*CC*NN];
__device__ float  g_win[BB*CC*NN];
__device__ float  g_opart[NSPLIT*BB*CC*NN];
__device__ float  g_mpart[NSPLIT*BB*NN];
__device__ float  g_lpart[NSPLIT*BB*NN];
// quad-packed padded rpe: g_rpe4[r][xc] = (P[y][x], P[y+1][x], P[y][x+1], P[y+1][x+1])
// with y=r-2, x=xc-2, P = zero-padded rpe
__device__ float4 g_rpe4[RP_ROWS*RP_STRIDE];

// ---------------- tf32 MMA helpers ----------------------------------------------
__device__ __forceinline__ uint32_t f2tf(float f) {
    uint32_t r; asm("cvt.rna.tf32.f32 %0, %1;" : "=r"(r) : "f"(f)); return r;
}
__device__ __forceinline__ void mma_tf32(float* c,
                                         uint32_t a0, uint32_t a1, uint32_t a2, uint32_t a3,
                                         uint32_t b0, uint32_t b1) {
    asm("mma.sync.aligned.m16n8k8.row.col.f32.tf32.tf32.f32 "
        "{%0,%1,%2,%3}, {%4,%5,%6,%7}, {%8,%9}, {%0,%1,%2,%3};"
        : "+f"(c[0]), "+f"(c[1]), "+f"(c[2]), "+f"(c[3])
        : "r"(a0), "r"(a1), "r"(a2), "r"(a3), "r"(b0), "r"(b1));
}

// ---------------- shared 48x48 GEMM tile (128 pixels per block) -------------------
struct ConvSmem {
    float Xs[128 * 52];
    float Ws[48 * 64];
    float bias_s[48];
    float sc_s[48];
};

__device__ __forceinline__ void conv_fill(ConvSmem& S, const float* __restrict__ srcb,
                                          int m0, const float* __restrict__ W, int tid) {
    for (int i = tid; i < CC * 128; i += 256) {
        int c = i >> 7, m = i & 127;
        S.Xs[m * 52 + c] = __uint_as_float(f2tf(srcb[c * NN + m0 + m]));
    }
    for (int i = tid; i < 48 * 64; i += 256) {
        int c = i >> 6, o = i & 63;
        float v = (o < 48) ? W[o * CC + c] * S.sc_s[o] : 0.f;
        S.Ws[c * 64 + (o ^ ((c & 3) << 3))] = __uint_as_float(f2tf(v));
    }
}

__device__ __forceinline__ void conv_mma(const ConvSmem& S, float cS[6][4],
                                         int qrow, int tig, int gid) {
    const uint32_t* Xu = (const uint32_t*)S.Xs;
    const uint32_t* Wu = (const uint32_t*)S.Ws;
#pragma unroll
    for (int nb = 0; nb < 6; nb++) {
        int col = nb * 8 + 2 * tig;
        cS[nb][0] = cS[nb][2] = S.bias_s[col];
        cS[nb][1] = cS[nb][3] = S.bias_s[col + 1];
    }
    const int sw = tig << 3;
#pragma unroll
    for (int kb = 0; kb < 6; kb++) {
        uint32_t a0 = Xu[qrow * 52 + kb * 8 + tig];
        uint32_t a1 = Xu[(qrow + 8) * 52 + kb * 8 + tig];
        uint32_t a2 = Xu[qrow * 52 + kb * 8 + tig + 4];
        uint32_t a3 = Xu[(qrow + 8) * 52 + kb * 8 + tig + 4];
#pragma unroll
        for (int nb = 0; nb < 6; nb++) {
            uint32_t b0 = Wu[(kb * 8 + tig) * 64 + ((nb * 8 + gid) ^ sw)];
            uint32_t b1 = Wu[(kb * 8 + tig + 4) * 64 + ((nb * 8 + gid) ^ sw)];
            mma_tf32(cS[nb], a0, a1, a2, a3, b0, b1);
        }
    }
}

// ---------------- stage1: q + x2(BN) projections + rpe quad-pack -----------------
__global__ void __launch_bounds__(256, 2) stage1_kernel(
    const float* __restrict__ x,
    const float* __restrict__ Wq, const float* __restrict__ bq,
    const float* __restrict__ inp_w, const float* __restrict__ inp_b,
    const float* __restrict__ bng, const float* __restrict__ bnb,
    const float* __restrict__ bnm, const float* __restrict__ bnv,
    const float* __restrict__ rpe) {
    const int tid = threadIdx.x;
    if (blockIdx.y == 6) {
        for (int idx = blockIdx.x * 256 + tid; idx < RP_ROWS * RP_STRIDE; idx += 32 * 256) {
            int r  = idx / RP_STRIDE;
            int xc = idx - r * RP_STRIDE;
            int yy = r - 2, xx = xc - 2;
            float v00 = 0.f, v10 = 0.f, v01 = 0.f, v11 = 0.f;
            bool y0ok = (yy     >= 0 && yy     <= 190);
            bool y1ok = (yy + 1 >= 0 && yy + 1 <= 190);
            if (xx >= 0 && xx <= 190) {
                if (y0ok) v00 = rpe[yy * RPE_S + xx];
                if (y1ok) v10 = rpe[(yy + 1) * RPE_S + xx];
            }
            if (xx + 1 >= 0 && xx + 1 <= 190) {
                if (y0ok) v01 = rpe[yy * RPE_S + xx + 1];
                if (y1ok) v11 = rpe[(yy + 1) * RPE_S + xx + 1];
            }
            g_rpe4[idx] = make_float4(v00, v10, v01, v11);
        }
        return;
    }
    __shared__ ConvSmem S;
    const int job = blockIdx.y >> 1;
    const int b   = blockIdx.y & 1;
    const int m0  = blockIdx.x * 128;

    const float* W;
    const float* bi;
    const float* srcb = x + b * CC * NN;
    float* dstb;
    int bnoff = -1;
    if (job == 0)      { W = Wq;              bi = bq;          dstb = g_q  + b * CC * NN; }
    else if (job == 1) { W = inp_w;           bi = inp_b;       dstb = g_x2 + b * 96 * NN;            bnoff = 0;  }
    else               { W = inp_w + 48 * CC; bi = inp_b + 48;  dstb = g_x2 + (b * 96 + 48) * NN;     bnoff = 48; }

    if (tid < 48) {
        if (bnoff < 0) { S.sc_s[tid] = 1.f; S.bias_s[tid] = bi[tid]; }
        else {
            float sc = rsqrtf(bnv[bnoff + tid] + 1e-5f) * bng[bnoff + tid];
            S.sc_s[tid]   = sc;
            S.bias_s[tid] = (bi[tid] - bnm[bnoff + tid]) * sc + bnb[bnoff + tid];
        }
    }
    __syncthreads();
    conv_fill(S, srcb, m0, W, tid);
    __syncthreads();

    const int warp = tid >> 5, lane = tid & 31;
    const int gid = lane >> 2, tig = lane & 3;
    const int qrow = warp * 16 + gid;
    float cS[6][4];
    conv_mma(S, cS, qrow, tig, gid);

#pragma unroll
    for (int nb = 0; nb < 6; nb++) {
        int col = nb * 8 + 2 * tig;
        dstb[col * NN + m0 + qrow]           = cS[nb][0];
        dstb[(col + 1) * NN + m0 + qrow]     = cS[nb][1];
        dstb[col * NN + m0 + qrow + 8]       = cS[nb][2];
        dstb[(col + 1) * NN + m0 + qrow + 8] = cS[nb][3];
    }
}

// ---------------- stage2: k,v projections -----------------------------------------
__global__ void __launch_bounds__(256, 2) stage2_kernel(
    const float* __restrict__ Wk, const float* __restrict__ bk,
    const float* __restrict__ Wv, const float* __restrict__ bv) {
    __shared__ ConvSmem S;
    const int tid = threadIdx.x;
    const int job = blockIdx.y >> 1;
    const int b   = blockIdx.y & 1;
    const int m0  = blockIdx.x * 128;
    const float* W  = job ? Wv : Wk;
    const float* bi = job ? bv : bk;
    float* dstb = (job ? g_v : g_k) + b * CC * NN;
    const float* srcb = g_xs + b * CC * NN;

    if (tid < 48) { S.sc_s[tid] = 1.f; S.bias_s[tid] = bi[tid]; }
    __syncthreads();
    conv_fill(S, srcb, m0, W, tid);
    __syncthreads();

    const int warp = tid >> 5, lane = tid & 31;
    const int gid = lane >> 2, tig = lane & 3;
    const int qrow = warp * 16 + gid;
    float cS[6][4];
    conv_mma(S, cS, qrow, tig, gid);

#pragma unroll
    for (int nb = 0; nb < 6; nb++) {
        int col = nb * 8 + 2 * tig;
        dstb[col * NN + m0 + qrow]           = cS[nb][0];
        dstb[(col + 1) * NN + m0 + qrow]     = cS[nb][1];
        dstb[col * NN + m0 + qrow + 8]       = cS[nb][2];
        dstb[(col + 1) * NN + m0 + qrow + 8] = cS[nb][3];
    }
}

// ---------------- offset head + position + grid-sample x (512 thr) --------------
__global__ void deform_kernel(const float* __restrict__ x,
                              const float* __restrict__ dww, const float* __restrict__ dwb,
                              const float* __restrict__ lng, const float* __restrict__ lnb,
                              const float* __restrict__ pww) {
    int b = blockIdx.y;
    int y = blockIdx.x;
    int tid = threadIdx.x;
    __shared__ float ts[CC * WW];
    __shared__ float posr[WW * 2];
    __shared__ float redA[8][WW];
    __shared__ float redB[8][WW];

    for (int i = tid; i < CC * WW; i += 512) {
        int c = i >> 6, px = i & 63;
        float acc = dwb[c];
        const float* qc = g_q + (b * CC + c) * NN;
        const float* wc = dww + c * 9;
#pragma unroll
        for (int ky = 0; ky < 3; ky++) {
            int yy = y + ky - 1;
            if (yy < 0 || yy > 63) continue;
#pragma unroll
            for (int kx = 0; kx < 3; kx++) {
                int xx = px + kx - 1;
                if (xx < 0 || xx > 63) continue;
                acc += qc[(yy << 6) + xx] * wc[ky * 3 + kx];
            }
        }
        ts[c * 64 + px] = acc;
    }
    __syncthreads();

    const int sub = tid >> 6;
    const int px  = tid & 63;
    {
        float s = 0.f;
#pragma unroll
        for (int j = 0; j < 6; j++) s += ts[(sub * 6 + j) * 64 + px];
        redA[sub][px] = s;
    }
    __syncthreads();
    float mu = 0.f;
#pragma unroll
    for (int u = 0; u < 8; u++) mu += redA[u][px];
    mu *= (1.f / 48.f);
    {
        float v2 = 0.f;
#pragma unroll
        for (int j = 0; j < 6; j++) {
            float d = ts[(sub * 6 + j) * 64 + px] - mu;
            v2 += d * d;
        }
        redB[sub][px] = v2;
    }
    __syncthreads();
    float var = 0.f;
#pragma unroll
    for (int u = 0; u < 8; u++) var += redB[u][px];
    float rs = rsqrtf(var * (1.f / 48.f) + 1e-5f);
    {
        float a0 = 0.f, a1 = 0.f;
#pragma unroll
        for (int j = 0; j < 6; j++) {
            int c = sub * 6 + j;
            float v = (ts[c * 64 + px] - mu) * rs * lng[c] + lnb[c];
            v = 0.5f * v * (1.f + erff(v * 0.7071067811865475f));
            a0 += pww[c] * v;
            a1 += pww[CC + c] * v;
        }
        redA[sub][px] = a0;
        redB[sub][px] = a1;
    }
    __syncthreads();
    if (tid < WW) {
        float a0 = 0.f, a1 = 0.f;
#pragma unroll
        for (int u = 0; u < 8; u++) { a0 += redA[u][px]; a1 += redB[u][px]; }
        float py  = tanhf(a0) * (2.f / 63.f) + ((0.5f + (float)y ) * (2.f / 63.f) - 1.f);
        float pxx = tanhf(a1) * (2.f / 63.f) + ((0.5f + (float)px) * (2.f / 63.f) - 1.f);
        posr[px * 2 + 0] = py;
        posr[px * 2 + 1] = pxx;
        int n = (y << 6) + px;
        g_pos[(b * NN + n) * 2 + 0] = py;
        g_pos[(b * NN + n) * 2 + 1] = pxx;
    }
    __syncthreads();

    for (int i = tid; i < CC * WW; i += 512) {
        int c = i >> 6, p = i & 63;
        float py  = posr[p * 2 + 0];
        float pxx = posr[p * 2 + 1];
        float gx = (pxx + 1.f) * 0.5f * 63.f;
        float gy = (py  + 1.f) * 0.5f * 63.f;
        const float* img = x + (b * CC + c) * NN;
        float x0f = floorf(gx), y0f = floorf(gy);
        int   x0 = (int)x0f, y0 = (int)y0f;
        float wx = gx - x0f, wy = gy - y0f;
        float acc = 0.f;
#pragma unroll
        for (int dy = 0; dy < 2; dy++) {
            int yc = y0 + dy;
            if (yc < 0 || yc >= HH) continue;
            float wyv = dy ? wy : (1.f - wy);
#pragma unroll
            for (int dx = 0; dx < 2; dx++) {
                int xc = x0 + dx;
                if (xc < 0 || xc >= WW) continue;
                float wxv = dx ? wx : (1.f - wx);
                acc += img[yc * WW + xc] * (wyv * wxv);
            }
        }
        g_xs[(b * CC + c) * NN + (y << 6) + p] = acc;
    }
}

// ---------------- fused flash attention: tf32 MMA, quad rpe, conflict-free Vs ----
#define AOF_QS 0                        // 128 x 52
#define AOF_KS (AOF_QS + 128*52)        // 48 x 64 swizzled
#define AOF_VS (AOF_KS + 48*64)         // 64 x 56 (conflict-free B-frags)
#define AOF_PS (AOF_VS + 64*56)         // 128 x 66
#define ATTN_SMEM_FLOATS (AOF_PS + 128*66)
#define ATTN_SMEM_BYTES (ATTN_SMEM_FLOATS * 4)

__global__ void __launch_bounds__(256, 2) attn_kernel() {
    extern __shared__ float sm[];
    float* Qs = sm + AOF_QS;
    float* Ks = sm + AOF_KS;
    float* Vs = sm + AOF_VS;
    float* Ps = sm + AOF_PS;
    const uint32_t* Qu = (const uint32_t*)Qs;
    const uint32_t* Ku = (const uint32_t*)Ks;
    const uint32_t* Vu = (const uint32_t*)Vs;
    const uint32_t* Pu = (const uint32_t*)Ps;

    const int yb    = blockIdx.x;
    const int split = blockIdx.y;
    const int b     = blockIdx.z;
    const int tid   = threadIdx.x;
    const int warp  = tid >> 5;
    const int lane  = tid & 31;
    const int gid   = lane >> 2;
    const int tig   = lane & 3;
    const int m0    = yb * 128;
    const int qrow  = warp * 16 + gid;

    const float scale = 0.14433756729740643f;
    const float step  = 95.0f / 63.0f;

    for (int i = tid; i < CC * 128; i += 256) {
        int c = i >> 7, m = i & 127;
        Qs[m * 52 + c] = __uint_as_float(f2tf(g_q[(b * CC + c) * NN + m0 + m] * scale));
    }

    float rmax0 = -1e30f, rmax1 = -1e30f, rsum0 = 0.f, rsum1 = 0.f;
    float o[6][4];
#pragma unroll
    for (int nb = 0; nb < 6; nb++)
#pragma unroll
        for (int j = 0; j < 4; j++) o[nb][j] = 0.f;

    const int nbase = split * KEYS_PER_SPLIT;
    for (int t = 0; t < KEYS_PER_SPLIT / 64; t++) {
        const int n0 = nbase + t * 64;
        __syncthreads();

        // K tile swizzled
        for (int i = tid; i < CC * 64; i += 256) {
            int c = i >> 6, n = i & 63;
            Ks[c * 64 + (n ^ ((c & 3) << 3))] =
                __uint_as_float(f2tf(g_k[(b * CC + c) * NN + n0 + n]));
        }

        // bias -> Ps[m][n] (stride 66): one LDG.128 per bilinear sample
#pragma unroll
        for (int kk = 0; kk < 8; kk++) {
            int n = warp * 8 + kk;
            float py = g_pos[(b * NN + n0 + n) * 2 + 0];
            float px = g_pos[(b * NN + n0 + n) * 2 + 1];
            float kbx = 47.5f * px;
            float fy[2];
            const float4* row[2];
#pragma unroll
            for (int r = 0; r < 2; r++) {
                float gy = 47.5f + (float)(yb * 2 + r) * step - 47.5f * py;
                float yf = floorf(gy);
                int   iy = (int)yf;
                fy[r] = gy - yf;
                iy = min(max(iy, -2), 191);
                row[r] = g_rpe4 + (iy + 2) * RP_STRIDE;
            }
#pragma unroll
            for (int it = 0; it < 4; it++) {
                int m = it * 32 + lane;
                int r = it >> 1;
                float gx = 47.5f + (float)(m & 63) * step - kbx;
                float xf = floorf(gx);
                float fx = gx - xf;
                int   xi = (int)xf;
                xi = min(max(xi, -2), 192);
                float4 q4 = row[r][xi + 2];          // (v00, v10, v01, v11)
                float b0 = fmaf(fx, q4.z - q4.x, q4.x);
                float b1 = fmaf(fx, q4.w - q4.y, q4.y);
                Ps[m * 66 + n] = fmaf(fy[r], b1 - b0, b0);
            }
        }
        __syncthreads();

        // V tile [n][56] (conflict-free B-frags)
        for (int i = tid; i < CC * 64; i += 256) {
            int c = i >> 6, n = i & 63;
            Vs[n * 56 + c] = __uint_as_float(f2tf(g_v[(b * CC + c) * NN + n0 + n]));
        }

        float cS[8][4];
#pragma unroll
        for (int nb = 0; nb < 8; nb++) {
            int col = nb * 8 + 2 * tig;
            float2 bA = *(const float2*)&Ps[qrow * 66 + col];
            float2 bB = *(const float2*)&Ps[(qrow + 8) * 66 + col];
            cS[nb][0] = bA.x; cS[nb][1] = bA.y;
            cS[nb][2] = bB.x; cS[nb][3] = bB.y;
        }
#pragma unroll
        for (int kb = 0; kb < 6; kb++) {
            uint32_t a0 = Qu[qrow * 52 + kb * 8 + tig];
            uint32_t a1 = Qu[(qrow + 8) * 52 + kb * 8 + tig];
            uint32_t a2 = Qu[qrow * 52 + kb * 8 + tig + 4];
            uint32_t a3 = Qu[(qrow + 8) * 52 + kb * 8 + tig + 4];
            const int sw = tig << 3;
#pragma unroll
            for (int nb = 0; nb < 8; nb++) {
                uint32_t b0 = Ku[(kb * 8 + tig) * 64 + ((nb * 8 + gid) ^ sw)];
                uint32_t b1 = Ku[(kb * 8 + tig + 4) * 64 + ((nb * 8 + gid) ^ sw)];
                mma_tf32(cS[nb], a0, a1, a2, a3, b0, b1);
            }
        }

        float tmax0 = -1e30f, tmax1 = -1e30f;
#pragma unroll
        for (int nb = 0; nb < 8; nb++) {
            tmax0 = fmaxf(tmax0, fmaxf(cS[nb][0], cS[nb][1]));
            tmax1 = fmaxf(tmax1, fmaxf(cS[nb][2], cS[nb][3]));
        }
        tmax0 = fmaxf(tmax0, __shfl_xor_sync(0xffffffffu, tmax0, 1));
        tmax0 = fmaxf(tmax0, __shfl_xor_sync(0xffffffffu, tmax0, 2));
        tmax1 = fmaxf(tmax1, __shfl_xor_sync(0xffffffffu, tmax1, 1));
        tmax1 = fmaxf(tmax1, __shfl_xor_sync(0xffffffffu, tmax1, 2));
        float nmax0 = fmaxf(rmax0, tmax0);
        float nmax1 = fmaxf(rmax1, tmax1);
        float f0 = __expf(rmax0 - nmax0);
        float f1 = __expf(rmax1 - nmax1);
        rmax0 = nmax0; rmax1 = nmax1;

        float psum0 = 0.f, psum1 = 0.f;
#pragma unroll
        for (int nb = 0; nb < 8; nb++) {
            float p0 = __expf(cS[nb][0] - nmax0);
            float p1 = __expf(cS[nb][1] - nmax0);
            float p2 = __expf(cS[nb][2] - nmax1);
            float p3 = __expf(cS[nb][3] - nmax1);
            psum0 += p0 + p1;
            psum1 += p2 + p3;
            int col = nb * 8 + 2 * tig;
            float2 w0 = make_float2(__uint_as_float(f2tf(p0)), __uint_as_float(f2tf(p1)));
            float2 w1 = make_float2(__uint_as_float(f2tf(p2)), __uint_as_float(f2tf(p3)));
            *(float2*)&Ps[qrow * 66 + col]       = w0;
            *(float2*)&Ps[(qrow + 8) * 66 + col] = w1;
        }
        psum0 += __shfl_xor_sync(0xffffffffu, psum0, 1);
        psum0 += __shfl_xor_sync(0xffffffffu, psum0, 2);
        psum1 += __shfl_xor_sync(0xffffffffu, psum1, 1);
        psum1 += __shfl_xor_sync(0xffffffffu, psum1, 2);
        rsum0 = rsum0 * f0 + psum0;
        rsum1 = rsum1 * f1 + psum1;

#pragma unroll
        for (int nb = 0; nb < 6; nb++) {
            o[nb][0] *= f0; o[nb][1] *= f0;
            o[nb][2] *= f1; o[nb][3] *= f1;
        }
        __syncthreads();

#pragma unroll
        for (int kb = 0; kb < 8; kb++) {
            uint32_t a0 = Pu[qrow * 66 + kb * 8 + tig];
            uint32_t a1 = Pu[(qrow + 8) * 66 + kb * 8 + tig];
            uint32_t a2 = Pu[qrow * 66 + kb * 8 + tig + 4];
            uint32_t a3 = Pu[(qrow + 8) * 66 + kb * 8 + tig + 4];
#pragma unroll
            for (int nb = 0; nb < 6; nb++) {
                uint32_t b0 = Vu[(kb * 8 + tig) * 56 + nb * 8 + gid];
                uint32_t b1 = Vu[(kb * 8 + tig + 4) * 56 + nb * 8 + gid];
                mma_tf32(o[nb], a0, a1, a2, a3, b0, b1);
            }
        }
    }

    const int mA = m0 + qrow;
    const int mB = mA + 8;
    float* op = g_opart + (split * BB + b) * CC * NN;
#pragma unroll
    for (int nb = 0; nb < 6; nb++) {
        int ch = nb * 8 + 2 * tig;
        op[ch * NN + mA]       = o[nb][0];
        op[(ch + 1) * NN + mA] = o[nb][1];
        op[ch * NN + mB]       = o[nb][2];
        op[(ch + 1) * NN + mB] = o[nb][3];
    }
    if (tig == 0) {
        g_mpart[(split * BB + b) * NN + mA] = rmax0;
        g_mpart[(split * BB + b) * NN + mB] = rmax1;
        g_lpart[(split * BB + b) * NN + mA] = rsum0;
        g_lpart[(split * BB + b) * NN + mB] = rsum1;
    }
}

// ---------------- window attention: 4 windows per 256-thread block --------------
__global__ void __launch_bounds__(256, 4) winattn_kernel() {
    int b  = blockIdx.z;
    int sp = blockIdx.y;
    int wg = threadIdx.x >> 6;               // 0..3 window within block
    int w  = blockIdx.x * 4 + wg;            // window 0..63
    int t  = threadIdx.x & 63;

    __shared__ float qsm[4][64][17];
    __shared__ float vsm[4][64][17];

    int py, px;
    if (sp == 0)      { int wy = w >> 3, wx = w & 7; py = wy * 8 + (t >> 3); px = wx * 8 + (t & 7); }
    else if (sp == 1) { py = t;  px = w; }
    else              { py = w;  px = t; }
    int pix = py * 64 + px;

    int qbase = (b * 96 + sp * 32) * NN + pix;
#pragma unroll
    for (int c = 0; c < 16; c++) {
        qsm[wg][t][c] = g_x2[qbase + c * NN];
        vsm[wg][t][c] = g_x2[qbase + (16 + c) * NN];
    }
    __syncthreads();

    float qr[16];
#pragma unroll
    for (int c = 0; c < 16; c++) qr[c] = qsm[wg][t][c];

    float lg[64];
    float mx = -1e30f;
    for (int j = 0; j < 64; j++) {
        float d = 0.f;
#pragma unroll
        for (int c = 0; c < 16; c++) d += qr[c] * qsm[wg][j][c];
        lg[j] = d;
        mx = fmaxf(mx, d);
    }
    float s = 0.f;
    for (int j = 0; j < 64; j++) { lg[j] = __expf(lg[j] - mx); s += lg[j]; }
    float inv = 1.f / s;

    float o[16];
#pragma unroll
    for (int c = 0; c < 16; c++) o[c] = 0.f;
    for (int j = 0; j < 64; j++) {
        float p = lg[j] * inv;
#pragma unroll
        for (int c = 0; c < 16; c++) o[c] += p * vsm[wg][j][c];
    }
#pragma unroll
    for (int c = 0; c < 16; c++)
        g_win[(b * CC + sp * 16 + c) * NN + pix] = o[c];
}

// ---------------- final: MMA pout conv + split merge + average -------------------
__global__ void __launch_bounds__(256, 2) final_kernel(
    const float* __restrict__ pw, const float* __restrict__ pb,
    float* __restrict__ out) {
    __shared__ ConvSmem S;
    const int tid = threadIdx.x;
    const int b   = blockIdx.y;
    const int m0  = blockIdx.x * 128;

    if (tid < 48) { S.sc_s[tid] = 1.f; S.bias_s[tid] = pb[tid]; }
    __syncthreads();
    conv_fill(S, g_win + b * CC * NN, m0, pw, tid);
    __syncthreads();

    const int warp = tid >> 5, lane = tid & 31;
    const int gid = lane >> 2, tig = lane & 3;
    const int qrow = warp * 16 + gid;
    float cS[6][4];
    conv_mma(S, cS, qrow, tig, gid);

    const int mA = m0 + qrow;
    const int mB = mA + 8;

    float eA[NSPLIT], eB[NSPLIT];
    {
        float MA = -1e30f, MB = -1e30f;
        float mvA[NSPLIT], mvB[NSPLIT];
#pragma unroll
        for (int s = 0; s < NSPLIT; s++) {
            mvA[s] = g_mpart[(s * BB + b) * NN + mA];
            mvB[s] = g_mpart[(s * BB + b) * NN + mB];
            MA = fmaxf(MA, mvA[s]); MB = fmaxf(MB, mvB[s]);
        }
        float lA = 0.f, lB = 0.f;
#pragma unroll
        for (int s = 0; s < NSPLIT; s++) {
            eA[s] = __expf(mvA[s] - MA);
            eB[s] = __expf(mvB[s] - MB);
            lA += g_lpart[(s * BB + b) * NN + mA] * eA[s];
            lB += g_lpart[(s * BB + b) * NN + mB] * eB[s];
        }
        float ilA = 0.5f / lA, ilB = 0.5f / lB;
#pragma unroll
        for (int s = 0; s < NSPLIT; s++) { eA[s] *= ilA; eB[s] *= ilB; }
    }

#pragma unroll
    for (int nb = 0; nb < 6; nb++) {
        int col = nb * 8 + 2 * tig;
#pragma unroll
        for (int j = 0; j < 2; j++) {
            int ch = col + j;
            float odA = 0.f, odB = 0.f;
#pragma unroll
            for (int s = 0; s < NSPLIT; s++) {
                odA += g_opart[((s * BB + b) * CC + ch) * NN + mA] * eA[s];
                odB += g_opart[((s * BB + b) * CC + ch) * NN + mB] * eB[s];
            }
            out[(b * CC + ch) * NN + mA] = 0.5f * cS[nb][j]     + odA;
            out[(b * CC + ch) * NN + mB] = 0.5f * cS[nb][2 + j] + odB;
        }
    }
}

// ---------------- launch ---------------------------------------------------------
extern "C" void kernel_launch(void* const* d_in, const int* in_sizes, int n_in,
                              void* d_out, int out_size) {
    const float* x        = (const float*)d_in[0];
    const float* Wq       = (const float*)d_in[1];
    const float* bq       = (const float*)d_in[2];
    const float* off_dw_w = (const float*)d_in[3];
    const float* off_dw_b = (const float*)d_in[4];
    const float* off_ln_g = (const float*)d_in[5];
    const float* off_ln_b = (const float*)d_in[6];
    const float* off_pw_w = (const float*)d_in[7];
    const float* Wk       = (const float*)d_in[8];
    const float* bk       = (const float*)d_in[9];
    const float* Wv       = (const float*)d_in[10];
    const float* bv       = (const float*)d_in[11];
    const float* inp_w    = (const float*)d_in[12];
    const float* inp_b    = (const float*)d_in[13];
    const float* bn_g     = (const float*)d_in[14];
    const float* bn_b     = (const float*)d_in[15];
    const float* bn_mean  = (const float*)d_in[16];
    const float* bn_var   = (const float*)d_in[17];
    const float* pout_w   = (const float*)d_in[18];
    const float* pout_b   = (const float*)d_in[19];
    const float* rpe      = (const float*)d_in[20];
    float* out = (float*)d_out;

    cudaFuncSetAttribute(attn_kernel, cudaFuncAttributeMaxDynamicSharedMemorySize,
                         ATTN_SMEM_BYTES);

    stage1_kernel<<<dim3(32, 7), 256>>>(x, Wq, bq, inp_w, inp_b,
                                        bn_g, bn_b, bn_mean, bn_var, rpe);
    deform_kernel<<<dim3(HH, BB), 512>>>(x, off_dw_w, off_dw_b,
                                         off_ln_g, off_ln_b, off_pw_w);
    stage2_kernel<<<dim3(32, 4), 256>>>(Wk, bk, Wv, bv);
    attn_kernel<<<dim3(NN / 128, NSPLIT, BB), 256, ATTN_SMEM_BYTES>>>();
    winattn_kernel<<<dim3(16, 3, BB), 256>>>();
    final_kernel<<<dim3(32, BB), 256>>>(pout_w, pout_b, out);
}